// round 9
// baseline (speedup 1.0000x reference)
#include <cuda_runtime.h>
#include <cuda_bf16.h>
#include <cstdint>

// ---------------- problem constants ----------------
#define NB   128
#define NPV  20
#define NPP  500
#define NVG  (NB*NPV)     // 2560
#define NPG  (NB*NPP)     // 64000
#define DD   256
#define FV   6
#define FP   8
#define DEG  8
#define EV   (NVG*DEG)
#define EP   (NPG*DEG)
#define CAP  64
#define PPOOL 10

// ---------------- static device scratch ----------------
__device__ float g_p_tmp [NPG*DD];            // h1 (p layer-1 output)
__device__ __nv_bfloat16 g_p_hi[NPG*DD];      // agg(h1) split
__device__ __nv_bfloat16 g_p_lo[NPG*DD];

__device__ float g_v_init[NVG*DD];
__device__ float g_v_tmp [NVG*DD];
__device__ float g_v_node[NVG*DD];
__device__ __nv_bfloat16 g_v_hi[NVG*DD];
__device__ __nv_bfloat16 g_v_lo[NVG*DD];

__device__ __nv_bfloat16 g_wtv2_hi[DD*DD]; __device__ __nv_bfloat16 g_wtv2_lo[DD*DD];
__device__ __nv_bfloat16 g_wtp2_hi[DD*DD]; __device__ __nv_bfloat16 g_wtp2_lo[DD*DD];

__device__ float g_Mp[9*DD];   // rows 0-7: Wi@W1 (zero-padded); row 8: bi@W1
__device__ float g_Mv[9*DD];

__device__ float g_p_agg8[NPG*8];
__device__ float g_p_s[NPG];
__device__ float g_v_agg8[NVG*8];
__device__ float g_v_s[NVG];

__device__ int   g_p_indeg[NPG];
__device__ int   g_v_indeg[NVG];
__device__ float g_p_dinv[NPG];
__device__ float g_v_dinv[NVG];
__device__ int   g_p_csr[NPG*CAP];
__device__ int   g_v_csr[NVG*CAP];

__device__ float g_pg_part[NB*PPOOL*DD];  // pooled-agg partials
__device__ float g_vg[NB*DD];
__device__ float g_av2[NB*DD];            // combined per-graph additive vector

// ---------------- helpers ----------------
__device__ __forceinline__ uint32_t smem_u32(const void* p) {
    uint32_t a;
    asm("{ .reg .u64 t; cvta.to.shared.u64 t, %1; cvt.u32.u64 %0, t; }" : "=r"(a) : "l"(p));
    return a;
}
__device__ __forceinline__ void cpa16(uint32_t dst, const void* src) {
    asm volatile("cp.async.cg.shared.global [%0], [%1], 16;" :: "r"(dst), "l"(src) : "memory");
}
#define CPA_COMMIT() asm volatile("cp.async.commit_group;" ::: "memory")
#define CPA_WAIT0()  asm volatile("cp.async.wait_group 0;" ::: "memory")

#define MMA_OP(ACC, AH, B0, B1)                                                   \
    asm volatile(                                                                  \
        "mma.sync.aligned.m16n8k16.row.col.f32.bf16.bf16.f32 "                    \
        "{%0,%1,%2,%3}, {%4,%5,%6,%7}, {%8,%9}, {%0,%1,%2,%3};"                   \
        : "+f"((ACC)[0]), "+f"((ACC)[1]), "+f"((ACC)[2]), "+f"((ACC)[3])          \
        : "r"((AH)[0]), "r"((AH)[1]), "r"((AH)[2]), "r"((AH)[3]),                 \
          "r"(B0), "r"(B1))

// ---------------- setup kernels ----------------
__global__ void zero_all(int* p_indeg, int* v_indeg) {
    int i = blockIdx.x * blockDim.x + threadIdx.x;
    if (i < NPG) p_indeg[i] = 0;
    else if (i < NPG + NVG) v_indeg[i - NPG] = 0;
}
__global__ void build_csr(const int* __restrict__ src, const int* __restrict__ dst,
                          int E, int* __restrict__ indeg, int* __restrict__ csr) {
    int e = blockIdx.x * blockDim.x + threadIdx.x;
    if (e >= E) return;
    int d = dst[e];
    int slot = atomicAdd(&indeg[d], 1);
    if (slot < CAP) csr[d * CAP + slot] = src[e];
}
__global__ void dinv_both(const int* __restrict__ p_indeg, const int* __restrict__ v_indeg,
                          float* __restrict__ p_dinv, float* __restrict__ v_dinv) {
    int i = blockIdx.x * blockDim.x + threadIdx.x;
    if (i < NPG) p_dinv[i] = rsqrtf((float)p_indeg[i] + 1.0f);
    else if (i < NPG + NVG) v_dinv[i - NPG] = rsqrtf((float)v_indeg[i - NPG] + 1.0f);
}

// M rows 0..7 = Wi@W1 (zero-padded); row 8 = bi@W1 ; grid 18 covers p (0-8) and v (9-17)
__global__ __launch_bounds__(256) void prep_M_both(
    const float* __restrict__ pWi, const float* __restrict__ pbi, const float* __restrict__ pW1,
    const float* __restrict__ vWi, const float* __restrict__ vbi, const float* __restrict__ vW1,
    float* __restrict__ Mp, float* __restrict__ Mv) {
    int blk = blockIdx.x, d = threadIdx.x;
    const float* Wi; const float* bi; const float* W1; float* M; int F, f;
    if (blk < 9) { Wi = pWi; bi = pbi; W1 = pW1; M = Mp; F = FP; f = blk; }
    else         { Wi = vWi; bi = vbi; W1 = vW1; M = Mv; F = FV; f = blk - 9; }
    float acc = 0.0f;
    if (f < 8) {
        if (f < F)
            for (int j = 0; j < DD; j++)
                acc = fmaf(__ldg(&Wi[f * DD + j]), __ldg(&W1[j * DD + d]), acc);
    } else {
        for (int j = 0; j < DD; j++)
            acc = fmaf(__ldg(&bi[j]), __ldg(&W1[j * DD + d]), acc);
    }
    M[f * DD + d] = acc;
}

// transpose + bf16 split both W2s; grid 512
__global__ __launch_bounds__(256) void prep_wt_both(
    const float* __restrict__ pW2, const float* __restrict__ vW2,
    __nv_bfloat16* __restrict__ phi, __nv_bfloat16* __restrict__ plo,
    __nv_bfloat16* __restrict__ vhi, __nv_bfloat16* __restrict__ vlo) {
    int blk = blockIdx.x, k = threadIdx.x;
    const float* W; __nv_bfloat16 *hi, *lo; int n;
    if (blk < DD) { W = pW2; hi = phi; lo = plo; n = blk; }
    else          { W = vW2; hi = vhi; lo = vlo; n = blk - DD; }
    float w = W[k * DD + n];
    __nv_bfloat16 h = __float2bfloat16_rn(w);
    hi[n * DD + k] = h;
    lo[n * DD + k] = __float2bfloat16_rn(w - __bfloat162float(h));
}

// v init emb (needed for av2)
__global__ __launch_bounds__(256) void init_emb_kernel(
    const float* __restrict__ x, const float* __restrict__ W, const float* __restrict__ b,
    float* __restrict__ out, int F) {
    int node = blockIdx.x, d = threadIdx.x;
    const float* xr = x + node * F;
    float acc = __ldg(&b[d]);
    #pragma unroll 8
    for (int k = 0; k < 8; k++)
        if (k < F) acc = fmaf(__ldg(&xr[k]), __ldg(&W[k * DD + d]), acc);
    out[node * DD + d] = acc;
}

// ---------------- layer 1: feature-space agg (both nets, one launch) -------------
__global__ __launch_bounds__(256) void agg8_both(
    const float* __restrict__ px, const float* __restrict__ vx,
    const int* __restrict__ p_csr, const int* __restrict__ v_csr,
    const int* __restrict__ p_indeg, const int* __restrict__ v_indeg,
    const float* __restrict__ p_dinv, const float* __restrict__ v_dinv,
    float* __restrict__ p_agg8, float* __restrict__ v_agg8,
    float* __restrict__ p_s, float* __restrict__ v_s) {
    int i = blockIdx.x * blockDim.x + threadIdx.x;
    const float* x; const int* csr; const int* indeg; const float* dinv;
    float* agg8; float* sv; int node, F;
    if (i < NPG) { x = px; csr = p_csr; indeg = p_indeg; dinv = p_dinv;
                   agg8 = p_agg8; sv = p_s; node = i; F = FP; }
    else if (i < NPG + NVG) { x = vx; csr = v_csr; indeg = v_indeg; dinv = v_dinv;
                   agg8 = v_agg8; sv = v_s; node = i - NPG; F = FV; }
    else return;
    int deg = indeg[node];
    int cnt = deg < CAP ? deg : CAP;
    float self = 1.0f / ((float)deg + 1.0f);
    float ddst = dinv[node];
    float a[8];
    #pragma unroll
    for (int f = 0; f < 8; f++) a[f] = 0.0f;
    if (F == 8) {
        float4 x0 = *(const float4*)(x + node * 8);
        float4 x1 = *(const float4*)(x + node * 8 + 4);
        a[0] = x0.x * self; a[1] = x0.y * self; a[2] = x0.z * self; a[3] = x0.w * self;
        a[4] = x1.x * self; a[5] = x1.y * self; a[6] = x1.z * self; a[7] = x1.w * self;
    } else {
        for (int f = 0; f < F; f++) a[f] = x[node * F + f] * self;
    }
    float ssum = self;
    const int* cp = csr + node * CAP;
    for (int e = 0; e < cnt; e++) {
        int src = cp[e];
        float c = ddst * dinv[src];
        ssum += c;
        if (F == 8) {
            float4 m0 = *(const float4*)(x + src * 8);
            float4 m1 = *(const float4*)(x + src * 8 + 4);
            a[0] = fmaf(c, m0.x, a[0]); a[1] = fmaf(c, m0.y, a[1]);
            a[2] = fmaf(c, m0.z, a[2]); a[3] = fmaf(c, m0.w, a[3]);
            a[4] = fmaf(c, m1.x, a[4]); a[5] = fmaf(c, m1.y, a[5]);
            a[6] = fmaf(c, m1.z, a[6]); a[7] = fmaf(c, m1.w, a[7]);
        } else {
            for (int f = 0; f < F; f++) a[f] = fmaf(c, x[src * F + f], a[f]);
        }
    }
    *(float4*)(agg8 + node * 8)     = make_float4(a[0], a[1], a[2], a[3]);
    *(float4*)(agg8 + node * 8 + 4) = make_float4(a[4], a[5], a[6], a[7]);
    sv[node] = ssum;
}

// h1 = relu(agg8 @ M[0:8] + s * M[8] + b1) ; blocks cover p then v
__global__ __launch_bounds__(256) void layer1_both(
    const float* __restrict__ p_agg8, const float* __restrict__ p_sv,
    const float* __restrict__ v_agg8, const float* __restrict__ v_sv,
    const float* __restrict__ Mp, const float* __restrict__ Mv,
    const float* __restrict__ pb1, const float* __restrict__ vb1,
    float* __restrict__ p_h1, float* __restrict__ v_h1) {
    int blk = blockIdx.x, d = threadIdx.x;
    const float* agg8; const float* sv; const float* M; const float* b1; float* h1; int node;
    if (blk < NPG) { agg8 = p_agg8; sv = p_sv; M = Mp; b1 = pb1; h1 = p_h1; node = blk; }
    else           { agg8 = v_agg8; sv = v_sv; M = Mv; b1 = vb1; h1 = v_h1; node = blk - NPG; }
    float a0 = __ldg(&agg8[node * 8 + 0]), a1 = __ldg(&agg8[node * 8 + 1]);
    float a2 = __ldg(&agg8[node * 8 + 2]), a3 = __ldg(&agg8[node * 8 + 3]);
    float a4 = __ldg(&agg8[node * 8 + 4]), a5 = __ldg(&agg8[node * 8 + 5]);
    float a6 = __ldg(&agg8[node * 8 + 6]), a7 = __ldg(&agg8[node * 8 + 7]);
    float ss = __ldg(&sv[node]);
    float acc = __ldg(&b1[d]) + ss * __ldg(&M[8 * DD + d]);
    acc = fmaf(a0, __ldg(&M[0 * DD + d]), acc);
    acc = fmaf(a1, __ldg(&M[1 * DD + d]), acc);
    acc = fmaf(a2, __ldg(&M[2 * DD + d]), acc);
    acc = fmaf(a3, __ldg(&M[3 * DD + d]), acc);
    acc = fmaf(a4, __ldg(&M[4 * DD + d]), acc);
    acc = fmaf(a5, __ldg(&M[5 * DD + d]), acc);
    acc = fmaf(a6, __ldg(&M[6 * DD + d]), acc);
    acc = fmaf(a7, __ldg(&M[7 * DD + d]), acc);
    h1[node * DD + d] = fmaxf(acc, 0.0f);
}

// ---------------- 256-dim aggregation -> bf16 split (clean, no sync) ----------
__global__ __launch_bounds__(256) void gcn_agg(
    const float* __restrict__ h, const int* __restrict__ csr, const int* __restrict__ indeg,
    const float* __restrict__ dinv, __nv_bfloat16* __restrict__ out_hi,
    __nv_bfloat16* __restrict__ out_lo, int n_nodes) {
    int warp = threadIdx.x >> 5;
    int lane = threadIdx.x & 31;
    int node = blockIdx.x * 8 + warp;
    if (node >= n_nodes) return;
    int d0 = lane * 8;

    int deg = indeg[node];
    int cnt = deg < CAP ? deg : CAP;
    float self = 1.0f / ((float)deg + 1.0f);
    float ddst = dinv[node];
    const float* hn = h + node * DD + d0;
    float4 s0 = *(const float4*)hn;
    float4 s1 = *(const float4*)(hn + 4);
    float4 acc0 = make_float4(s0.x * self, s0.y * self, s0.z * self, s0.w * self);
    float4 acc1 = make_float4(s1.x * self, s1.y * self, s1.z * self, s1.w * self);
    const int* cp = csr + node * CAP;
    for (int e = 0; e < cnt; e++) {
        int src = cp[e];
        float c = ddst * dinv[src];
        const float* hs = h + src * DD + d0;
        float4 m0 = *(const float4*)hs;
        float4 m1 = *(const float4*)(hs + 4);
        acc0.x = fmaf(c, m0.x, acc0.x); acc0.y = fmaf(c, m0.y, acc0.y);
        acc0.z = fmaf(c, m0.z, acc0.z); acc0.w = fmaf(c, m0.w, acc0.w);
        acc1.x = fmaf(c, m1.x, acc1.x); acc1.y = fmaf(c, m1.y, acc1.y);
        acc1.z = fmaf(c, m1.z, acc1.z); acc1.w = fmaf(c, m1.w, acc1.w);
    }
    int base = node * DD + d0;
    float v[8] = {acc0.x, acc0.y, acc0.z, acc0.w, acc1.x, acc1.y, acc1.z, acc1.w};
    uint32_t hw[4], lw[4];
    #pragma unroll
    for (int q = 0; q < 4; q++) {
        __nv_bfloat16 h0 = __float2bfloat16_rn(v[q * 2]);
        __nv_bfloat16 h1v = __float2bfloat16_rn(v[q * 2 + 1]);
        __nv_bfloat16 l0 = __float2bfloat16_rn(v[q * 2] - __bfloat162float(h0));
        __nv_bfloat16 l1 = __float2bfloat16_rn(v[q * 2 + 1] - __bfloat162float(h1v));
        __nv_bfloat162 hp = __nv_bfloat162(h0, h1v);
        __nv_bfloat162 lp = __nv_bfloat162(l0, l1);
        hw[q] = *(uint32_t*)&hp;
        lw[q] = *(uint32_t*)&lp;
    }
    *(uint4*)(out_hi + base) = make_uint4(hw[0], hw[1], hw[2], hw[3]);
    *(uint4*)(out_lo + base) = make_uint4(lw[0], lw[1], lw[2], lw[3]);
}

// partial pooled agg from the bf16 split (hi+lo ~exact reconstruction)
// grid (NB, PPOOL): sums 50 nodes' agg vectors -> pg_part
__global__ __launch_bounds__(256) void pool_p_bf16(
    const __nv_bfloat16* __restrict__ hi, const __nv_bfloat16* __restrict__ lo,
    float* __restrict__ part) {
    int b = blockIdx.x, pp = blockIdx.y, d = threadIdx.x;
    const int chunk = NPP / PPOOL;   // 50
    size_t base = ((size_t)b * NPP + pp * chunk) * DD + d;
    float s = 0.f;
    #pragma unroll 2
    for (int i = 0; i < chunk; i++) {
        size_t idx = base + (size_t)i * DD;
        s += __bfloat162float(hi[idx]) + __bfloat162float(lo[idx]);
    }
    part[(b * PPOOL + pp) * DD + d] = s;
}

// ---------------- smem-staged bf16-split GEMM ----------------
#define KC 32
#define APITCH 80
#define PIECE (128*APITCH)
#define STAGE_BYTES (4*PIECE)
#define GEMM_SMEM (2*STAGE_BYTES)

#define GEMM_PRE()                                                                 \
    extern __shared__ char sm[];                                                   \
    uint32_t sb = smem_u32(sm);                                                    \
    int tid = threadIdx.x;                                                         \
    int wid = tid >> 5, lane = tid & 31;                                           \
    int g = lane >> 2, t = lane & 3;                                               \
    int warp_m = wid & 3, warp_n = wid >> 2;                                       \
    int row0 = blockIdx.y * 128;                                                   \
    int col0 = blockIdx.x * 128;                                                   \
    float acc[2][8][4];                                                            \
    _Pragma("unroll")                                                              \
    for (int s = 0; s < 2; s++)                                                    \
        _Pragma("unroll")                                                          \
        for (int n = 0; n < 8; n++)                                                \
            _Pragma("unroll")                                                      \
            for (int q = 0; q < 4; q++) acc[s][n][q] = 0.0f;                       \
    int r0i = (tid + 0) >> 2,  c0i = (tid + 0) & 3;                                \
    int r1i = (tid + 256) >> 2, c1i = (tid + 256) & 3;                             \
    auto stage_load = [&](int st) {                                                \
        uint32_t base = sb + (st & 1) * STAGE_BYTES;                               \
        int kc0 = st * KC;                                                         \
        {                                                                          \
            uint32_t d0 = base + r0i * APITCH + c0i * 16;                          \
            size_t ga = (size_t)(row0 + r0i) * DD + kc0 + c0i * 8;                 \
            size_t gb = (size_t)(col0 + r0i) * DD + kc0 + c0i * 8;                 \
            cpa16(d0,           A_hi + ga);                                        \
            cpa16(d0 + PIECE,   A_lo + ga);                                        \
            cpa16(d0 + 2*PIECE, Bt_hi + gb);                                       \
            cpa16(d0 + 3*PIECE, Bt_lo + gb);                                       \
        }                                                                          \
        {                                                                          \
            uint32_t d0 = base + r1i * APITCH + c1i * 16;                          \
            size_t ga = (size_t)(row0 + r1i) * DD + kc0 + c1i * 8;                 \
            size_t gb = (size_t)(col0 + r1i) * DD + kc0 + c1i * 8;                 \
            cpa16(d0,           A_hi + ga);                                        \
            cpa16(d0 + PIECE,   A_lo + ga);                                        \
            cpa16(d0 + 2*PIECE, Bt_hi + gb);                                       \
            cpa16(d0 + 3*PIECE, Bt_lo + gb);                                       \
        }                                                                          \
        CPA_COMMIT();                                                              \
    };                                                                             \
    stage_load(0);                                                                 \
    CPA_WAIT0();                                                                   \
    __syncthreads();                                                               \
    for (int st = 0; st < DD / KC; st++) {                                         \
        if (st + 1 < DD / KC) stage_load(st + 1);                                  \
        const char* cur = sm + (st & 1) * STAGE_BYTES;                             \
        _Pragma("unroll")                                                          \
        for (int kk = 0; kk < 2; kk++) {                                           \
            int kb = (kk * 16 + t * 2) * 2;                                        \
            uint32_t ah[2][4], al[2][4];                                           \
            _Pragma("unroll")                                                      \
            for (int s = 0; s < 2; s++) {                                          \
                const char* pa = cur + (warp_m * 32 + s * 16 + g) * APITCH + kb;   \
                ah[s][0] = *(const uint32_t*)pa;                                   \
                ah[s][1] = *(const uint32_t*)(pa + 8 * APITCH);                    \
                ah[s][2] = *(const uint32_t*)(pa + 16);                            \
                ah[s][3] = *(const uint32_t*)(pa + 8 * APITCH + 16);               \
                const char* pl = pa + PIECE;                                       \
                al[s][0] = *(const uint32_t*)pl;                                   \
                al[s][1] = *(const uint32_t*)(pl + 8 * APITCH);                    \
                al[s][2] = *(const uint32_t*)(pl + 16);                            \
                al[s][3] = *(const uint32_t*)(pl + 8 * APITCH + 16);               \
            }                                                                      \
            _Pragma("unroll")                                                      \
            for (int nt = 0; nt < 8; nt++) {                                       \
                const char* pb = cur + 2 * PIECE + (warp_n * 64 + nt * 8 + g) * APITCH + kb; \
                uint32_t bh0 = *(const uint32_t*)pb;                               \
                uint32_t bh1 = *(const uint32_t*)(pb + 16);                        \
                const char* pbl = pb + PIECE;                                      \
                uint32_t bl0 = *(const uint32_t*)pbl;                              \
                uint32_t bl1 = *(const uint32_t*)(pbl + 16);                       \
                _Pragma("unroll")                                                  \
                for (int s = 0; s < 2; s++) {                                      \
                    MMA_OP(acc[s][nt], ah[s], bh0, bh1);                           \
                    MMA_OP(acc[s][nt], ah[s], bl0, bl1);                           \
                    MMA_OP(acc[s][nt], al[s], bh0, bh1);                           \
                }                                                                  \
            }                                                                      \
        }                                                                          \
        CPA_WAIT0();                                                               \
        __syncthreads();                                                           \
    }

__global__ void __launch_bounds__(256, 2) gemm_smem(
    const __nv_bfloat16* __restrict__ A_hi, const __nv_bfloat16* __restrict__ A_lo,
    const __nv_bfloat16* __restrict__ Bt_hi, const __nv_bfloat16* __restrict__ Bt_lo,
    const float* __restrict__ bias, float* __restrict__ C) {
    GEMM_PRE()
    #pragma unroll
    for (int s = 0; s < 2; s++) {
        int r = row0 + warp_m * 32 + s * 16 + g;
        #pragma unroll
        for (int nt = 0; nt < 8; nt++) {
            int c = col0 + warp_n * 64 + nt * 8 + t * 2;
            float bx = __ldg(&bias[c]), by = __ldg(&bias[c + 1]);
            *(float2*)(C + r * DD + c)       = make_float2(acc[s][nt][0] + bx, acc[s][nt][1] + by);
            *(float2*)(C + (r + 8) * DD + c) = make_float2(acc[s][nt][2] + bx, acc[s][nt][3] + by);
        }
    }
}

// p-net GEMM with fully fused output epilogue:
// out[r,c] = acc + av2[b(r),c] + sum_k px[r,k]*Wi[k,c]
__global__ void __launch_bounds__(256, 2) gemm_fused_out(
    const __nv_bfloat16* __restrict__ A_hi, const __nv_bfloat16* __restrict__ A_lo,
    const __nv_bfloat16* __restrict__ Bt_hi, const __nv_bfloat16* __restrict__ Bt_lo,
    const float* __restrict__ av2, const float* __restrict__ px,
    const float* __restrict__ Wi, float* __restrict__ Cout) {
    GEMM_PRE()
    #pragma unroll
    for (int s = 0; s < 2; s++) {
        #pragma unroll
        for (int half = 0; half < 2; half++) {
            int rr = row0 + warp_m * 32 + s * 16 + g + half * 8;
            int bg = rr / NPP;
            const float* xr = px + rr * FP;
            float xv[8];
            #pragma unroll
            for (int k = 0; k < 8; k++) xv[k] = __ldg(&xr[k]);
            #pragma unroll
            for (int nt = 0; nt < 8; nt++) {
                int c = col0 + warp_n * 64 + nt * 8 + t * 2;
                float a0 = acc[s][nt][half * 2 + 0];
                float a1 = acc[s][nt][half * 2 + 1];
                float v0 = __ldg(&av2[bg * DD + c]);
                float v1 = __ldg(&av2[bg * DD + c + 1]);
                float p0 = 0.f, p1 = 0.f;
                #pragma unroll
                for (int k = 0; k < 8; k++) {
                    float2 w = *(const float2*)(Wi + k * DD + c);
                    p0 = fmaf(xv[k], w.x, p0);
                    p1 = fmaf(xv[k], w.y, p1);
                }
                *(float2*)(Cout + (size_t)rr * DD + c) = make_float2(a0 + v0 + p0, a1 + v1 + p1);
            }
        }
    }
}

// ---------------- pooling / combine ----------------
__global__ __launch_bounds__(256) void pool_v_kernel(
    const float* __restrict__ node_emb, float* __restrict__ g) {
    int b = blockIdx.x, d = threadIdx.x;
    const float* p = node_emb + (size_t)b * NPV * DD + d;
    float s = 0.f;
    #pragma unroll
    for (int i = 0; i < NPV; i++) s += p[i * DD];
    g[b * DD + d] = s * (1.0f / NPV);
}

// av2[b,d] = (meanAgg[b])@W2[d] + 2*b2[d] + bi[d] + 2*vg + v_node[cid] + v_init[cid]
__global__ __launch_bounds__(256) void pg_addvec(
    const float* __restrict__ part, const float* __restrict__ W2,
    const float* __restrict__ p_b2, const float* __restrict__ p_bi,
    const float* __restrict__ vg, const float* __restrict__ v_node,
    const float* __restrict__ v_init, const int* __restrict__ curr,
    float* __restrict__ av2) {
    int b = blockIdx.x, d = threadIdx.x;
    __shared__ float pa[DD];
    float s = 0.f;
    #pragma unroll
    for (int j = 0; j < PPOOL; j++) s += part[(b * PPOOL + j) * DD + d];
    pa[d] = s * (1.0f / NPP);
    __syncthreads();
    float acc = 0.f;
    #pragma unroll 8
    for (int k = 0; k < DD; k++)
        acc = fmaf(pa[k], __ldg(&W2[k * DD + d]), acc);
    int cid = curr[b];
    int vi = (b * NPV + cid) * DD + d;
    av2[b * DD + d] = acc + 2.0f * __ldg(&p_b2[d]) + __ldg(&p_bi[d])
                    + 2.0f * vg[b * DD + d] + v_node[vi] + v_init[vi];
}

// ---------------- host launch ----------------
static inline void* sym(const void* s) {
    void* p = nullptr;
    cudaGetSymbolAddress(&p, s);
    return p;
}

extern "C" void kernel_launch(void* const* d_in, const int* in_sizes, int n_in,
                              void* d_out, int out_size) {
    const float* v_x     = (const float*)d_in[0];
    const float* p_x     = (const float*)d_in[1];
    const int*   v_src   = (const int*)d_in[2];
    const int*   v_dst   = (const int*)d_in[3];
    const int*   p_src   = (const int*)d_in[4];
    const int*   p_dst   = (const int*)d_in[5];
    const int*   curr    = (const int*)d_in[8];
    const float* v_initW = (const float*)d_in[9];
    const float* v_initb = (const float*)d_in[10];
    const float* v_W1    = (const float*)d_in[11];
    const float* v_b1    = (const float*)d_in[12];
    const float* v_W2    = (const float*)d_in[13];
    const float* v_b2    = (const float*)d_in[14];
    const float* p_initW = (const float*)d_in[15];
    const float* p_initb = (const float*)d_in[16];
    const float* p_W1    = (const float*)d_in[17];
    const float* p_b1    = (const float*)d_in[18];
    const float* p_W2    = (const float*)d_in[19];
    const float* p_b2    = (const float*)d_in[20];
    float* out = (float*)d_out;

    float* p_tmp  = (float*)sym(g_p_tmp);
    __nv_bfloat16* p_hi = (__nv_bfloat16*)sym(g_p_hi);
    __nv_bfloat16* p_lo = (__nv_bfloat16*)sym(g_p_lo);
    float* v_init = (float*)sym(g_v_init);
    float* v_tmp  = (float*)sym(g_v_tmp);
    float* v_node = (float*)sym(g_v_node);
    __nv_bfloat16* v_hi = (__nv_bfloat16*)sym(g_v_hi);
    __nv_bfloat16* v_lo = (__nv_bfloat16*)sym(g_v_lo);
    __nv_bfloat16* wtv2h = (__nv_bfloat16*)sym(g_wtv2_hi);
    __nv_bfloat16* wtv2l = (__nv_bfloat16*)sym(g_wtv2_lo);
    __nv_bfloat16* wtp2h = (__nv_bfloat16*)sym(g_wtp2_hi);
    __nv_bfloat16* wtp2l = (__nv_bfloat16*)sym(g_wtp2_lo);
    float* Mp = (float*)sym(g_Mp);
    float* Mv = (float*)sym(g_Mv);
    float* p_agg8 = (float*)sym(g_p_agg8);
    float* p_s    = (float*)sym(g_p_s);
    float* v_agg8 = (float*)sym(g_v_agg8);
    float* v_s    = (float*)sym(g_v_s);
    int* p_indeg  = (int*)sym(g_p_indeg);
    int* v_indeg  = (int*)sym(g_v_indeg);
    float* p_dinv = (float*)sym(g_p_dinv);
    float* v_dinv = (float*)sym(g_v_dinv);
    int* p_csr    = (int*)sym(g_p_csr);
    int* v_csr    = (int*)sym(g_v_csr);
    float* pgp    = (float*)sym(g_pg_part);
    float* vg     = (float*)sym(g_vg);
    float* av2    = (float*)sym(g_av2);

    cudaFuncSetAttribute(gemm_smem, cudaFuncAttributeMaxDynamicSharedMemorySize, GEMM_SMEM);
    cudaFuncSetAttribute(gemm_fused_out, cudaFuncAttributeMaxDynamicSharedMemorySize, GEMM_SMEM);

    // graph structure
    zero_all<<<(NPG + NVG + 255) / 256, 256>>>(p_indeg, v_indeg);
    build_csr<<<(EV + 255) / 256, 256>>>(v_src, v_dst, EV, v_indeg, v_csr);
    build_csr<<<(EP + 255) / 256, 256>>>(p_src, p_dst, EP, p_indeg, p_csr);
    dinv_both<<<(NPG + NVG + 255) / 256, 256>>>(p_indeg, v_indeg, p_dinv, v_dinv);
    // weight prep
    prep_M_both<<<18, 256>>>(p_initW, p_initb, p_W1, v_initW, v_initb, v_W1, Mp, Mv);
    prep_wt_both<<<512, 256>>>(p_W2, v_W2, wtp2h, wtp2l, wtv2h, wtv2l);
    // v init emb
    init_emb_kernel<<<NVG, 256>>>(v_x, v_initW, v_initb, v_init, FV);
    // layer 1 both nets
    agg8_both<<<(NPG + NVG + 255) / 256, 256>>>(p_x, v_x, p_csr, v_csr, p_indeg, v_indeg,
                                                p_dinv, v_dinv, p_agg8, v_agg8, p_s, v_s);
    layer1_both<<<NPG + NVG, 256>>>(p_agg8, p_s, v_agg8, v_s, Mp, Mv, p_b1, v_b1, p_tmp, v_tmp);
    // v net layer 2 + pooling
    gcn_agg<<<(NVG + 7) / 8, 256>>>(v_tmp, v_csr, v_indeg, v_dinv, v_hi, v_lo, NVG);
    {
        dim3 gv(2, NVG / 128);
        gemm_smem<<<gv, 256, GEMM_SMEM>>>(v_hi, v_lo, wtv2h, wtv2l, v_b2, v_node);
    }
    pool_v_kernel<<<NB, 256>>>(v_node, vg);
    // p net layer 2: agg -> bf16 pooling -> av2 -> fused GEMM out
    gcn_agg<<<(NPG + 7) / 8, 256>>>(p_tmp, p_csr, p_indeg, p_dinv, p_hi, p_lo, NPG);
    {
        dim3 g(NB, PPOOL);
        pool_p_bf16<<<g, 256>>>(p_hi, p_lo, pgp);
    }
    pg_addvec<<<NB, 256>>>(pgp, p_W2, p_b2, p_initb, vg, v_node, v_init, curr, av2);
    {
        dim3 gp(2, NPG / 128);
        gemm_fused_out<<<gp, 256, GEMM_SMEM>>>(p_hi, p_lo, wtp2h, wtp2l, av2, p_x, p_initW, out);
    }
}

// round 10
// speedup vs baseline: 1.1127x; 1.1127x over previous
#include <cuda_runtime.h>
#include <cuda_bf16.h>
#include <cstdint>

// ---------------- problem constants ----------------
#define NB   128
#define NPV  20
#define NPP  500
#define NVG  (NB*NPV)     // 2560
#define NPG  (NB*NPP)     // 64000
#define DD   256
#define FV   6
#define FP   8
#define DEG  8
#define EV   (NVG*DEG)
#define EP   (NPG*DEG)
#define CAP  64
#define PPOOL 10

// ---------------- static device scratch ----------------
__device__ float g_p_tmp [NPG*DD];            // h1 (p layer-1 output)
__device__ float g_p_node[NPG*DD];            // p layer-2 output
__device__ __nv_bfloat16 g_p_hi[NPG*DD];      // agg(h1) split
__device__ __nv_bfloat16 g_p_lo[NPG*DD];

__device__ float g_v_init[NVG*DD];
__device__ float g_v_tmp [NVG*DD];
__device__ float g_v_node[NVG*DD];
__device__ __nv_bfloat16 g_v_hi[NVG*DD];
__device__ __nv_bfloat16 g_v_lo[NVG*DD];

__device__ __nv_bfloat16 g_wtv2_hi[DD*DD]; __device__ __nv_bfloat16 g_wtv2_lo[DD*DD];
__device__ __nv_bfloat16 g_wtp2_hi[DD*DD]; __device__ __nv_bfloat16 g_wtp2_lo[DD*DD];

__device__ float g_Mp[9*DD];   // rows 0-7: Wi@W1 (zero-padded); row 8: bi@W1
__device__ float g_Mv[9*DD];

__device__ float g_p_agg8[NPG*8];
__device__ float g_p_s[NPG];
__device__ float g_v_agg8[NVG*8];
__device__ float g_v_s[NVG];

__device__ int   g_p_indeg[NPG];
__device__ int   g_v_indeg[NVG];
__device__ float g_p_dinv[NPG];
__device__ float g_v_dinv[NVG];
__device__ int   g_p_csr[NPG*CAP];
__device__ int   g_v_csr[NVG*CAP];

__device__ float g_pg_part[NB*PPOOL*DD];
__device__ float g_vg[NB*DD];
__device__ float g_addvec[NB*DD];

// ---------------- helpers ----------------
__device__ __forceinline__ uint32_t smem_u32(const void* p) {
    uint32_t a;
    asm("{ .reg .u64 t; cvta.to.shared.u64 t, %1; cvt.u32.u64 %0, t; }" : "=r"(a) : "l"(p));
    return a;
}
__device__ __forceinline__ void cpa16(uint32_t dst, const void* src) {
    asm volatile("cp.async.cg.shared.global [%0], [%1], 16;" :: "r"(dst), "l"(src) : "memory");
}
#define CPA_COMMIT() asm volatile("cp.async.commit_group;" ::: "memory")
#define CPA_WAIT0()  asm volatile("cp.async.wait_group 0;" ::: "memory")

#define MMA_OP(ACC, AH, B0, B1)                                                   \
    asm volatile(                                                                  \
        "mma.sync.aligned.m16n8k16.row.col.f32.bf16.bf16.f32 "                    \
        "{%0,%1,%2,%3}, {%4,%5,%6,%7}, {%8,%9}, {%0,%1,%2,%3};"                   \
        : "+f"((ACC)[0]), "+f"((ACC)[1]), "+f"((ACC)[2]), "+f"((ACC)[3])          \
        : "r"((AH)[0]), "r"((AH)[1]), "r"((AH)[2]), "r"((AH)[3]),                 \
          "r"(B0), "r"(B1))

// ---------------- setup kernels (merged) ----------------
__global__ void zero_all(int* p_indeg, int* v_indeg) {
    int i = blockIdx.x * blockDim.x + threadIdx.x;
    if (i < NPG) p_indeg[i] = 0;
    else if (i < NPG + NVG) v_indeg[i - NPG] = 0;
}
__global__ void build_csr(const int* __restrict__ src, const int* __restrict__ dst,
                          int E, int* __restrict__ indeg, int* __restrict__ csr) {
    int e = blockIdx.x * blockDim.x + threadIdx.x;
    if (e >= E) return;
    int d = dst[e];
    int slot = atomicAdd(&indeg[d], 1);
    if (slot < CAP) csr[d * CAP + slot] = src[e];
}
__global__ void dinv_both(const int* __restrict__ p_indeg, const int* __restrict__ v_indeg,
                          float* __restrict__ p_dinv, float* __restrict__ v_dinv) {
    int i = blockIdx.x * blockDim.x + threadIdx.x;
    if (i < NPG) p_dinv[i] = rsqrtf((float)p_indeg[i] + 1.0f);
    else if (i < NPG + NVG) v_dinv[i - NPG] = rsqrtf((float)v_indeg[i - NPG] + 1.0f);
}

// M rows 0..7 = Wi@W1 (zero-padded); row 8 = bi@W1 ; grid 18 covers p (0-8) and v (9-17)
__global__ __launch_bounds__(256) void prep_M_both(
    const float* __restrict__ pWi, const float* __restrict__ pbi, const float* __restrict__ pW1,
    const float* __restrict__ vWi, const float* __restrict__ vbi, const float* __restrict__ vW1,
    float* __restrict__ Mp, float* __restrict__ Mv) {
    int blk = blockIdx.x, d = threadIdx.x;
    const float* Wi; const float* bi; const float* W1; float* M; int F, f;
    if (blk < 9) { Wi = pWi; bi = pbi; W1 = pW1; M = Mp; F = FP; f = blk; }
    else         { Wi = vWi; bi = vbi; W1 = vW1; M = Mv; F = FV; f = blk - 9; }
    float acc = 0.0f;
    if (f < 8) {
        if (f < F)
            for (int j = 0; j < DD; j++)
                acc = fmaf(__ldg(&Wi[f * DD + j]), __ldg(&W1[j * DD + d]), acc);
    } else {
        for (int j = 0; j < DD; j++)
            acc = fmaf(__ldg(&bi[j]), __ldg(&W1[j * DD + d]), acc);
    }
    M[f * DD + d] = acc;
}

// transpose + bf16 split both W2s; grid 512
__global__ __launch_bounds__(256) void prep_wt_both(
    const float* __restrict__ pW2, const float* __restrict__ vW2,
    __nv_bfloat16* __restrict__ phi, __nv_bfloat16* __restrict__ plo,
    __nv_bfloat16* __restrict__ vhi, __nv_bfloat16* __restrict__ vlo) {
    int blk = blockIdx.x, k = threadIdx.x;
    const float* W; __nv_bfloat16 *hi, *lo; int n;
    if (blk < DD) { W = pW2; hi = phi; lo = plo; n = blk; }
    else          { W = vW2; hi = vhi; lo = vlo; n = blk - DD; }
    float w = W[k * DD + n];
    __nv_bfloat16 h = __float2bfloat16_rn(w);
    hi[n * DD + k] = h;
    lo[n * DD + k] = __float2bfloat16_rn(w - __bfloat162float(h));
}

// v init emb (needed in addvec)
__global__ __launch_bounds__(256) void init_emb_kernel(
    const float* __restrict__ x, const float* __restrict__ W, const float* __restrict__ b,
    float* __restrict__ out, int F) {
    int node = blockIdx.x, d = threadIdx.x;
    const float* xr = x + node * F;
    float acc = __ldg(&b[d]);
    #pragma unroll 8
    for (int k = 0; k < 8; k++)
        if (k < F) acc = fmaf(__ldg(&xr[k]), __ldg(&W[k * DD + d]), acc);
    out[node * DD + d] = acc;
}

// ---------------- layer 1: feature-space agg (both nets, one launch) -------------
__global__ __launch_bounds__(256) void agg8_both(
    const float* __restrict__ px, const float* __restrict__ vx,
    const int* __restrict__ p_csr, const int* __restrict__ v_csr,
    const int* __restrict__ p_indeg, const int* __restrict__ v_indeg,
    const float* __restrict__ p_dinv, const float* __restrict__ v_dinv,
    float* __restrict__ p_agg8, float* __restrict__ v_agg8,
    float* __restrict__ p_s, float* __restrict__ v_s) {
    int i = blockIdx.x * blockDim.x + threadIdx.x;
    const float* x; const int* csr; const int* indeg; const float* dinv;
    float* agg8; float* sv; int node, F;
    if (i < NPG) { x = px; csr = p_csr; indeg = p_indeg; dinv = p_dinv;
                   agg8 = p_agg8; sv = p_s; node = i; F = FP; }
    else if (i < NPG + NVG) { x = vx; csr = v_csr; indeg = v_indeg; dinv = v_dinv;
                   agg8 = v_agg8; sv = v_s; node = i - NPG; F = FV; }
    else return;
    int deg = indeg[node];
    int cnt = deg < CAP ? deg : CAP;
    float self = 1.0f / ((float)deg + 1.0f);
    float ddst = dinv[node];
    float a[8];
    #pragma unroll
    for (int f = 0; f < 8; f++) a[f] = 0.0f;
    if (F == 8) {
        float4 x0 = *(const float4*)(x + node * 8);
        float4 x1 = *(const float4*)(x + node * 8 + 4);
        a[0] = x0.x * self; a[1] = x0.y * self; a[2] = x0.z * self; a[3] = x0.w * self;
        a[4] = x1.x * self; a[5] = x1.y * self; a[6] = x1.z * self; a[7] = x1.w * self;
    } else {
        for (int f = 0; f < F; f++) a[f] = x[node * F + f] * self;
    }
    float ssum = self;
    const int* cp = csr + node * CAP;
    for (int e = 0; e < cnt; e++) {
        int src = cp[e];
        float c = ddst * dinv[src];
        ssum += c;
        if (F == 8) {
            float4 m0 = *(const float4*)(x + src * 8);
            float4 m1 = *(const float4*)(x + src * 8 + 4);
            a[0] = fmaf(c, m0.x, a[0]); a[1] = fmaf(c, m0.y, a[1]);
            a[2] = fmaf(c, m0.z, a[2]); a[3] = fmaf(c, m0.w, a[3]);
            a[4] = fmaf(c, m1.x, a[4]); a[5] = fmaf(c, m1.y, a[5]);
            a[6] = fmaf(c, m1.z, a[6]); a[7] = fmaf(c, m1.w, a[7]);
        } else {
            for (int f = 0; f < F; f++) a[f] = fmaf(c, x[src * F + f], a[f]);
        }
    }
    *(float4*)(agg8 + node * 8)     = make_float4(a[0], a[1], a[2], a[3]);
    *(float4*)(agg8 + node * 8 + 4) = make_float4(a[4], a[5], a[6], a[7]);
    sv[node] = ssum;
}

// h1 = relu(agg8 @ M[0:8] + s * M[8] + b1) ; blocks cover p then v
__global__ __launch_bounds__(256) void layer1_both(
    const float* __restrict__ p_agg8, const float* __restrict__ p_sv,
    const float* __restrict__ v_agg8, const float* __restrict__ v_sv,
    const float* __restrict__ Mp, const float* __restrict__ Mv,
    const float* __restrict__ pb1, const float* __restrict__ vb1,
    float* __restrict__ p_h1, float* __restrict__ v_h1) {
    int blk = blockIdx.x, d = threadIdx.x;
    const float* agg8; const float* sv; const float* M; const float* b1; float* h1; int node;
    if (blk < NPG) { agg8 = p_agg8; sv = p_sv; M = Mp; b1 = pb1; h1 = p_h1; node = blk; }
    else           { agg8 = v_agg8; sv = v_sv; M = Mv; b1 = vb1; h1 = v_h1; node = blk - NPG; }
    float a0 = __ldg(&agg8[node * 8 + 0]), a1 = __ldg(&agg8[node * 8 + 1]);
    float a2 = __ldg(&agg8[node * 8 + 2]), a3 = __ldg(&agg8[node * 8 + 3]);
    float a4 = __ldg(&agg8[node * 8 + 4]), a5 = __ldg(&agg8[node * 8 + 5]);
    float a6 = __ldg(&agg8[node * 8 + 6]), a7 = __ldg(&agg8[node * 8 + 7]);
    float ss = __ldg(&sv[node]);
    float acc = __ldg(&b1[d]) + ss * __ldg(&M[8 * DD + d]);
    acc = fmaf(a0, __ldg(&M[0 * DD + d]), acc);
    acc = fmaf(a1, __ldg(&M[1 * DD + d]), acc);
    acc = fmaf(a2, __ldg(&M[2 * DD + d]), acc);
    acc = fmaf(a3, __ldg(&M[3 * DD + d]), acc);
    acc = fmaf(a4, __ldg(&M[4 * DD + d]), acc);
    acc = fmaf(a5, __ldg(&M[5 * DD + d]), acc);
    acc = fmaf(a6, __ldg(&M[6 * DD + d]), acc);
    acc = fmaf(a7, __ldg(&M[7 * DD + d]), acc);
    h1[node * DD + d] = fmaxf(acc, 0.0f);
}

// ---------------- 256-dim aggregation -> bf16 split (clean, no sync) ----------
__global__ __launch_bounds__(256) void gcn_agg(
    const float* __restrict__ h, const int* __restrict__ csr, const int* __restrict__ indeg,
    const float* __restrict__ dinv, __nv_bfloat16* __restrict__ out_hi,
    __nv_bfloat16* __restrict__ out_lo, int n_nodes) {
    int warp = threadIdx.x >> 5;
    int lane = threadIdx.x & 31;
    int node = blockIdx.x * 8 + warp;
    if (node >= n_nodes) return;
    int d0 = lane * 8;

    int deg = indeg[node];
    int cnt = deg < CAP ? deg : CAP;
    float self = 1.0f / ((float)deg + 1.0f);
    float ddst = dinv[node];
    const float* hn = h + node * DD + d0;
    float4 s0 = *(const float4*)hn;
    float4 s1 = *(const float4*)(hn + 4);
    float4 acc0 = make_float4(s0.x * self, s0.y * self, s0.z * self, s0.w * self);
    float4 acc1 = make_float4(s1.x * self, s1.y * self, s1.z * self, s1.w * self);
    const int* cp = csr + node * CAP;
    for (int e = 0; e < cnt; e++) {
        int src = cp[e];
        float c = ddst * dinv[src];
        const float* hs = h + src * DD + d0;
        float4 m0 = *(const float4*)hs;
        float4 m1 = *(const float4*)(hs + 4);
        acc0.x = fmaf(c, m0.x, acc0.x); acc0.y = fmaf(c, m0.y, acc0.y);
        acc0.z = fmaf(c, m0.z, acc0.z); acc0.w = fmaf(c, m0.w, acc0.w);
        acc1.x = fmaf(c, m1.x, acc1.x); acc1.y = fmaf(c, m1.y, acc1.y);
        acc1.z = fmaf(c, m1.z, acc1.z); acc1.w = fmaf(c, m1.w, acc1.w);
    }
    int base = node * DD + d0;
    float v[8] = {acc0.x, acc0.y, acc0.z, acc0.w, acc1.x, acc1.y, acc1.z, acc1.w};
    uint32_t hw[4], lw[4];
    #pragma unroll
    for (int q = 0; q < 4; q++) {
        __nv_bfloat16 h0 = __float2bfloat16_rn(v[q * 2]);
        __nv_bfloat16 h1v = __float2bfloat16_rn(v[q * 2 + 1]);
        __nv_bfloat16 l0 = __float2bfloat16_rn(v[q * 2] - __bfloat162float(h0));
        __nv_bfloat16 l1 = __float2bfloat16_rn(v[q * 2 + 1] - __bfloat162float(h1v));
        __nv_bfloat162 hp = __nv_bfloat162(h0, h1v);
        __nv_bfloat162 lp = __nv_bfloat162(l0, l1);
        hw[q] = *(uint32_t*)&hp;
        lw[q] = *(uint32_t*)&lp;
    }
    *(uint4*)(out_hi + base) = make_uint4(hw[0], hw[1], hw[2], hw[3]);
    *(uint4*)(out_lo + base) = make_uint4(lw[0], lw[1], lw[2], lw[3]);
}

// ---------------- smem-staged bf16-split GEMM (R7-proven) ----------------
#define KC 32
#define APITCH 80
#define PIECE (128*APITCH)
#define STAGE_BYTES (4*PIECE)
#define GEMM_SMEM (2*STAGE_BYTES)

__global__ void __launch_bounds__(256, 2) gemm_smem(
    const __nv_bfloat16* __restrict__ A_hi, const __nv_bfloat16* __restrict__ A_lo,
    const __nv_bfloat16* __restrict__ Bt_hi, const __nv_bfloat16* __restrict__ Bt_lo,
    const float* __restrict__ bias, float* __restrict__ C) {
    extern __shared__ char sm[];
    uint32_t sb = smem_u32(sm);
    int tid = threadIdx.x;
    int wid = tid >> 5, lane = tid & 31;
    int g = lane >> 2, t = lane & 3;
    int warp_m = wid & 3, warp_n = wid >> 2;
    int row0 = blockIdx.y * 128;
    int col0 = blockIdx.x * 128;

    float acc[2][8][4];
    #pragma unroll
    for (int s = 0; s < 2; s++)
        #pragma unroll
        for (int n = 0; n < 8; n++)
            #pragma unroll
            for (int q = 0; q < 4; q++) acc[s][n][q] = 0.0f;

    int r0i = (tid + 0) >> 2,  c0i = (tid + 0) & 3;
    int r1i = (tid + 256) >> 2, c1i = (tid + 256) & 3;

    auto stage_load = [&](int st) {
        uint32_t base = sb + (st & 1) * STAGE_BYTES;
        int kc0 = st * KC;
        {
            uint32_t d0 = base + r0i * APITCH + c0i * 16;
            size_t ga = (size_t)(row0 + r0i) * DD + kc0 + c0i * 8;
            size_t gb = (size_t)(col0 + r0i) * DD + kc0 + c0i * 8;
            cpa16(d0,           A_hi + ga);
            cpa16(d0 + PIECE,   A_lo + ga);
            cpa16(d0 + 2*PIECE, Bt_hi + gb);
            cpa16(d0 + 3*PIECE, Bt_lo + gb);
        }
        {
            uint32_t d0 = base + r1i * APITCH + c1i * 16;
            size_t ga = (size_t)(row0 + r1i) * DD + kc0 + c1i * 8;
            size_t gb = (size_t)(col0 + r1i) * DD + kc0 + c1i * 8;
            cpa16(d0,           A_hi + ga);
            cpa16(d0 + PIECE,   A_lo + ga);
            cpa16(d0 + 2*PIECE, Bt_hi + gb);
            cpa16(d0 + 3*PIECE, Bt_lo + gb);
        }
        CPA_COMMIT();
    };

    stage_load(0);
    CPA_WAIT0();
    __syncthreads();

    for (int st = 0; st < DD / KC; st++) {
        if (st + 1 < DD / KC) stage_load(st + 1);
        const char* cur = sm + (st & 1) * STAGE_BYTES;

        #pragma unroll
        for (int kk = 0; kk < 2; kk++) {
            int kb = (kk * 16 + t * 2) * 2;
            uint32_t ah[2][4], al[2][4];
            #pragma unroll
            for (int s = 0; s < 2; s++) {
                const char* pa = cur + (warp_m * 32 + s * 16 + g) * APITCH + kb;
                ah[s][0] = *(const uint32_t*)pa;
                ah[s][1] = *(const uint32_t*)(pa + 8 * APITCH);
                ah[s][2] = *(const uint32_t*)(pa + 16);
                ah[s][3] = *(const uint32_t*)(pa + 8 * APITCH + 16);
                const char* pl = pa + PIECE;
                al[s][0] = *(const uint32_t*)pl;
                al[s][1] = *(const uint32_t*)(pl + 8 * APITCH);
                al[s][2] = *(const uint32_t*)(pl + 16);
                al[s][3] = *(const uint32_t*)(pl + 8 * APITCH + 16);
            }
            #pragma unroll
            for (int nt = 0; nt < 8; nt++) {
                const char* pb = cur + 2 * PIECE + (warp_n * 64 + nt * 8 + g) * APITCH + kb;
                uint32_t bh0 = *(const uint32_t*)pb;
                uint32_t bh1 = *(const uint32_t*)(pb + 16);
                const char* pbl = pb + PIECE;
                uint32_t bl0 = *(const uint32_t*)pbl;
                uint32_t bl1 = *(const uint32_t*)(pbl + 16);
                #pragma unroll
                for (int s = 0; s < 2; s++) {
                    MMA_OP(acc[s][nt], ah[s], bh0, bh1);
                    MMA_OP(acc[s][nt], ah[s], bl0, bl1);
                    MMA_OP(acc[s][nt], al[s], bh0, bh1);
                }
            }
        }
        CPA_WAIT0();
        __syncthreads();
    }

    #pragma unroll
    for (int s = 0; s < 2; s++) {
        int r = row0 + warp_m * 32 + s * 16 + g;
        #pragma unroll
        for (int nt = 0; nt < 8; nt++) {
            int c = col0 + warp_n * 64 + nt * 8 + t * 2;
            float bx = __ldg(&bias[c]), by = __ldg(&bias[c + 1]);
            *(float2*)(C + r * DD + c)       = make_float2(acc[s][nt][0] + bx, acc[s][nt][1] + by);
            *(float2*)(C + (r + 8) * DD + c) = make_float2(acc[s][nt][2] + bx, acc[s][nt][3] + by);
        }
    }
}

// ---------------- pooling / fuse (R7-proven) ----------------
__global__ __launch_bounds__(256) void pool_v_kernel(
    const float* __restrict__ node_emb, float* __restrict__ g) {
    int b = blockIdx.x, d = threadIdx.x;
    const float* p = node_emb + (size_t)b * NPV * DD + d;
    float s = 0.f;
    #pragma unroll
    for (int i = 0; i < NPV; i++) s += p[i * DD];
    g[b * DD + d] = s * (1.0f / NPV);
}
__global__ __launch_bounds__(256) void pool_p_partial(
    const float* __restrict__ node_emb, float* __restrict__ part) {
    int b = blockIdx.x, ppart = blockIdx.y, d = threadIdx.x;
    const int chunk = NPP / PPOOL;
    const float* p = node_emb + ((size_t)b * NPP + ppart * chunk) * DD + d;
    float s0 = 0.f, s1 = 0.f;
    #pragma unroll
    for (int i = 0; i < chunk; i += 2) {
        s0 += p[i * DD];
        s1 += p[(i + 1) * DD];
    }
    part[(b * PPOOL + ppart) * DD + d] = s0 + s1;
}
__global__ void addvec_kernel(const float* __restrict__ pg_part, const float* __restrict__ vg,
                              const float* __restrict__ v_node, const float* __restrict__ v_init,
                              const int* __restrict__ curr, float* __restrict__ av) {
    int b = blockIdx.x, d = threadIdx.x;
    float pgs = 0.f;
    #pragma unroll
    for (int j = 0; j < PPOOL; j++) pgs += pg_part[(b * PPOOL + j) * DD + d];
    float pgd = pgs * (1.0f / NPP);
    int cid = curr[b];
    int vi = (b * NPV + cid) * DD + d;
    av[b * DD + d] = pgd + 2.0f * vg[b * DD + d] + v_node[vi] + v_init[vi];
}

// out = p_node + (p_x@Wi + bi) + addvec[b]
__global__ void final_kernel(const float* __restrict__ pn, const float* __restrict__ px,
                             const float* __restrict__ Wi, const float* __restrict__ bi,
                             const float* __restrict__ av, float* __restrict__ out) {
    int idx = blockIdx.x * blockDim.x + threadIdx.x;
    const int total4 = NPG * (DD / 4);
    if (idx >= total4) return;
    int node = idx >> 6;
    int d4 = idx & 63;
    int d = d4 * 4;
    int b = node / NPP;
    float4 a = ((const float4*)pn)[idx];
    float4 v = ((const float4*)av)[b * (DD / 4) + d4];
    float4 bb = *(const float4*)(bi + d);
    float4 r = make_float4(a.x + v.x + bb.x, a.y + v.y + bb.y,
                           a.z + v.z + bb.z, a.w + v.w + bb.w);
    const float* xr = px + node * FP;
    #pragma unroll
    for (int k = 0; k < FP; k++) {
        float xv = __ldg(&xr[k]);
        float4 w = *(const float4*)(Wi + k * DD + d);
        r.x = fmaf(xv, w.x, r.x); r.y = fmaf(xv, w.y, r.y);
        r.z = fmaf(xv, w.z, r.z); r.w = fmaf(xv, w.w, r.w);
    }
    ((float4*)out)[idx] = r;
}

// ---------------- host launch ----------------
static inline void* sym(const void* s) {
    void* p = nullptr;
    cudaGetSymbolAddress(&p, s);
    return p;
}

extern "C" void kernel_launch(void* const* d_in, const int* in_sizes, int n_in,
                              void* d_out, int out_size) {
    const float* v_x     = (const float*)d_in[0];
    const float* p_x     = (const float*)d_in[1];
    const int*   v_src   = (const int*)d_in[2];
    const int*   v_dst   = (const int*)d_in[3];
    const int*   p_src   = (const int*)d_in[4];
    const int*   p_dst   = (const int*)d_in[5];
    const int*   curr    = (const int*)d_in[8];
    const float* v_initW = (const float*)d_in[9];
    const float* v_initb = (const float*)d_in[10];
    const float* v_W1    = (const float*)d_in[11];
    const float* v_b1    = (const float*)d_in[12];
    const float* v_W2    = (const float*)d_in[13];
    const float* v_b2    = (const float*)d_in[14];
    const float* p_initW = (const float*)d_in[15];
    const float* p_initb = (const float*)d_in[16];
    const float* p_W1    = (const float*)d_in[17];
    const float* p_b1    = (const float*)d_in[18];
    const float* p_W2    = (const float*)d_in[19];
    const float* p_b2    = (const float*)d_in[20];
    float* out = (float*)d_out;

    float* p_tmp  = (float*)sym(g_p_tmp);
    float* p_node = (float*)sym(g_p_node);
    __nv_bfloat16* p_hi = (__nv_bfloat16*)sym(g_p_hi);
    __nv_bfloat16* p_lo = (__nv_bfloat16*)sym(g_p_lo);
    float* v_init = (float*)sym(g_v_init);
    float* v_tmp  = (float*)sym(g_v_tmp);
    float* v_node = (float*)sym(g_v_node);
    __nv_bfloat16* v_hi = (__nv_bfloat16*)sym(g_v_hi);
    __nv_bfloat16* v_lo = (__nv_bfloat16*)sym(g_v_lo);
    __nv_bfloat16* wtv2h = (__nv_bfloat16*)sym(g_wtv2_hi);
    __nv_bfloat16* wtv2l = (__nv_bfloat16*)sym(g_wtv2_lo);
    __nv_bfloat16* wtp2h = (__nv_bfloat16*)sym(g_wtp2_hi);
    __nv_bfloat16* wtp2l = (__nv_bfloat16*)sym(g_wtp2_lo);
    float* Mp = (float*)sym(g_Mp);
    float* Mv = (float*)sym(g_Mv);
    float* p_agg8 = (float*)sym(g_p_agg8);
    float* p_s    = (float*)sym(g_p_s);
    float* v_agg8 = (float*)sym(g_v_agg8);
    float* v_s    = (float*)sym(g_v_s);
    int* p_indeg  = (int*)sym(g_p_indeg);
    int* v_indeg  = (int*)sym(g_v_indeg);
    float* p_dinv = (float*)sym(g_p_dinv);
    float* v_dinv = (float*)sym(g_v_dinv);
    int* p_csr    = (int*)sym(g_p_csr);
    int* v_csr    = (int*)sym(g_v_csr);
    float* pgp    = (float*)sym(g_pg_part);
    float* vg     = (float*)sym(g_vg);
    float* av     = (float*)sym(g_addvec);

    cudaFuncSetAttribute(gemm_smem, cudaFuncAttributeMaxDynamicSharedMemorySize, GEMM_SMEM);

    // graph structure
    zero_all<<<(NPG + NVG + 255) / 256, 256>>>(p_indeg, v_indeg);
    build_csr<<<(EV + 255) / 256, 256>>>(v_src, v_dst, EV, v_indeg, v_csr);
    build_csr<<<(EP + 255) / 256, 256>>>(p_src, p_dst, EP, p_indeg, p_csr);
    dinv_both<<<(NPG + NVG + 255) / 256, 256>>>(p_indeg, v_indeg, p_dinv, v_dinv);
    // weight prep
    prep_M_both<<<18, 256>>>(p_initW, p_initb, p_W1, v_initW, v_initb, v_W1, Mp, Mv);
    prep_wt_both<<<512, 256>>>(p_W2, v_W2, wtp2h, wtp2l, wtv2h, wtv2l);
    // v init emb
    init_emb_kernel<<<NVG, 256>>>(v_x, v_initW, v_initb, v_init, FV);
    // layer 1 both nets
    agg8_both<<<(NPG + NVG + 255) / 256, 256>>>(p_x, v_x, p_csr, v_csr, p_indeg, v_indeg,
                                                p_dinv, v_dinv, p_agg8, v_agg8, p_s, v_s);
    layer1_both<<<NPG + NVG, 256>>>(p_agg8, p_s, v_agg8, v_s, Mp, Mv, p_b1, v_b1, p_tmp, v_tmp);
    // layer 2: agg then GEMM (both nets)
    gcn_agg<<<(NVG + 7) / 8, 256>>>(v_tmp, v_csr, v_indeg, v_dinv, v_hi, v_lo, NVG);
    gcn_agg<<<(NPG + 7) / 8, 256>>>(p_tmp, p_csr, p_indeg, p_dinv, p_hi, p_lo, NPG);
    {
        dim3 gp(2, NPG / 128);
        gemm_smem<<<gp, 256, GEMM_SMEM>>>(p_hi, p_lo, wtp2h, wtp2l, p_b2, p_node);
        dim3 gv(2, NVG / 128);
        gemm_smem<<<gv, 256, GEMM_SMEM>>>(v_hi, v_lo, wtv2h, wtv2l, v_b2, v_node);
    }
    // pooling + fuse
    pool_v_kernel<<<NB, 256>>>(v_node, vg);
    {
        dim3 g(NB, PPOOL);
        pool_p_partial<<<g, 256>>>(p_node, pgp);
    }
    addvec_kernel<<<NB, 256>>>(pgp, vg, v_node, v_init, curr, av);
    const int total4 = NPG * (DD / 4);
    final_kernel<<<(total4 + 255) / 256, 256>>>(p_node, p_x, p_initW, p_initb, av, out);
}

// round 12
// speedup vs baseline: 1.2156x; 1.0925x over previous
#include <cuda_runtime.h>
#include <cuda_bf16.h>
#include <cuda_fp16.h>
#include <cstdint>

// ---------------- problem constants ----------------
#define NB   128
#define NPV  20
#define NPP  500
#define NVG  (NB*NPV)     // 2560
#define NPG  (NB*NPP)     // 64000
#define DD   256
#define FV   6
#define FP   8
#define DEG  8
#define EV   (NVG*DEG)
#define EP   (NPG*DEG)
#define CAP  64
#define PPOOL 10

// ---------------- static device scratch ----------------
__device__ __half g_p_tmp [NPG*DD];           // h1 (p layer-1 output, fp16)
__device__ float  g_p_node[NPG*DD];           // p layer-2 output
__device__ __nv_bfloat16 g_p_hi[NPG*DD];      // agg(h1) split
__device__ __nv_bfloat16 g_p_lo[NPG*DD];

__device__ float  g_v_init[NVG*DD];
__device__ __half g_v_tmp [NVG*DD];           // v h1 (fp16)
__device__ float  g_v_node[NVG*DD];
__device__ __nv_bfloat16 g_v_hi[NVG*DD];
__device__ __nv_bfloat16 g_v_lo[NVG*DD];

__device__ __nv_bfloat16 g_wtv2_hi[DD*DD]; __device__ __nv_bfloat16 g_wtv2_lo[DD*DD];
__device__ __nv_bfloat16 g_wtp2_hi[DD*DD]; __device__ __nv_bfloat16 g_wtp2_lo[DD*DD];

__device__ float g_Mp[9*DD];   // rows 0-7: Wi@W1 (zero-padded); row 8: bi@W1
__device__ float g_Mv[9*DD];

__device__ float g_p_agg8[NPG*8];
__device__ float g_p_s[NPG];
__device__ float g_v_agg8[NVG*8];
__device__ float g_v_s[NVG];

__device__ int   g_p_indeg[NPG];
__device__ int   g_v_indeg[NVG];
__device__ float g_p_dinv[NPG];
__device__ float g_v_dinv[NVG];
__device__ int   g_p_csr[NPG*CAP];
__device__ int   g_v_csr[NVG*CAP];

__device__ float g_pg_part[NB*PPOOL*DD];
__device__ float g_vg[NB*DD];
__device__ float g_addvec[NB*DD];

// ---------------- helpers ----------------
__device__ __forceinline__ uint32_t smem_u32(const void* p) {
    uint32_t a;
    asm("{ .reg .u64 t; cvta.to.shared.u64 t, %1; cvt.u32.u64 %0, t; }" : "=r"(a) : "l"(p));
    return a;
}
__device__ __forceinline__ void cpa16(uint32_t dst, const void* src) {
    asm volatile("cp.async.cg.shared.global [%0], [%1], 16;" :: "r"(dst), "l"(src) : "memory");
}
#define CPA_COMMIT() asm volatile("cp.async.commit_group;" ::: "memory")
#define CPA_WAIT0()  asm volatile("cp.async.wait_group 0;" ::: "memory")

#define MMA_OP(ACC, AH, B0, B1)                                                   \
    asm volatile(                                                                  \
        "mma.sync.aligned.m16n8k16.row.col.f32.bf16.bf16.f32 "                    \
        "{%0,%1,%2,%3}, {%4,%5,%6,%7}, {%8,%9}, {%0,%1,%2,%3};"                   \
        : "+f"((ACC)[0]), "+f"((ACC)[1]), "+f"((ACC)[2]), "+f"((ACC)[3])          \
        : "r"((AH)[0]), "r"((AH)[1]), "r"((AH)[2]), "r"((AH)[3]),                 \
          "r"(B0), "r"(B1))

// ---------------- setup kernels ----------------
__global__ void zero_all(int* p_indeg, int* v_indeg) {
    int i = blockIdx.x * blockDim.x + threadIdx.x;
    if (i < NPG) p_indeg[i] = 0;
    else if (i < NPG + NVG) v_indeg[i - NPG] = 0;
}
__global__ void build_csr(const int* __restrict__ src, const int* __restrict__ dst,
                          int E, int* __restrict__ indeg, int* __restrict__ csr) {
    int e = blockIdx.x * blockDim.x + threadIdx.x;
    if (e >= E) return;
    int d = dst[e];
    int slot = atomicAdd(&indeg[d], 1);
    if (slot < CAP) csr[d * CAP + slot] = src[e];
}
__global__ void dinv_both(const int* __restrict__ p_indeg, const int* __restrict__ v_indeg,
                          float* __restrict__ p_dinv, float* __restrict__ v_dinv) {
    int i = blockIdx.x * blockDim.x + threadIdx.x;
    if (i < NPG) p_dinv[i] = rsqrtf((float)p_indeg[i] + 1.0f);
    else if (i < NPG + NVG) v_dinv[i - NPG] = rsqrtf((float)v_indeg[i - NPG] + 1.0f);
}

// M rows 0..7 = Wi@W1 (zero-padded); row 8 = bi@W1 ; grid 18 covers p (0-8) and v (9-17)
__global__ __launch_bounds__(256) void prep_M_both(
    const float* __restrict__ pWi, const float* __restrict__ pbi, const float* __restrict__ pW1,
    const float* __restrict__ vWi, const float* __restrict__ vbi, const float* __restrict__ vW1,
    float* __restrict__ Mp, float* __restrict__ Mv) {
    int blk = blockIdx.x, d = threadIdx.x;
    const float* Wi; const float* bi; const float* W1; float* M; int F, f;
    if (blk < 9) { Wi = pWi; bi = pbi; W1 = pW1; M = Mp; F = FP; f = blk; }
    else         { Wi = vWi; bi = vbi; W1 = vW1; M = Mv; F = FV; f = blk - 9; }
    float acc = 0.0f;
    if (f < 8) {
        if (f < F)
            for (int j = 0; j < DD; j++)
                acc = fmaf(__ldg(&Wi[f * DD + j]), __ldg(&W1[j * DD + d]), acc);
    } else {
        for (int j = 0; j < DD; j++)
            acc = fmaf(__ldg(&bi[j]), __ldg(&W1[j * DD + d]), acc);
    }
    M[f * DD + d] = acc;
}

// transpose + bf16 split both W2s; grid 512
__global__ __launch_bounds__(256) void prep_wt_both(
    const float* __restrict__ pW2, const float* __restrict__ vW2,
    __nv_bfloat16* __restrict__ phi, __nv_bfloat16* __restrict__ plo,
    __nv_bfloat16* __restrict__ vhi, __nv_bfloat16* __restrict__ vlo) {
    int blk = blockIdx.x, k = threadIdx.x;
    const float* W; __nv_bfloat16 *hi, *lo; int n;
    if (blk < DD) { W = pW2; hi = phi; lo = plo; n = blk; }
    else          { W = vW2; hi = vhi; lo = vlo; n = blk - DD; }
    float w = W[k * DD + n];
    __nv_bfloat16 h = __float2bfloat16_rn(w);
    hi[n * DD + k] = h;
    lo[n * DD + k] = __float2bfloat16_rn(w - __bfloat162float(h));
}

// v init emb (needed in addvec)
__global__ __launch_bounds__(256) void init_emb_kernel(
    const float* __restrict__ x, const float* __restrict__ W, const float* __restrict__ b,
    float* __restrict__ out, int F) {
    int node = blockIdx.x, d = threadIdx.x;
    const float* xr = x + node * F;
    float acc = __ldg(&b[d]);
    #pragma unroll 8
    for (int k = 0; k < 8; k++)
        if (k < F) acc = fmaf(__ldg(&xr[k]), __ldg(&W[k * DD + d]), acc);
    out[node * DD + d] = acc;
}

// ---------------- layer 1: feature-space agg (both nets, one launch) -------------
__global__ __launch_bounds__(256) void agg8_both(
    const float* __restrict__ px, const float* __restrict__ vx,
    const int* __restrict__ p_csr, const int* __restrict__ v_csr,
    const int* __restrict__ p_indeg, const int* __restrict__ v_indeg,
    const float* __restrict__ p_dinv, const float* __restrict__ v_dinv,
    float* __restrict__ p_agg8, float* __restrict__ v_agg8,
    float* __restrict__ p_s, float* __restrict__ v_s) {
    int i = blockIdx.x * blockDim.x + threadIdx.x;
    const float* x; const int* csr; const int* indeg; const float* dinv;
    float* agg8; float* sv; int node, F;
    if (i < NPG) { x = px; csr = p_csr; indeg = p_indeg; dinv = p_dinv;
                   agg8 = p_agg8; sv = p_s; node = i; F = FP; }
    else if (i < NPG + NVG) { x = vx; csr = v_csr; indeg = v_indeg; dinv = v_dinv;
                   agg8 = v_agg8; sv = v_s; node = i - NPG; F = FV; }
    else return;
    int deg = indeg[node];
    int cnt = deg < CAP ? deg : CAP;
    float self = 1.0f / ((float)deg + 1.0f);
    float ddst = dinv[node];
    float a[8];
    #pragma unroll
    for (int f = 0; f < 8; f++) a[f] = 0.0f;
    if (F == 8) {
        float4 x0 = *(const float4*)(x + node * 8);
        float4 x1 = *(const float4*)(x + node * 8 + 4);
        a[0] = x0.x * self; a[1] = x0.y * self; a[2] = x0.z * self; a[3] = x0.w * self;
        a[4] = x1.x * self; a[5] = x1.y * self; a[6] = x1.z * self; a[7] = x1.w * self;
    } else {
        for (int f = 0; f < F; f++) a[f] = x[node * F + f] * self;
    }
    float ssum = self;
    const int* cp = csr + node * CAP;
    for (int e = 0; e < cnt; e++) {
        int src = cp[e];
        float c = ddst * dinv[src];
        ssum += c;
        if (F == 8) {
            float4 m0 = *(const float4*)(x + src * 8);
            float4 m1 = *(const float4*)(x + src * 8 + 4);
            a[0] = fmaf(c, m0.x, a[0]); a[1] = fmaf(c, m0.y, a[1]);
            a[2] = fmaf(c, m0.z, a[2]); a[3] = fmaf(c, m0.w, a[3]);
            a[4] = fmaf(c, m1.x, a[4]); a[5] = fmaf(c, m1.y, a[5]);
            a[6] = fmaf(c, m1.z, a[6]); a[7] = fmaf(c, m1.w, a[7]);
        } else {
            for (int f = 0; f < F; f++) a[f] = fmaf(c, x[src * F + f], a[f]);
        }
    }
    *(float4*)(agg8 + node * 8)     = make_float4(a[0], a[1], a[2], a[3]);
    *(float4*)(agg8 + node * 8 + 4) = make_float4(a[4], a[5], a[6], a[7]);
    sv[node] = ssum;
}

// h1 = relu(agg8 @ M[0:8] + s * M[8] + b1) -> fp16 ; blocks cover p then v
__global__ __launch_bounds__(256) void layer1_both(
    const float* __restrict__ p_agg8, const float* __restrict__ p_sv,
    const float* __restrict__ v_agg8, const float* __restrict__ v_sv,
    const float* __restrict__ Mp, const float* __restrict__ Mv,
    const float* __restrict__ pb1, const float* __restrict__ vb1,
    __half* __restrict__ p_h1, __half* __restrict__ v_h1) {
    int blk = blockIdx.x, d = threadIdx.x;
    const float* agg8; const float* sv; const float* M; const float* b1; __half* h1; int node;
    if (blk < NPG) { agg8 = p_agg8; sv = p_sv; M = Mp; b1 = pb1; h1 = p_h1; node = blk; }
    else           { agg8 = v_agg8; sv = v_sv; M = Mv; b1 = vb1; h1 = v_h1; node = blk - NPG; }
    float a0 = __ldg(&agg8[node * 8 + 0]), a1 = __ldg(&agg8[node * 8 + 1]);
    float a2 = __ldg(&agg8[node * 8 + 2]), a3 = __ldg(&agg8[node * 8 + 3]);
    float a4 = __ldg(&agg8[node * 8 + 4]), a5 = __ldg(&agg8[node * 8 + 5]);
    float a6 = __ldg(&agg8[node * 8 + 6]), a7 = __ldg(&agg8[node * 8 + 7]);
    float ss = __ldg(&sv[node]);
    float acc = __ldg(&b1[d]) + ss * __ldg(&M[8 * DD + d]);
    acc = fmaf(a0, __ldg(&M[0 * DD + d]), acc);
    acc = fmaf(a1, __ldg(&M[1 * DD + d]), acc);
    acc = fmaf(a2, __ldg(&M[2 * DD + d]), acc);
    acc = fmaf(a3, __ldg(&M[3 * DD + d]), acc);
    acc = fmaf(a4, __ldg(&M[4 * DD + d]), acc);
    acc = fmaf(a5, __ldg(&M[5 * DD + d]), acc);
    acc = fmaf(a6, __ldg(&M[6 * DD + d]), acc);
    acc = fmaf(a7, __ldg(&M[7 * DD + d]), acc);
    h1[node * DD + d] = __float2half_rn(fmaxf(acc, 0.0f));
}

// ---------------- 256-dim aggregation (fp16 gather) -> bf16 split ----------
// Merged p+v: blocks [0, PBLK) -> p net; [PBLK, PBLK+VBLK) -> v net.
#define PBLK ((NPG + 7) / 8)
#define VBLK ((NVG + 7) / 8)
__global__ __launch_bounds__(256) void gcn_agg_both(
    const __half* __restrict__ p_h, const __half* __restrict__ v_h,
    const int* __restrict__ p_csr, const int* __restrict__ v_csr,
    const int* __restrict__ p_indeg, const int* __restrict__ v_indeg,
    const float* __restrict__ p_dinv, const float* __restrict__ v_dinv,
    __nv_bfloat16* __restrict__ p_ohi, __nv_bfloat16* __restrict__ p_olo,
    __nv_bfloat16* __restrict__ v_ohi, __nv_bfloat16* __restrict__ v_olo) {
    int blk = blockIdx.x;
    const __half* h; const int* csr; const int* indeg; const float* dinv;
    __nv_bfloat16 *ohi, *olo; int node0, n_nodes;
    if (blk < PBLK) { h = p_h; csr = p_csr; indeg = p_indeg; dinv = p_dinv;
                      ohi = p_ohi; olo = p_olo; node0 = blk * 8; n_nodes = NPG; }
    else            { h = v_h; csr = v_csr; indeg = v_indeg; dinv = v_dinv;
                      ohi = v_ohi; olo = v_olo; node0 = (blk - PBLK) * 8; n_nodes = NVG; }
    int warp = threadIdx.x >> 5;
    int lane = threadIdx.x & 31;
    int node = node0 + warp;
    if (node >= n_nodes) return;
    int d0 = lane * 8;

    int deg = indeg[node];
    int cnt = deg < CAP ? deg : CAP;
    float self = 1.0f / ((float)deg + 1.0f);
    float ddst = dinv[node];

    // self row: 8 halfs = 16B
    uint4 hv = *(const uint4*)(h + node * DD + d0);
    const __half2* hp = (const __half2*)&hv;
    float2 f0 = __half22float2(hp[0]);
    float2 f1 = __half22float2(hp[1]);
    float2 f2 = __half22float2(hp[2]);
    float2 f3 = __half22float2(hp[3]);
    float acc[8] = {f0.x * self, f0.y * self, f1.x * self, f1.y * self,
                    f2.x * self, f2.y * self, f3.x * self, f3.y * self};

    const int* cp = csr + node * CAP;
    for (int e = 0; e < cnt; e++) {
        int src = cp[e];
        float c = ddst * dinv[src];
        uint4 mv = *(const uint4*)(h + src * DD + d0);
        const __half2* mp = (const __half2*)&mv;
        float2 m0 = __half22float2(mp[0]);
        float2 m1 = __half22float2(mp[1]);
        float2 m2 = __half22float2(mp[2]);
        float2 m3 = __half22float2(mp[3]);
        acc[0] = fmaf(c, m0.x, acc[0]); acc[1] = fmaf(c, m0.y, acc[1]);
        acc[2] = fmaf(c, m1.x, acc[2]); acc[3] = fmaf(c, m1.y, acc[3]);
        acc[4] = fmaf(c, m2.x, acc[4]); acc[5] = fmaf(c, m2.y, acc[5]);
        acc[6] = fmaf(c, m3.x, acc[6]); acc[7] = fmaf(c, m3.y, acc[7]);
    }
    int base = node * DD + d0;
    uint32_t hw[4], lw[4];
    #pragma unroll
    for (int q = 0; q < 4; q++) {
        __nv_bfloat16 h0 = __float2bfloat16_rn(acc[q * 2]);
        __nv_bfloat16 h1v = __float2bfloat16_rn(acc[q * 2 + 1]);
        __nv_bfloat16 l0 = __float2bfloat16_rn(acc[q * 2] - __bfloat162float(h0));
        __nv_bfloat16 l1 = __float2bfloat16_rn(acc[q * 2 + 1] - __bfloat162float(h1v));
        __nv_bfloat162 hpx = __nv_bfloat162(h0, h1v);
        __nv_bfloat162 lpx = __nv_bfloat162(l0, l1);
        hw[q] = *(uint32_t*)&hpx;
        lw[q] = *(uint32_t*)&lpx;
    }
    *(uint4*)(ohi + base) = make_uint4(hw[0], hw[1], hw[2], hw[3]);
    *(uint4*)(olo + base) = make_uint4(lw[0], lw[1], lw[2], lw[3]);
}

// ---------------- smem-staged bf16-split GEMM (merged p+v) ----------------
#define KC 32
#define APITCH 80
#define PIECE (128*APITCH)
#define STAGE_BYTES (4*PIECE)
#define GEMM_SMEM (2*STAGE_BYTES)
#define PGY (NPG / 128)   // 500
#define VGY (NVG / 128)   // 20

__global__ void __launch_bounds__(256, 2) gemm_smem_both(
    const __nv_bfloat16* __restrict__ pA_hi, const __nv_bfloat16* __restrict__ pA_lo,
    const __nv_bfloat16* __restrict__ pB_hi, const __nv_bfloat16* __restrict__ pB_lo,
    const float* __restrict__ p_bias, float* __restrict__ pC,
    const __nv_bfloat16* __restrict__ vA_hi, const __nv_bfloat16* __restrict__ vA_lo,
    const __nv_bfloat16* __restrict__ vB_hi, const __nv_bfloat16* __restrict__ vB_lo,
    const float* __restrict__ v_bias, float* __restrict__ vC) {
    const __nv_bfloat16 *A_hi, *A_lo, *Bt_hi, *Bt_lo;
    const float* bias; float* C; int row0;
    if (blockIdx.y < PGY) {
        A_hi = pA_hi; A_lo = pA_lo; Bt_hi = pB_hi; Bt_lo = pB_lo;
        bias = p_bias; C = pC; row0 = blockIdx.y * 128;
    } else {
        A_hi = vA_hi; A_lo = vA_lo; Bt_hi = vB_hi; Bt_lo = vB_lo;
        bias = v_bias; C = vC; row0 = (blockIdx.y - PGY) * 128;
    }
    extern __shared__ char sm[];
    uint32_t sb = smem_u32(sm);
    int tid = threadIdx.x;
    int wid = tid >> 5, lane = tid & 31;
    int g = lane >> 2, t = lane & 3;
    int warp_m = wid & 3, warp_n = wid >> 2;
    int col0 = blockIdx.x * 128;

    float acc[2][8][4];
    #pragma unroll
    for (int s = 0; s < 2; s++)
        #pragma unroll
        for (int n = 0; n < 8; n++)
            #pragma unroll
            for (int q = 0; q < 4; q++) acc[s][n][q] = 0.0f;

    int r0i = (tid + 0) >> 2,  c0i = (tid + 0) & 3;
    int r1i = (tid + 256) >> 2, c1i = (tid + 256) & 3;

    auto stage_load = [&](int st) {
        uint32_t base = sb + (st & 1) * STAGE_BYTES;
        int kc0 = st * KC;
        {
            uint32_t d0 = base + r0i * APITCH + c0i * 16;
            size_t ga = (size_t)(row0 + r0i) * DD + kc0 + c0i * 8;
            size_t gb = (size_t)(col0 + r0i) * DD + kc0 + c0i * 8;
            cpa16(d0,           A_hi + ga);
            cpa16(d0 + PIECE,   A_lo + ga);
            cpa16(d0 + 2*PIECE, Bt_hi + gb);
            cpa16(d0 + 3*PIECE, Bt_lo + gb);
        }
        {
            uint32_t d0 = base + r1i * APITCH + c1i * 16;
            size_t ga = (size_t)(row0 + r1i) * DD + kc0 + c1i * 8;
            size_t gb = (size_t)(col0 + r1i) * DD + kc0 + c1i * 8;
            cpa16(d0,           A_hi + ga);
            cpa16(d0 + PIECE,   A_lo + ga);
            cpa16(d0 + 2*PIECE, Bt_hi + gb);
            cpa16(d0 + 3*PIECE, Bt_lo + gb);
        }
        CPA_COMMIT();
    };

    stage_load(0);
    CPA_WAIT0();
    __syncthreads();

    for (int st = 0; st < DD / KC; st++) {
        if (st + 1 < DD / KC) stage_load(st + 1);
        const char* cur = sm + (st & 1) * STAGE_BYTES;

        #pragma unroll
        for (int kk = 0; kk < 2; kk++) {
            int kb = (kk * 16 + t * 2) * 2;
            uint32_t ah[2][4], al[2][4];
            #pragma unroll
            for (int s = 0; s < 2; s++) {
                const char* pa = cur + (warp_m * 32 + s * 16 + g) * APITCH + kb;
                ah[s][0] = *(const uint32_t*)pa;
                ah[s][1] = *(const uint32_t*)(pa + 8 * APITCH);
                ah[s][2] = *(const uint32_t*)(pa + 16);
                ah[s][3] = *(const uint32_t*)(pa + 8 * APITCH + 16);
                const char* pl = pa + PIECE;
                al[s][0] = *(const uint32_t*)pl;
                al[s][1] = *(const uint32_t*)(pl + 8 * APITCH);
                al[s][2] = *(const uint32_t*)(pl + 16);
                al[s][3] = *(const uint32_t*)(pl + 8 * APITCH + 16);
            }
            #pragma unroll
            for (int nt = 0; nt < 8; nt++) {
                const char* pb = cur + 2 * PIECE + (warp_n * 64 + nt * 8 + g) * APITCH + kb;
                uint32_t bh0 = *(const uint32_t*)pb;
                uint32_t bh1 = *(const uint32_t*)(pb + 16);
                const char* pbl = pb + PIECE;
                uint32_t bl0 = *(const uint32_t*)pbl;
                uint32_t bl1 = *(const uint32_t*)(pbl + 16);
                #pragma unroll
                for (int s = 0; s < 2; s++) {
                    MMA_OP(acc[s][nt], ah[s], bh0, bh1);
                    MMA_OP(acc[s][nt], ah[s], bl0, bl1);
                    MMA_OP(acc[s][nt], al[s], bh0, bh1);
                }
            }
        }
        CPA_WAIT0();
        __syncthreads();
    }

    #pragma unroll
    for (int s = 0; s < 2; s++) {
        int r = row0 + warp_m * 32 + s * 16 + g;
        #pragma unroll
        for (int nt = 0; nt < 8; nt++) {
            int c = col0 + warp_n * 64 + nt * 8 + t * 2;
            float bx = __ldg(&bias[c]), by = __ldg(&bias[c + 1]);
            *(float2*)(C + r * DD + c)       = make_float2(acc[s][nt][0] + bx, acc[s][nt][1] + by);
            *(float2*)(C + (r + 8) * DD + c) = make_float2(acc[s][nt][2] + bx, acc[s][nt][3] + by);
        }
    }
}

// ---------------- pooling / fuse ----------------
__global__ __launch_bounds__(256) void pool_v_kernel(
    const float* __restrict__ node_emb, float* __restrict__ g) {
    int b = blockIdx.x, d = threadIdx.x;
    const float* p = node_emb + (size_t)b * NPV * DD + d;
    float s = 0.f;
    #pragma unroll
    for (int i = 0; i < NPV; i++) s += p[i * DD];
    g[b * DD + d] = s * (1.0f / NPV);
}
__global__ __launch_bounds__(256) void pool_p_partial(
    const float* __restrict__ node_emb, float* __restrict__ part) {
    int b = blockIdx.x, ppart = blockIdx.y, d = threadIdx.x;
    const int chunk = NPP / PPOOL;
    const float* p = node_emb + ((size_t)b * NPP + ppart * chunk) * DD + d;
    float s0 = 0.f, s1 = 0.f;
    #pragma unroll
    for (int i = 0; i < chunk; i += 2) {
        s0 += p[i * DD];
        s1 += p[(i + 1) * DD];
    }
    part[(b * PPOOL + ppart) * DD + d] = s0 + s1;
}
__global__ void addvec_kernel(const float* __restrict__ pg_part, const float* __restrict__ vg,
                              const float* __restrict__ v_node, const float* __restrict__ v_init,
                              const int* __restrict__ curr, float* __restrict__ av) {
    int b = blockIdx.x, d = threadIdx.x;
    float pgs = 0.f;
    #pragma unroll
    for (int j = 0; j < PPOOL; j++) pgs += pg_part[(b * PPOOL + j) * DD + d];
    float pgd = pgs * (1.0f / NPP);
    int cid = curr[b];
    int vi = (b * NPV + cid) * DD + d;
    av[b * DD + d] = pgd + 2.0f * vg[b * DD + d] + v_node[vi] + v_init[vi];
}

// out = p_node + (p_x@Wi + bi) + addvec[b]
__global__ void final_kernel(const float* __restrict__ pn, const float* __restrict__ px,
                             const float* __restrict__ Wi, const float* __restrict__ bi,
                             const float* __restrict__ av, float* __restrict__ out) {
    int idx = blockIdx.x * blockDim.x + threadIdx.x;
    const int total4 = NPG * (DD / 4);
    if (idx >= total4) return;
    int node = idx >> 6;
    int d4 = idx & 63;
    int d = d4 * 4;
    int b = node / NPP;
    float4 a = ((const float4*)pn)[idx];
    float4 v = ((const float4*)av)[b * (DD / 4) + d4];
    float4 bb = *(const float4*)(bi + d);
    float4 r = make_float4(a.x + v.x + bb.x, a.y + v.y + bb.y,
                           a.z + v.z + bb.z, a.w + v.w + bb.w);
    const float* xr = px + node * FP;
    #pragma unroll
    for (int k = 0; k < FP; k++) {
        float xv = __ldg(&xr[k]);
        float4 w = *(const float4*)(Wi + k * DD + d);
        r.x = fmaf(xv, w.x, r.x); r.y = fmaf(xv, w.y, r.y);
        r.z = fmaf(xv, w.z, r.z); r.w = fmaf(xv, w.w, r.w);
    }
    ((float4*)out)[idx] = r;
}

// ---------------- host launch ----------------
static inline void* sym(const void* s) {
    void* p = nullptr;
    cudaGetSymbolAddress(&p, s);
    return p;
}

extern "C" void kernel_launch(void* const* d_in, const int* in_sizes, int n_in,
                              void* d_out, int out_size) {
    const float* v_x     = (const float*)d_in[0];
    const float* p_x     = (const float*)d_in[1];
    const int*   v_src   = (const int*)d_in[2];
    const int*   v_dst   = (const int*)d_in[3];
    const int*   p_src   = (const int*)d_in[4];
    const int*   p_dst   = (const int*)d_in[5];
    const int*   curr    = (const int*)d_in[8];
    const float* v_initW = (const float*)d_in[9];
    const float* v_initb = (const float*)d_in[10];
    const float* v_W1    = (const float*)d_in[11];
    const float* v_b1    = (const float*)d_in[12];
    const float* v_W2    = (const float*)d_in[13];
    const float* v_b2    = (const float*)d_in[14];
    const float* p_initW = (const float*)d_in[15];
    const float* p_initb = (const float*)d_in[16];
    const float* p_W1    = (const float*)d_in[17];
    const float* p_b1    = (const float*)d_in[18];
    const float* p_W2    = (const float*)d_in[19];
    const float* p_b2    = (const float*)d_in[20];
    float* out = (float*)d_out;

    __half* p_tmp = (__half*)sym(g_p_tmp);
    float* p_node = (float*)sym(g_p_node);
    __nv_bfloat16* p_hi = (__nv_bfloat16*)sym(g_p_hi);
    __nv_bfloat16* p_lo = (__nv_bfloat16*)sym(g_p_lo);
    float* v_init = (float*)sym(g_v_init);
    __half* v_tmp = (__half*)sym(g_v_tmp);
    float* v_node = (float*)sym(g_v_node);
    __nv_bfloat16* v_hi = (__nv_bfloat16*)sym(g_v_hi);
    __nv_bfloat16* v_lo = (__nv_bfloat16*)sym(g_v_lo);
    __nv_bfloat16* wtv2h = (__nv_bfloat16*)sym(g_wtv2_hi);
    __nv_bfloat16* wtv2l = (__nv_bfloat16*)sym(g_wtv2_lo);
    __nv_bfloat16* wtp2h = (__nv_bfloat16*)sym(g_wtp2_hi);
    __nv_bfloat16* wtp2l = (__nv_bfloat16*)sym(g_wtp2_lo);
    float* Mp = (float*)sym(g_Mp);
    float* Mv = (float*)sym(g_Mv);
    float* p_agg8 = (float*)sym(g_p_agg8);
    float* p_s    = (float*)sym(g_p_s);
    float* v_agg8 = (float*)sym(g_v_agg8);
    float* v_s    = (float*)sym(g_v_s);
    int* p_indeg  = (int*)sym(g_p_indeg);
    int* v_indeg  = (int*)sym(g_v_indeg);
    float* p_dinv = (float*)sym(g_p_dinv);
    float* v_dinv = (float*)sym(g_v_dinv);
    int* p_csr    = (int*)sym(g_p_csr);
    int* v_csr    = (int*)sym(g_v_csr);
    float* pgp    = (float*)sym(g_pg_part);
    float* vg     = (float*)sym(g_vg);
    float* av     = (float*)sym(g_addvec);

    cudaFuncSetAttribute(gemm_smem_both, cudaFuncAttributeMaxDynamicSharedMemorySize, GEMM_SMEM);

    // graph structure
    zero_all<<<(NPG + NVG + 255) / 256, 256>>>(p_indeg, v_indeg);
    build_csr<<<(EV + 255) / 256, 256>>>(v_src, v_dst, EV, v_indeg, v_csr);
    build_csr<<<(EP + 255) / 256, 256>>>(p_src, p_dst, EP, p_indeg, p_csr);
    dinv_both<<<(NPG + NVG + 255) / 256, 256>>>(p_indeg, v_indeg, p_dinv, v_dinv);
    // weight prep
    prep_M_both<<<18, 256>>>(p_initW, p_initb, p_W1, v_initW, v_initb, v_W1, Mp, Mv);
    prep_wt_both<<<512, 256>>>(p_W2, v_W2, wtp2h, wtp2l, wtv2h, wtv2l);
    // v init emb
    init_emb_kernel<<<NVG, 256>>>(v_x, v_initW, v_initb, v_init, FV);
    // layer 1 both nets (h1 -> fp16)
    agg8_both<<<(NPG + NVG + 255) / 256, 256>>>(p_x, v_x, p_csr, v_csr, p_indeg, v_indeg,
                                                p_dinv, v_dinv, p_agg8, v_agg8, p_s, v_s);
    layer1_both<<<NPG + NVG, 256>>>(p_agg8, p_s, v_agg8, v_s, Mp, Mv, p_b1, v_b1, p_tmp, v_tmp);
    // layer 2: merged agg (fp16 gather), merged GEMM
    gcn_agg_both<<<PBLK + VBLK, 256>>>(p_tmp, v_tmp, p_csr, v_csr, p_indeg, v_indeg,
                                       p_dinv, v_dinv, p_hi, p_lo, v_hi, v_lo);
    {
        dim3 gg(2, PGY + VGY);
        gemm_smem_both<<<gg, 256, GEMM_SMEM>>>(p_hi, p_lo, wtp2h, wtp2l, p_b2, p_node,
                                               v_hi, v_lo, wtv2h, wtv2l, v_b2, v_node);
    }
    // pooling + fuse
    pool_v_kernel<<<NB, 256>>>(v_node, vg);
    {
        dim3 g(NB, PPOOL);
        pool_p_partial<<<g, 256>>>(p_node, pgp);
    }
    addvec_kernel<<<NB, 256>>>(pgp, vg, v_node, v_init, curr, av);
    const int total4 = NPG * (DD / 4);
    final_kernel<<<(total4 + 255) / 256, 256>>>(p_node, p_x, p_initW, p_initb, av, out);
}

// round 13
// speedup vs baseline: 1.3332x; 1.0967x over previous
#include <cuda_runtime.h>
#include <cuda_bf16.h>
#include <cuda_fp16.h>
#include <cstdint>

// ---------------- problem constants ----------------
#define NB   128
#define NPV  20
#define NPP  500
#define NVG  (NB*NPV)     // 2560
#define NPG  (NB*NPP)     // 64000
#define DD   256
#define FV   6
#define FP   8
#define DEG  8
#define EV   (NVG*DEG)
#define EP   (NPG*DEG)
#define CAP  64
#define PPOOL 10

// ---------------- static device scratch ----------------
__device__ __half g_p_tmp [NPG*DD];           // h1 (p layer-1 output, fp16)
__device__ float  g_p_node[NPG*DD];           // p layer-2 output
__device__ __half g_p_agg [NPG*DD];           // agg(h1), fp16

__device__ float  g_v_init[NVG*DD];
__device__ __half g_v_tmp [NVG*DD];           // v h1 (fp16)
__device__ float  g_v_node[NVG*DD];
__device__ __half g_v_agg [NVG*DD];

__device__ __half g_wtv2_hi[DD*DD]; __device__ __half g_wtv2_lo[DD*DD];
__device__ __half g_wtp2_hi[DD*DD]; __device__ __half g_wtp2_lo[DD*DD];

__device__ float g_Mp[9*DD];   // rows 0-7: Wi@W1 (zero-padded); row 8: bi@W1
__device__ float g_Mv[9*DD];

__device__ float g_p_agg8[NPG*8];
__device__ float g_p_s[NPG];
__device__ float g_v_agg8[NVG*8];
__device__ float g_v_s[NVG];

__device__ int   g_p_indeg[NPG];
__device__ int   g_v_indeg[NVG];
__device__ float g_p_dinv[NPG];
__device__ float g_v_dinv[NVG];
__device__ int   g_p_csr[NPG*CAP];
__device__ int   g_v_csr[NVG*CAP];

__device__ float g_pg_part[NB*PPOOL*DD];
__device__ float g_vg[NB*DD];
__device__ float g_addvec[NB*DD];

// ---------------- helpers ----------------
__device__ __forceinline__ uint32_t smem_u32(const void* p) {
    uint32_t a;
    asm("{ .reg .u64 t; cvta.to.shared.u64 t, %1; cvt.u32.u64 %0, t; }" : "=r"(a) : "l"(p));
    return a;
}
__device__ __forceinline__ void cpa16(uint32_t dst, const void* src) {
    asm volatile("cp.async.cg.shared.global [%0], [%1], 16;" :: "r"(dst), "l"(src) : "memory");
}
#define CPA_COMMIT() asm volatile("cp.async.commit_group;" ::: "memory")
#define CPA_WAIT0()  asm volatile("cp.async.wait_group 0;" ::: "memory")

// fp16 x fp16 -> fp32 mma
#define MMA_F16(ACC, AH, B0, B1)                                                  \
    asm volatile(                                                                  \
        "mma.sync.aligned.m16n8k16.row.col.f32.f16.f16.f32 "                      \
        "{%0,%1,%2,%3}, {%4,%5,%6,%7}, {%8,%9}, {%0,%1,%2,%3};"                   \
        : "+f"((ACC)[0]), "+f"((ACC)[1]), "+f"((ACC)[2]), "+f"((ACC)[3])          \
        : "r"((AH)[0]), "r"((AH)[1]), "r"((AH)[2]), "r"((AH)[3]),                 \
          "r"(B0), "r"(B1))

// ---------------- setup kernels ----------------
__global__ void zero_all(int* p_indeg, int* v_indeg) {
    int i = blockIdx.x * blockDim.x + threadIdx.x;
    if (i < NPG) p_indeg[i] = 0;
    else if (i < NPG + NVG) v_indeg[i - NPG] = 0;
}
__global__ void build_csr(const int* __restrict__ src, const int* __restrict__ dst,
                          int E, int* __restrict__ indeg, int* __restrict__ csr) {
    int e = blockIdx.x * blockDim.x + threadIdx.x;
    if (e >= E) return;
    int d = dst[e];
    int slot = atomicAdd(&indeg[d], 1);
    if (slot < CAP) csr[d * CAP + slot] = src[e];
}
__global__ void dinv_both(const int* __restrict__ p_indeg, const int* __restrict__ v_indeg,
                          float* __restrict__ p_dinv, float* __restrict__ v_dinv) {
    int i = blockIdx.x * blockDim.x + threadIdx.x;
    if (i < NPG) p_dinv[i] = rsqrtf((float)p_indeg[i] + 1.0f);
    else if (i < NPG + NVG) v_dinv[i - NPG] = rsqrtf((float)v_indeg[i - NPG] + 1.0f);
}

// M rows 0..7 = Wi@W1 (zero-padded); row 8 = bi@W1 ; grid 18 covers p (0-8) and v (9-17)
__global__ __launch_bounds__(256) void prep_M_both(
    const float* __restrict__ pWi, const float* __restrict__ pbi, const float* __restrict__ pW1,
    const float* __restrict__ vWi, const float* __restrict__ vbi, const float* __restrict__ vW1,
    float* __restrict__ Mp, float* __restrict__ Mv) {
    int blk = blockIdx.x, d = threadIdx.x;
    const float* Wi; const float* bi; const float* W1; float* M; int F, f;
    if (blk < 9) { Wi = pWi; bi = pbi; W1 = pW1; M = Mp; F = FP; f = blk; }
    else         { Wi = vWi; bi = vbi; W1 = vW1; M = Mv; F = FV; f = blk - 9; }
    float acc = 0.0f;
    if (f < 8) {
        if (f < F)
            for (int j = 0; j < DD; j++)
                acc = fmaf(__ldg(&Wi[f * DD + j]), __ldg(&W1[j * DD + d]), acc);
    } else {
        for (int j = 0; j < DD; j++)
            acc = fmaf(__ldg(&bi[j]), __ldg(&W1[j * DD + d]), acc);
    }
    M[f * DD + d] = acc;
}

// transpose + fp16 split both W2s; grid 512
__global__ __launch_bounds__(256) void prep_wt_both(
    const float* __restrict__ pW2, const float* __restrict__ vW2,
    __half* __restrict__ phi, __half* __restrict__ plo,
    __half* __restrict__ vhi, __half* __restrict__ vlo) {
    int blk = blockIdx.x, k = threadIdx.x;
    const float* W; __half *hi, *lo; int n;
    if (blk < DD) { W = pW2; hi = phi; lo = plo; n = blk; }
    else          { W = vW2; hi = vhi; lo = vlo; n = blk - DD; }
    float w = W[k * DD + n];
    __half h = __float2half_rn(w);
    hi[n * DD + k] = h;
    lo[n * DD + k] = __float2half_rn(w - __half2float(h));
}

// v init emb (needed in addvec)
__global__ __launch_bounds__(256) void init_emb_kernel(
    const float* __restrict__ x, const float* __restrict__ W, const float* __restrict__ b,
    float* __restrict__ out, int F) {
    int node = blockIdx.x, d = threadIdx.x;
    const float* xr = x + node * F;
    float acc = __ldg(&b[d]);
    #pragma unroll 8
    for (int k = 0; k < 8; k++)
        if (k < F) acc = fmaf(__ldg(&xr[k]), __ldg(&W[k * DD + d]), acc);
    out[node * DD + d] = acc;
}

// ---------------- layer 1: feature-space agg (both nets, one launch) -------------
__global__ __launch_bounds__(256) void agg8_both(
    const float* __restrict__ px, const float* __restrict__ vx,
    const int* __restrict__ p_csr, const int* __restrict__ v_csr,
    const int* __restrict__ p_indeg, const int* __restrict__ v_indeg,
    const float* __restrict__ p_dinv, const float* __restrict__ v_dinv,
    float* __restrict__ p_agg8, float* __restrict__ v_agg8,
    float* __restrict__ p_s, float* __restrict__ v_s) {
    int i = blockIdx.x * blockDim.x + threadIdx.x;
    const float* x; const int* csr; const int* indeg; const float* dinv;
    float* agg8; float* sv; int node, F;
    if (i < NPG) { x = px; csr = p_csr; indeg = p_indeg; dinv = p_dinv;
                   agg8 = p_agg8; sv = p_s; node = i; F = FP; }
    else if (i < NPG + NVG) { x = vx; csr = v_csr; indeg = v_indeg; dinv = v_dinv;
                   agg8 = v_agg8; sv = v_s; node = i - NPG; F = FV; }
    else return;
    int deg = indeg[node];
    int cnt = deg < CAP ? deg : CAP;
    float self = 1.0f / ((float)deg + 1.0f);
    float ddst = dinv[node];
    float a[8];
    #pragma unroll
    for (int f = 0; f < 8; f++) a[f] = 0.0f;
    if (F == 8) {
        float4 x0 = *(const float4*)(x + node * 8);
        float4 x1 = *(const float4*)(x + node * 8 + 4);
        a[0] = x0.x * self; a[1] = x0.y * self; a[2] = x0.z * self; a[3] = x0.w * self;
        a[4] = x1.x * self; a[5] = x1.y * self; a[6] = x1.z * self; a[7] = x1.w * self;
    } else {
        for (int f = 0; f < F; f++) a[f] = x[node * F + f] * self;
    }
    float ssum = self;
    const int* cp = csr + node * CAP;
    for (int e = 0; e < cnt; e++) {
        int src = cp[e];
        float c = ddst * dinv[src];
        ssum += c;
        if (F == 8) {
            float4 m0 = *(const float4*)(x + src * 8);
            float4 m1 = *(const float4*)(x + src * 8 + 4);
            a[0] = fmaf(c, m0.x, a[0]); a[1] = fmaf(c, m0.y, a[1]);
            a[2] = fmaf(c, m0.z, a[2]); a[3] = fmaf(c, m0.w, a[3]);
            a[4] = fmaf(c, m1.x, a[4]); a[5] = fmaf(c, m1.y, a[5]);
            a[6] = fmaf(c, m1.z, a[6]); a[7] = fmaf(c, m1.w, a[7]);
        } else {
            for (int f = 0; f < F; f++) a[f] = fmaf(c, x[src * F + f], a[f]);
        }
    }
    *(float4*)(agg8 + node * 8)     = make_float4(a[0], a[1], a[2], a[3]);
    *(float4*)(agg8 + node * 8 + 4) = make_float4(a[4], a[5], a[6], a[7]);
    sv[node] = ssum;
}

// h1 = relu(agg8 @ M[0:8] + s * M[8] + b1) -> fp16 ; blocks cover p then v
__global__ __launch_bounds__(256) void layer1_both(
    const float* __restrict__ p_agg8, const float* __restrict__ p_sv,
    const float* __restrict__ v_agg8, const float* __restrict__ v_sv,
    const float* __restrict__ Mp, const float* __restrict__ Mv,
    const float* __restrict__ pb1, const float* __restrict__ vb1,
    __half* __restrict__ p_h1, __half* __restrict__ v_h1) {
    int blk = blockIdx.x, d = threadIdx.x;
    const float* agg8; const float* sv; const float* M; const float* b1; __half* h1; int node;
    if (blk < NPG) { agg8 = p_agg8; sv = p_sv; M = Mp; b1 = pb1; h1 = p_h1; node = blk; }
    else           { agg8 = v_agg8; sv = v_sv; M = Mv; b1 = vb1; h1 = v_h1; node = blk - NPG; }
    float a0 = __ldg(&agg8[node * 8 + 0]), a1 = __ldg(&agg8[node * 8 + 1]);
    float a2 = __ldg(&agg8[node * 8 + 2]), a3 = __ldg(&agg8[node * 8 + 3]);
    float a4 = __ldg(&agg8[node * 8 + 4]), a5 = __ldg(&agg8[node * 8 + 5]);
    float a6 = __ldg(&agg8[node * 8 + 6]), a7 = __ldg(&agg8[node * 8 + 7]);
    float ss = __ldg(&sv[node]);
    float acc = __ldg(&b1[d]) + ss * __ldg(&M[8 * DD + d]);
    acc = fmaf(a0, __ldg(&M[0 * DD + d]), acc);
    acc = fmaf(a1, __ldg(&M[1 * DD + d]), acc);
    acc = fmaf(a2, __ldg(&M[2 * DD + d]), acc);
    acc = fmaf(a3, __ldg(&M[3 * DD + d]), acc);
    acc = fmaf(a4, __ldg(&M[4 * DD + d]), acc);
    acc = fmaf(a5, __ldg(&M[5 * DD + d]), acc);
    acc = fmaf(a6, __ldg(&M[6 * DD + d]), acc);
    acc = fmaf(a7, __ldg(&M[7 * DD + d]), acc);
    h1[node * DD + d] = __float2half_rn(fmaxf(acc, 0.0f));
}

// ---------------- 256-dim aggregation (fp16 gather) -> fp16 ----------
#define PBLK ((NPG + 7) / 8)
#define VBLK ((NVG + 7) / 8)
__global__ __launch_bounds__(256) void gcn_agg_both(
    const __half* __restrict__ p_h, const __half* __restrict__ v_h,
    const int* __restrict__ p_csr, const int* __restrict__ v_csr,
    const int* __restrict__ p_indeg, const int* __restrict__ v_indeg,
    const float* __restrict__ p_dinv, const float* __restrict__ v_dinv,
    __half* __restrict__ p_out, __half* __restrict__ v_out) {
    int blk = blockIdx.x;
    const __half* h; const int* csr; const int* indeg; const float* dinv;
    __half* outp; int node0, n_nodes;
    if (blk < PBLK) { h = p_h; csr = p_csr; indeg = p_indeg; dinv = p_dinv;
                      outp = p_out; node0 = blk * 8; n_nodes = NPG; }
    else            { h = v_h; csr = v_csr; indeg = v_indeg; dinv = v_dinv;
                      outp = v_out; node0 = (blk - PBLK) * 8; n_nodes = NVG; }
    int warp = threadIdx.x >> 5;
    int lane = threadIdx.x & 31;
    int node = node0 + warp;
    if (node >= n_nodes) return;
    int d0 = lane * 8;

    int deg = indeg[node];
    int cnt = deg < CAP ? deg : CAP;
    float self = 1.0f / ((float)deg + 1.0f);
    float ddst = dinv[node];

    uint4 hv = *(const uint4*)(h + node * DD + d0);
    const __half2* hp = (const __half2*)&hv;
    float2 f0 = __half22float2(hp[0]);
    float2 f1 = __half22float2(hp[1]);
    float2 f2 = __half22float2(hp[2]);
    float2 f3 = __half22float2(hp[3]);
    float acc[8] = {f0.x * self, f0.y * self, f1.x * self, f1.y * self,
                    f2.x * self, f2.y * self, f3.x * self, f3.y * self};

    const int* cp = csr + node * CAP;
    for (int e = 0; e < cnt; e++) {
        int src = cp[e];
        float c = ddst * dinv[src];
        uint4 mv = *(const uint4*)(h + src * DD + d0);
        const __half2* mp = (const __half2*)&mv;
        float2 m0 = __half22float2(mp[0]);
        float2 m1 = __half22float2(mp[1]);
        float2 m2 = __half22float2(mp[2]);
        float2 m3 = __half22float2(mp[3]);
        acc[0] = fmaf(c, m0.x, acc[0]); acc[1] = fmaf(c, m0.y, acc[1]);
        acc[2] = fmaf(c, m1.x, acc[2]); acc[3] = fmaf(c, m1.y, acc[3]);
        acc[4] = fmaf(c, m2.x, acc[4]); acc[5] = fmaf(c, m2.y, acc[5]);
        acc[6] = fmaf(c, m3.x, acc[6]); acc[7] = fmaf(c, m3.y, acc[7]);
    }
    int base = node * DD + d0;
    __half2 o0 = __floats2half2_rn(acc[0], acc[1]);
    __half2 o1 = __floats2half2_rn(acc[2], acc[3]);
    __half2 o2 = __floats2half2_rn(acc[4], acc[5]);
    __half2 o3 = __floats2half2_rn(acc[6], acc[7]);
    uint4 ov = make_uint4(*(uint32_t*)&o0, *(uint32_t*)&o1, *(uint32_t*)&o2, *(uint32_t*)&o3);
    *(uint4*)(outp + base) = ov;
}

// ---------------- smem-staged fp16 GEMM, 2-term B split (merged p+v) ----------
// C = A_f16 @ (Whi + Wlo) + bias
#define KC 32
#define APITCH 80
#define PIECE (128*APITCH)
#define STAGE_BYTES (3*PIECE)      // A, Bhi, Blo
#define GEMM_SMEM (2*STAGE_BYTES)  // 61440
#define PGY (NPG / 128)   // 500
#define VGY (NVG / 128)   // 20

__global__ void __launch_bounds__(256, 2) gemm_smem_both(
    const __half* __restrict__ pA, const __half* __restrict__ pB_hi,
    const __half* __restrict__ pB_lo, const float* __restrict__ p_bias,
    float* __restrict__ pC,
    const __half* __restrict__ vA, const __half* __restrict__ vB_hi,
    const __half* __restrict__ vB_lo, const float* __restrict__ v_bias,
    float* __restrict__ vC) {
    const __half *A, *Bt_hi, *Bt_lo;
    const float* bias; float* C; int row0;
    if (blockIdx.y < PGY) {
        A = pA; Bt_hi = pB_hi; Bt_lo = pB_lo;
        bias = p_bias; C = pC; row0 = blockIdx.y * 128;
    } else {
        A = vA; Bt_hi = vB_hi; Bt_lo = vB_lo;
        bias = v_bias; C = vC; row0 = (blockIdx.y - PGY) * 128;
    }
    extern __shared__ char sm[];
    uint32_t sb = smem_u32(sm);
    int tid = threadIdx.x;
    int wid = tid >> 5, lane = tid & 31;
    int g = lane >> 2, t = lane & 3;
    int warp_m = wid & 3, warp_n = wid >> 2;
    int col0 = blockIdx.x * 128;

    float acc[2][8][4];
    #pragma unroll
    for (int s = 0; s < 2; s++)
        #pragma unroll
        for (int n = 0; n < 8; n++)
            #pragma unroll
            for (int q = 0; q < 4; q++) acc[s][n][q] = 0.0f;

    int r0i = (tid + 0) >> 2,  c0i = (tid + 0) & 3;
    int r1i = (tid + 256) >> 2, c1i = (tid + 256) & 3;

    auto stage_load = [&](int st) {
        uint32_t base = sb + (st & 1) * STAGE_BYTES;
        int kc0 = st * KC;
        {
            uint32_t d0 = base + r0i * APITCH + c0i * 16;
            size_t ga = (size_t)(row0 + r0i) * DD + kc0 + c0i * 8;
            size_t gb = (size_t)(col0 + r0i) * DD + kc0 + c0i * 8;
            cpa16(d0,           A + ga);
            cpa16(d0 + PIECE,   Bt_hi + gb);
            cpa16(d0 + 2*PIECE, Bt_lo + gb);
        }
        {
            uint32_t d0 = base + r1i * APITCH + c1i * 16;
            size_t ga = (size_t)(row0 + r1i) * DD + kc0 + c1i * 8;
            size_t gb = (size_t)(col0 + r1i) * DD + kc0 + c1i * 8;
            cpa16(d0,           A + ga);
            cpa16(d0 + PIECE,   Bt_hi + gb);
            cpa16(d0 + 2*PIECE, Bt_lo + gb);
        }
        CPA_COMMIT();
    };

    stage_load(0);
    CPA_WAIT0();
    __syncthreads();

    for (int st = 0; st < DD / KC; st++) {
        if (st + 1 < DD / KC) stage_load(st + 1);
        const char* cur = sm + (st & 1) * STAGE_BYTES;

        #pragma unroll
        for (int kk = 0; kk < 2; kk++) {
            int kb = (kk * 16 + t * 2) * 2;
            uint32_t ah[2][4];
            #pragma unroll
            for (int s = 0; s < 2; s++) {
                const char* pa = cur + (warp_m * 32 + s * 16 + g) * APITCH + kb;
                ah[s][0] = *(const uint32_t*)pa;
                ah[s][1] = *(const uint32_t*)(pa + 8 * APITCH);
                ah[s][2] = *(const uint32_t*)(pa + 16);
                ah[s][3] = *(const uint32_t*)(pa + 8 * APITCH + 16);
            }
            #pragma unroll
            for (int nt = 0; nt < 8; nt++) {
                const char* pb = cur + PIECE + (warp_n * 64 + nt * 8 + g) * APITCH + kb;
                uint32_t bh0 = *(const uint32_t*)pb;
                uint32_t bh1 = *(const uint32_t*)(pb + 16);
                const char* pbl = pb + PIECE;
                uint32_t bl0 = *(const uint32_t*)pbl;
                uint32_t bl1 = *(const uint32_t*)(pbl + 16);
                #pragma unroll
                for (int s = 0; s < 2; s++) {
                    MMA_F16(acc[s][nt], ah[s], bh0, bh1);
                    MMA_F16(acc[s][nt], ah[s], bl0, bl1);
                }
            }
        }
        CPA_WAIT0();
        __syncthreads();
    }

    #pragma unroll
    for (int s = 0; s < 2; s++) {
        int r = row0 + warp_m * 32 + s * 16 + g;
        #pragma unroll
        for (int nt = 0; nt < 8; nt++) {
            int c = col0 + warp_n * 64 + nt * 8 + t * 2;
            float bx = __ldg(&bias[c]), by = __ldg(&bias[c + 1]);
            *(float2*)(C + r * DD + c)       = make_float2(acc[s][nt][0] + bx, acc[s][nt][1] + by);
            *(float2*)(C + (r + 8) * DD + c) = make_float2(acc[s][nt][2] + bx, acc[s][nt][3] + by);
        }
    }
}

// ---------------- pooling / fuse ----------------
__global__ __launch_bounds__(256) void pool_v_kernel(
    const float* __restrict__ node_emb, float* __restrict__ g) {
    int b = blockIdx.x, d = threadIdx.x;
    const float* p = node_emb + (size_t)b * NPV * DD + d;
    float s = 0.f;
    #pragma unroll
    for (int i = 0; i < NPV; i++) s += p[i * DD];
    g[b * DD + d] = s * (1.0f / NPV);
}
__global__ __launch_bounds__(256) void pool_p_partial(
    const float* __restrict__ node_emb, float* __restrict__ part) {
    int b = blockIdx.x, ppart = blockIdx.y, d = threadIdx.x;
    const int chunk = NPP / PPOOL;
    const float* p = node_emb + ((size_t)b * NPP + ppart * chunk) * DD + d;
    float s0 = 0.f, s1 = 0.f;
    #pragma unroll
    for (int i = 0; i < chunk; i += 2) {
        s0 += p[i * DD];
        s1 += p[(i + 1) * DD];
    }
    part[(b * PPOOL + ppart) * DD + d] = s0 + s1;
}
__global__ void addvec_kernel(const float* __restrict__ pg_part, const float* __restrict__ vg,
                              const float* __restrict__ v_node, const float* __restrict__ v_init,
                              const int* __restrict__ curr, float* __restrict__ av) {
    int b = blockIdx.x, d = threadIdx.x;
    float pgs = 0.f;
    #pragma unroll
    for (int j = 0; j < PPOOL; j++) pgs += pg_part[(b * PPOOL + j) * DD + d];
    float pgd = pgs * (1.0f / NPP);
    int cid = curr[b];
    int vi = (b * NPV + cid) * DD + d;
    av[b * DD + d] = pgd + 2.0f * vg[b * DD + d] + v_node[vi] + v_init[vi];
}

// out = p_node + (p_x@Wi + bi) + addvec[b]
__global__ void final_kernel(const float* __restrict__ pn, const float* __restrict__ px,
                             const float* __restrict__ Wi, const float* __restrict__ bi,
                             const float* __restrict__ av, float* __restrict__ out) {
    int idx = blockIdx.x * blockDim.x + threadIdx.x;
    const int total4 = NPG * (DD / 4);
    if (idx >= total4) return;
    int node = idx >> 6;
    int d4 = idx & 63;
    int d = d4 * 4;
    int b = node / NPP;
    float4 a = ((const float4*)pn)[idx];
    float4 v = ((const float4*)av)[b * (DD / 4) + d4];
    float4 bb = *(const float4*)(bi + d);
    float4 r = make_float4(a.x + v.x + bb.x, a.y + v.y + bb.y,
                           a.z + v.z + bb.z, a.w + v.w + bb.w);
    const float* xr = px + node * FP;
    #pragma unroll
    for (int k = 0; k < FP; k++) {
        float xv = __ldg(&xr[k]);
        float4 w = *(const float4*)(Wi + k * DD + d);
        r.x = fmaf(xv, w.x, r.x); r.y = fmaf(xv, w.y, r.y);
        r.z = fmaf(xv, w.z, r.z); r.w = fmaf(xv, w.w, r.w);
    }
    ((float4*)out)[idx] = r;
}

// ---------------- host launch ----------------
static inline void* sym(const void* s) {
    void* p = nullptr;
    cudaGetSymbolAddress(&p, s);
    return p;
}

extern "C" void kernel_launch(void* const* d_in, const int* in_sizes, int n_in,
                              void* d_out, int out_size) {
    const float* v_x     = (const float*)d_in[0];
    const float* p_x     = (const float*)d_in[1];
    const int*   v_src   = (const int*)d_in[2];
    const int*   v_dst   = (const int*)d_in[3];
    const int*   p_src   = (const int*)d_in[4];
    const int*   p_dst   = (const int*)d_in[5];
    const int*   curr    = (const int*)d_in[8];
    const float* v_initW = (const float*)d_in[9];
    const float* v_initb = (const float*)d_in[10];
    const float* v_W1    = (const float*)d_in[11];
    const float* v_b1    = (const float*)d_in[12];
    const float* v_W2    = (const float*)d_in[13];
    const float* v_b2    = (const float*)d_in[14];
    const float* p_initW = (const float*)d_in[15];
    const float* p_initb = (const float*)d_in[16];
    const float* p_W1    = (const float*)d_in[17];
    const float* p_b1    = (const float*)d_in[18];
    const float* p_W2    = (const float*)d_in[19];
    const float* p_b2    = (const float*)d_in[20];
    float* out = (float*)d_out;

    __half* p_tmp = (__half*)sym(g_p_tmp);
    float* p_node = (float*)sym(g_p_node);
    __half* p_agg = (__half*)sym(g_p_agg);
    float* v_init = (float*)sym(g_v_init);
    __half* v_tmp = (__half*)sym(g_v_tmp);
    float* v_node = (float*)sym(g_v_node);
    __half* v_agg = (__half*)sym(g_v_agg);
    __half* wtv2h = (__half*)sym(g_wtv2_hi);
    __half* wtv2l = (__half*)sym(g_wtv2_lo);
    __half* wtp2h = (__half*)sym(g_wtp2_hi);
    __half* wtp2l = (__half*)sym(g_wtp2_lo);
    float* Mp = (float*)sym(g_Mp);
    float* Mv = (float*)sym(g_Mv);
    float* p_agg8 = (float*)sym(g_p_agg8);
    float* p_s    = (float*)sym(g_p_s);
    float* v_agg8 = (float*)sym(g_v_agg8);
    float* v_s    = (float*)sym(g_v_s);
    int* p_indeg  = (int*)sym(g_p_indeg);
    int* v_indeg  = (int*)sym(g_v_indeg);
    float* p_dinv = (float*)sym(g_p_dinv);
    float* v_dinv = (float*)sym(g_v_dinv);
    int* p_csr    = (int*)sym(g_p_csr);
    int* v_csr    = (int*)sym(g_v_csr);
    float* pgp    = (float*)sym(g_pg_part);
    float* vg     = (float*)sym(g_vg);
    float* av     = (float*)sym(g_addvec);

    cudaFuncSetAttribute(gemm_smem_both, cudaFuncAttributeMaxDynamicSharedMemorySize, GEMM_SMEM);

    // graph structure
    zero_all<<<(NPG + NVG + 255) / 256, 256>>>(p_indeg, v_indeg);
    build_csr<<<(EV + 255) / 256, 256>>>(v_src, v_dst, EV, v_indeg, v_csr);
    build_csr<<<(EP + 255) / 256, 256>>>(p_src, p_dst, EP, p_indeg, p_csr);
    dinv_both<<<(NPG + NVG + 255) / 256, 256>>>(p_indeg, v_indeg, p_dinv, v_dinv);
    // weight prep
    prep_M_both<<<18, 256>>>(p_initW, p_initb, p_W1, v_initW, v_initb, v_W1, Mp, Mv);
    prep_wt_both<<<512, 256>>>(p_W2, v_W2, wtp2h, wtp2l, wtv2h, wtv2l);
    // v init emb
    init_emb_kernel<<<NVG, 256>>>(v_x, v_initW, v_initb, v_init, FV);
    // layer 1 both nets (h1 -> fp16)
    agg8_both<<<(NPG + NVG + 255) / 256, 256>>>(p_x, v_x, p_csr, v_csr, p_indeg, v_indeg,
                                                p_dinv, v_dinv, p_agg8, v_agg8, p_s, v_s);
    layer1_both<<<NPG + NVG, 256>>>(p_agg8, p_s, v_agg8, v_s, Mp, Mv, p_b1, v_b1, p_tmp, v_tmp);
    // layer 2: merged agg (fp16 in/out), merged fp16 GEMM
    gcn_agg_both<<<PBLK + VBLK, 256>>>(p_tmp, v_tmp, p_csr, v_csr, p_indeg, v_indeg,
                                       p_dinv, v_dinv, p_agg, v_agg);
    {
        dim3 gg(2, PGY + VGY);
        gemm_smem_both<<<gg, 256, GEMM_SMEM>>>(p_agg, wtp2h, wtp2l, p_b2, p_node,
                                               v_agg, wtv2h, wtv2l, v_b2, v_node);
    }
    // pooling + fuse
    pool_v_kernel<<<NB, 256>>>(v_node, vg);
    {
        dim3 g(NB, PPOOL);
        pool_p_partial<<<g, 256>>>(p_node, pgp);
    }
    addvec_kernel<<<NB, 256>>>(pgp, vg, v_node, v_init, curr, av);
    const int total4 = NPG * (DD / 4);
    final_kernel<<<(total4 + 255) / 256, 256>>>(p_node, p_x, p_initW, p_initb, av, out);
}

// round 14
// speedup vs baseline: 1.3748x; 1.0312x over previous
#include <cuda_runtime.h>
#include <cuda_bf16.h>
#include <cuda_fp16.h>
#include <cstdint>

// ---------------- problem constants ----------------
#define NB   128
#define NPV  20
#define NPP  500
#define NVG  (NB*NPV)     // 2560
#define NPG  (NB*NPP)     // 64000
#define DD   256
#define FV   6
#define FP   8
#define DEG  8
#define EV   (NVG*DEG)
#define EP   (NPG*DEG)
#define CAP  64
#define PPOOL 10

// ---------------- static device scratch ----------------
__device__ __half g_p_tmp [NPG*DD];           // h1 (p layer-1 output, fp16)
__device__ __half g_p_node[NPG*DD];           // p layer-2 output (fp16)
__device__ __half g_p_agg [NPG*DD];           // agg(h1), fp16

__device__ float  g_v_init[NVG*DD];
__device__ __half g_v_tmp [NVG*DD];           // v h1 (fp16)
__device__ __half g_v_node[NVG*DD];           // v layer-2 output (fp16)
__device__ __half g_v_agg [NVG*DD];

__device__ __half g_wtv2_hi[DD*DD]; __device__ __half g_wtv2_lo[DD*DD];
__device__ __half g_wtp2_hi[DD*DD]; __device__ __half g_wtp2_lo[DD*DD];

__device__ float g_Mp[9*DD];   // rows 0-7: Wi@W1 (zero-padded); row 8: bi@W1
__device__ float g_Mv[9*DD];

__device__ float g_p_agg8[NPG*8];
__device__ float g_p_s[NPG];
__device__ float g_v_agg8[NVG*8];
__device__ float g_v_s[NVG];

__device__ int   g_p_indeg[NPG];
__device__ int   g_v_indeg[NVG];
__device__ int   g_p_csr[NPG*CAP];
__device__ int   g_v_csr[NVG*CAP];

__device__ float g_pg_part[NB*PPOOL*DD];
__device__ float g_vg[NB*DD];
__device__ float g_addvec[NB*DD];

// ---------------- helpers ----------------
__device__ __forceinline__ uint32_t smem_u32(const void* p) {
    uint32_t a;
    asm("{ .reg .u64 t; cvta.to.shared.u64 t, %1; cvt.u32.u64 %0, t; }" : "=r"(a) : "l"(p));
    return a;
}
__device__ __forceinline__ void cpa16(uint32_t dst, const void* src) {
    asm volatile("cp.async.cg.shared.global [%0], [%1], 16;" :: "r"(dst), "l"(src) : "memory");
}
#define CPA_COMMIT() asm volatile("cp.async.commit_group;" ::: "memory")
#define CPA_WAIT0()  asm volatile("cp.async.wait_group 0;" ::: "memory")

#define MMA_F16(ACC, AH, B0, B1)                                                  \
    asm volatile(                                                                  \
        "mma.sync.aligned.m16n8k16.row.col.f32.f16.f16.f32 "                      \
        "{%0,%1,%2,%3}, {%4,%5,%6,%7}, {%8,%9}, {%0,%1,%2,%3};"                   \
        : "+f"((ACC)[0]), "+f"((ACC)[1]), "+f"((ACC)[2]), "+f"((ACC)[3])          \
        : "r"((AH)[0]), "r"((AH)[1]), "r"((AH)[2]), "r"((AH)[3]),                 \
          "r"(B0), "r"(B1))

// ---------------- setup kernels ----------------
__global__ void zero_all(int* p_indeg, int* v_indeg) {
    int i = blockIdx.x * blockDim.x + threadIdx.x;
    if (i < NPG) p_indeg[i] = 0;
    else if (i < NPG + NVG) v_indeg[i - NPG] = 0;
}
__global__ void build_csr(const int* __restrict__ src, const int* __restrict__ dst,
                          int E, int* __restrict__ indeg, int* __restrict__ csr) {
    int e = blockIdx.x * blockDim.x + threadIdx.x;
    if (e >= E) return;
    int d = dst[e];
    int slot = atomicAdd(&indeg[d], 1);
    if (slot < CAP) csr[d * CAP + slot] = src[e];
}

// M rows 0..7 = Wi@W1 (zero-padded); row 8 = bi@W1 ; grid 18 covers p (0-8) and v (9-17)
__global__ __launch_bounds__(256) void prep_M_both(
    const float* __restrict__ pWi, const float* __restrict__ pbi, const float* __restrict__ pW1,
    const float* __restrict__ vWi, const float* __restrict__ vbi, const float* __restrict__ vW1,
    float* __restrict__ Mp, float* __restrict__ Mv) {
    int blk = blockIdx.x, d = threadIdx.x;
    const float* Wi; const float* bi; const float* W1; float* M; int F, f;
    if (blk < 9) { Wi = pWi; bi = pbi; W1 = pW1; M = Mp; F = FP; f = blk; }
    else         { Wi = vWi; bi = vbi; W1 = vW1; M = Mv; F = FV; f = blk - 9; }
    float acc = 0.0f;
    if (f < 8) {
        if (f < F)
            for (int j = 0; j < DD; j++)
                acc = fmaf(__ldg(&Wi[f * DD + j]), __ldg(&W1[j * DD + d]), acc);
    } else {
        for (int j = 0; j < DD; j++)
            acc = fmaf(__ldg(&bi[j]), __ldg(&W1[j * DD + d]), acc);
    }
    M[f * DD + d] = acc;
}

// transpose + fp16 split both W2s; grid 512
__global__ __launch_bounds__(256) void prep_wt_both(
    const float* __restrict__ pW2, const float* __restrict__ vW2,
    __half* __restrict__ phi, __half* __restrict__ plo,
    __half* __restrict__ vhi, __half* __restrict__ vlo) {
    int blk = blockIdx.x, k = threadIdx.x;
    const float* W; __half *hi, *lo; int n;
    if (blk < DD) { W = pW2; hi = phi; lo = plo; n = blk; }
    else          { W = vW2; hi = vhi; lo = vlo; n = blk - DD; }
    float w = W[k * DD + n];
    __half h = __float2half_rn(w);
    hi[n * DD + k] = h;
    lo[n * DD + k] = __float2half_rn(w - __half2float(h));
}

// v init emb (needed in addvec)
__global__ __launch_bounds__(256) void init_emb_kernel(
    const float* __restrict__ x, const float* __restrict__ W, const float* __restrict__ b,
    float* __restrict__ out, int F) {
    int node = blockIdx.x, d = threadIdx.x;
    const float* xr = x + node * F;
    float acc = __ldg(&b[d]);
    #pragma unroll 8
    for (int k = 0; k < 8; k++)
        if (k < F) acc = fmaf(__ldg(&xr[k]), __ldg(&W[k * DD + d]), acc);
    out[node * DD + d] = acc;
}

// ---------------- layer 1: feature-space agg (both nets; launch slot 4) ---------
__global__ __launch_bounds__(256) void agg8_both(
    const float* __restrict__ px, const float* __restrict__ vx,
    const int* __restrict__ p_csr, const int* __restrict__ v_csr,
    const int* __restrict__ p_indeg, const int* __restrict__ v_indeg,
    float* __restrict__ p_agg8, float* __restrict__ v_agg8,
    float* __restrict__ p_s, float* __restrict__ v_s) {
    int i = blockIdx.x * blockDim.x + threadIdx.x;
    const float* x; const int* csr; const int* indeg;
    float* agg8; float* sv; int node, F;
    if (i < NPG) { x = px; csr = p_csr; indeg = p_indeg;
                   agg8 = p_agg8; sv = p_s; node = i; F = FP; }
    else if (i < NPG + NVG) { x = vx; csr = v_csr; indeg = v_indeg;
                   agg8 = v_agg8; sv = v_s; node = i - NPG; F = FV; }
    else return;
    int deg = indeg[node];
    int cnt = deg < CAP ? deg : CAP;
    float self = 1.0f / ((float)deg + 1.0f);
    float ddst = rsqrtf((float)deg + 1.0f);
    float a[8];
    #pragma unroll
    for (int f = 0; f < 8; f++) a[f] = 0.0f;
    if (F == 8) {
        float4 x0 = *(const float4*)(x + node * 8);
        float4 x1 = *(const float4*)(x + node * 8 + 4);
        a[0] = x0.x * self; a[1] = x0.y * self; a[2] = x0.z * self; a[3] = x0.w * self;
        a[4] = x1.x * self; a[5] = x1.y * self; a[6] = x1.z * self; a[7] = x1.w * self;
    } else {
        for (int f = 0; f < F; f++) a[f] = x[node * F + f] * self;
    }
    float ssum = self;
    const int* cp = csr + node * CAP;
    for (int e = 0; e < cnt; e++) {
        int src = cp[e];
        float c = ddst * rsqrtf((float)indeg[src] + 1.0f);
        ssum += c;
        if (F == 8) {
            float4 m0 = *(const float4*)(x + src * 8);
            float4 m1 = *(const float4*)(x + src * 8 + 4);
            a[0] = fmaf(c, m0.x, a[0]); a[1] = fmaf(c, m0.y, a[1]);
            a[2] = fmaf(c, m0.z, a[2]); a[3] = fmaf(c, m0.w, a[3]);
            a[4] = fmaf(c, m1.x, a[4]); a[5] = fmaf(c, m1.y, a[5]);
            a[6] = fmaf(c, m1.z, a[6]); a[7] = fmaf(c, m1.w, a[7]);
        } else {
            for (int f = 0; f < F; f++) a[f] = fmaf(c, x[src * F + f], a[f]);
        }
    }
    *(float4*)(agg8 + node * 8)     = make_float4(a[0], a[1], a[2], a[3]);
    *(float4*)(agg8 + node * 8 + 4) = make_float4(a[4], a[5], a[6], a[7]);
    sv[node] = ssum;
}

// h1 = relu(agg8 @ M[0:8] + s * M[8] + b1) -> fp16 ; blocks cover p then v
__global__ __launch_bounds__(256) void layer1_both(
    const float* __restrict__ p_agg8, const float* __restrict__ p_sv,
    const float* __restrict__ v_agg8, const float* __restrict__ v_sv,
    const float* __restrict__ Mp, const float* __restrict__ Mv,
    const float* __restrict__ pb1, const float* __restrict__ vb1,
    __half* __restrict__ p_h1, __half* __restrict__ v_h1) {
    int blk = blockIdx.x, d = threadIdx.x;
    const float* agg8; const float* sv; const float* M; const float* b1; __half* h1; int node;
    if (blk < NPG) { agg8 = p_agg8; sv = p_sv; M = Mp; b1 = pb1; h1 = p_h1; node = blk; }
    else           { agg8 = v_agg8; sv = v_sv; M = Mv; b1 = vb1; h1 = v_h1; node = blk - NPG; }
    float a0 = __ldg(&agg8[node * 8 + 0]), a1 = __ldg(&agg8[node * 8 + 1]);
    float a2 = __ldg(&agg8[node * 8 + 2]), a3 = __ldg(&agg8[node * 8 + 3]);
    float a4 = __ldg(&agg8[node * 8 + 4]), a5 = __ldg(&agg8[node * 8 + 5]);
    float a6 = __ldg(&agg8[node * 8 + 6]), a7 = __ldg(&agg8[node * 8 + 7]);
    float ss = __ldg(&sv[node]);
    float acc = __ldg(&b1[d]) + ss * __ldg(&M[8 * DD + d]);
    acc = fmaf(a0, __ldg(&M[0 * DD + d]), acc);
    acc = fmaf(a1, __ldg(&M[1 * DD + d]), acc);
    acc = fmaf(a2, __ldg(&M[2 * DD + d]), acc);
    acc = fmaf(a3, __ldg(&M[3 * DD + d]), acc);
    acc = fmaf(a4, __ldg(&M[4 * DD + d]), acc);
    acc = fmaf(a5, __ldg(&M[5 * DD + d]), acc);
    acc = fmaf(a6, __ldg(&M[6 * DD + d]), acc);
    acc = fmaf(a7, __ldg(&M[7 * DD + d]), acc);
    h1[node * DD + d] = __float2half_rn(fmaxf(acc, 0.0f));
}

// ---------------- 256-dim aggregation (fp16 gather) -> fp16 ----------
#define PBLK ((NPG + 7) / 8)
#define VBLK ((NVG + 7) / 8)
__global__ __launch_bounds__(256) void gcn_agg_both(
    const __half* __restrict__ p_h, const __half* __restrict__ v_h,
    const int* __restrict__ p_csr, const int* __restrict__ v_csr,
    const int* __restrict__ p_indeg, const int* __restrict__ v_indeg,
    __half* __restrict__ p_out, __half* __restrict__ v_out) {
    int blk = blockIdx.x;
    const __half* h; const int* csr; const int* indeg;
    __half* outp; int node0, n_nodes;
    if (blk < PBLK) { h = p_h; csr = p_csr; indeg = p_indeg;
                      outp = p_out; node0 = blk * 8; n_nodes = NPG; }
    else            { h = v_h; csr = v_csr; indeg = v_indeg;
                      outp = v_out; node0 = (blk - PBLK) * 8; n_nodes = NVG; }
    int warp = threadIdx.x >> 5;
    int lane = threadIdx.x & 31;
    int node = node0 + warp;
    if (node >= n_nodes) return;
    int d0 = lane * 8;

    int deg = indeg[node];
    int cnt = deg < CAP ? deg : CAP;
    float self = 1.0f / ((float)deg + 1.0f);
    float ddst = rsqrtf((float)deg + 1.0f);

    uint4 hv = *(const uint4*)(h + node * DD + d0);
    const __half2* hp = (const __half2*)&hv;
    float2 f0 = __half22float2(hp[0]);
    float2 f1 = __half22float2(hp[1]);
    float2 f2 = __half22float2(hp[2]);
    float2 f3 = __half22float2(hp[3]);
    float acc[8] = {f0.x * self, f0.y * self, f1.x * self, f1.y * self,
                    f2.x * self, f2.y * self, f3.x * self, f3.y * self};

    const int* cp = csr + node * CAP;
    for (int e = 0; e < cnt; e++) {
        int src = cp[e];
        float c = ddst * rsqrtf((float)indeg[src] + 1.0f);
        uint4 mv = *(const uint4*)(h + src * DD + d0);
        const __half2* mp = (const __half2*)&mv;
        float2 m0 = __half22float2(mp[0]);
        float2 m1 = __half22float2(mp[1]);
        float2 m2 = __half22float2(mp[2]);
        float2 m3 = __half22float2(mp[3]);
        acc[0] = fmaf(c, m0.x, acc[0]); acc[1] = fmaf(c, m0.y, acc[1]);
        acc[2] = fmaf(c, m1.x, acc[2]); acc[3] = fmaf(c, m1.y, acc[3]);
        acc[4] = fmaf(c, m2.x, acc[4]); acc[5] = fmaf(c, m2.y, acc[5]);
        acc[6] = fmaf(c, m3.x, acc[6]); acc[7] = fmaf(c, m3.y, acc[7]);
    }
    int base = node * DD + d0;
    __half2 o0 = __floats2half2_rn(acc[0], acc[1]);
    __half2 o1 = __floats2half2_rn(acc[2], acc[3]);
    __half2 o2 = __floats2half2_rn(acc[4], acc[5]);
    __half2 o3 = __floats2half2_rn(acc[6], acc[7]);
    uint4 ov = make_uint4(*(uint32_t*)&o0, *(uint32_t*)&o1, *(uint32_t*)&o2, *(uint32_t*)&o3);
    *(uint4*)(outp + base) = ov;
}

// ---------------- smem-staged fp16 GEMM, 2-term B split, fp16 out (merged p+v) --
#define KC 32
#define APITCH 80
#define PIECE (128*APITCH)
#define STAGE_BYTES (3*PIECE)
#define GEMM_SMEM (2*STAGE_BYTES)
#define PGY (NPG / 128)   // 500
#define VGY (NVG / 128)   // 20

__global__ void __launch_bounds__(256, 2) gemm_smem_both(
    const __half* __restrict__ pA, const __half* __restrict__ pB_hi,
    const __half* __restrict__ pB_lo, const float* __restrict__ p_bias,
    __half* __restrict__ pC,
    const __half* __restrict__ vA, const __half* __restrict__ vB_hi,
    const __half* __restrict__ vB_lo, const float* __restrict__ v_bias,
    __half* __restrict__ vC) {
    const __half *A, *Bt_hi, *Bt_lo;
    const float* bias; __half* C; int row0;
    if (blockIdx.y < PGY) {
        A = pA; Bt_hi = pB_hi; Bt_lo = pB_lo;
        bias = p_bias; C = pC; row0 = blockIdx.y * 128;
    } else {
        A = vA; Bt_hi = vB_hi; Bt_lo = vB_lo;
        bias = v_bias; C = vC; row0 = (blockIdx.y - PGY) * 128;
    }
    extern __shared__ char sm[];
    uint32_t sb = smem_u32(sm);
    int tid = threadIdx.x;
    int wid = tid >> 5, lane = tid & 31;
    int g = lane >> 2, t = lane & 3;
    int warp_m = wid & 3, warp_n = wid >> 2;
    int col0 = blockIdx.x * 128;

    float acc[2][8][4];
    #pragma unroll
    for (int s = 0; s < 2; s++)
        #pragma unroll
        for (int n = 0; n < 8; n++)
            #pragma unroll
            for (int q = 0; q < 4; q++) acc[s][n][q] = 0.0f;

    int r0i = (tid + 0) >> 2,  c0i = (tid + 0) & 3;
    int r1i = (tid + 256) >> 2, c1i = (tid + 256) & 3;

    auto stage_load = [&](int st) {
        uint32_t base = sb + (st & 1) * STAGE_BYTES;
        int kc0 = st * KC;
        {
            uint32_t d0 = base + r0i * APITCH + c0i * 16;
            size_t ga = (size_t)(row0 + r0i) * DD + kc0 + c0i * 8;
            size_t gb = (size_t)(col0 + r0i) * DD + kc0 + c0i * 8;
            cpa16(d0,           A + ga);
            cpa16(d0 + PIECE,   Bt_hi + gb);
            cpa16(d0 + 2*PIECE, Bt_lo + gb);
        }
        {
            uint32_t d0 = base + r1i * APITCH + c1i * 16;
            size_t ga = (size_t)(row0 + r1i) * DD + kc0 + c1i * 8;
            size_t gb = (size_t)(col0 + r1i) * DD + kc0 + c1i * 8;
            cpa16(d0,           A + ga);
            cpa16(d0 + PIECE,   Bt_hi + gb);
            cpa16(d0 + 2*PIECE, Bt_lo + gb);
        }
        CPA_COMMIT();
    };

    stage_load(0);
    CPA_WAIT0();
    __syncthreads();

    for (int st = 0; st < DD / KC; st++) {
        if (st + 1 < DD / KC) stage_load(st + 1);
        const char* cur = sm + (st & 1) * STAGE_BYTES;

        #pragma unroll
        for (int kk = 0; kk < 2; kk++) {
            int kb = (kk * 16 + t * 2) * 2;
            uint32_t ah[2][4];
            #pragma unroll
            for (int s = 0; s < 2; s++) {
                const char* pa = cur + (warp_m * 32 + s * 16 + g) * APITCH + kb;
                ah[s][0] = *(const uint32_t*)pa;
                ah[s][1] = *(const uint32_t*)(pa + 8 * APITCH);
                ah[s][2] = *(const uint32_t*)(pa + 16);
                ah[s][3] = *(const uint32_t*)(pa + 8 * APITCH + 16);
            }
            #pragma unroll
            for (int nt = 0; nt < 8; nt++) {
                const char* pb = cur + PIECE + (warp_n * 64 + nt * 8 + g) * APITCH + kb;
                uint32_t bh0 = *(const uint32_t*)pb;
                uint32_t bh1 = *(const uint32_t*)(pb + 16);
                const char* pbl = pb + PIECE;
                uint32_t bl0 = *(const uint32_t*)pbl;
                uint32_t bl1 = *(const uint32_t*)(pbl + 16);
                #pragma unroll
                for (int s = 0; s < 2; s++) {
                    MMA_F16(acc[s][nt], ah[s], bh0, bh1);
                    MMA_F16(acc[s][nt], ah[s], bl0, bl1);
                }
            }
        }
        CPA_WAIT0();
        __syncthreads();
    }

    #pragma unroll
    for (int s = 0; s < 2; s++) {
        int r = row0 + warp_m * 32 + s * 16 + g;
        #pragma unroll
        for (int nt = 0; nt < 8; nt++) {
            int c = col0 + warp_n * 64 + nt * 8 + t * 2;
            float bx = __ldg(&bias[c]), by = __ldg(&bias[c + 1]);
            __half2 o0 = __floats2half2_rn(acc[s][nt][0] + bx, acc[s][nt][1] + by);
            __half2 o1 = __floats2half2_rn(acc[s][nt][2] + bx, acc[s][nt][3] + by);
            *(uint32_t*)(C + r * DD + c)       = *(uint32_t*)&o0;
            *(uint32_t*)(C + (r + 8) * DD + c) = *(uint32_t*)&o1;
        }
    }
}

// ---------------- pooling (merged p partials + v) ----------------
// grid (NB, PPOOL+1): y < PPOOL -> p partial over 50 nodes; y == PPOOL -> v pool
__global__ __launch_bounds__(256) void pool_both(
    const __half* __restrict__ p_node, const __half* __restrict__ v_node,
    float* __restrict__ part, float* __restrict__ vg) {
    int b = blockIdx.x, y = blockIdx.y, d = threadIdx.x;
    if (y < PPOOL) {
        const int chunk = NPP / PPOOL;
        const __half* p = p_node + ((size_t)b * NPP + y * chunk) * DD + d;
        float s0 = 0.f, s1 = 0.f;
        #pragma unroll
        for (int i = 0; i < chunk; i += 2) {
            s0 += __half2float(p[i * DD]);
            s1 += __half2float(p[(i + 1) * DD]);
        }
        part[(b * PPOOL + y) * DD + d] = s0 + s1;
    } else {
        const __half* p = v_node + (size_t)b * NPV * DD + d;
        float s = 0.f;
        #pragma unroll
        for (int i = 0; i < NPV; i++) s += __half2float(p[i * DD]);
        vg[b * DD + d] = s * (1.0f / NPV);
    }
}

__global__ void addvec_kernel(const float* __restrict__ pg_part, const float* __restrict__ vg,
                              const __half* __restrict__ v_node, const float* __restrict__ v_init,
                              const int* __restrict__ curr, float* __restrict__ av) {
    int b = blockIdx.x, d = threadIdx.x;
    float pgs = 0.f;
    #pragma unroll
    for (int j = 0; j < PPOOL; j++) pgs += pg_part[(b * PPOOL + j) * DD + d];
    float pgd = pgs * (1.0f / NPP);
    int cid = curr[b];
    int vi = (b * NPV + cid) * DD + d;
    av[b * DD + d] = pgd + 2.0f * vg[b * DD + d] + __half2float(v_node[vi]) + v_init[vi];
}

// out = p_node(fp16) + (p_x@Wi + bi) + addvec[b]
__global__ void final_kernel(const __half* __restrict__ pn, const float* __restrict__ px,
                             const float* __restrict__ Wi, const float* __restrict__ bi,
                             const float* __restrict__ av, float* __restrict__ out) {
    int idx = blockIdx.x * blockDim.x + threadIdx.x;
    const int total4 = NPG * (DD / 4);
    if (idx >= total4) return;
    int node = idx >> 6;
    int d4 = idx & 63;
    int d = d4 * 4;
    int b = node / NPP;
    uint2 pv = *(const uint2*)(pn + (size_t)idx * 4);
    const __half2* ph = (const __half2*)&pv;
    float2 a01 = __half22float2(ph[0]);
    float2 a23 = __half22float2(ph[1]);
    float4 v = ((const float4*)av)[b * (DD / 4) + d4];
    float4 bb = *(const float4*)(bi + d);
    float4 r = make_float4(a01.x + v.x + bb.x, a01.y + v.y + bb.y,
                           a23.x + v.z + bb.z, a23.y + v.w + bb.w);
    const float* xr = px + node * FP;
    #pragma unroll
    for (int k = 0; k < FP; k++) {
        float xv = __ldg(&xr[k]);
        float4 w = *(const float4*)(Wi + k * DD + d);
        r.x = fmaf(xv, w.x, r.x); r.y = fmaf(xv, w.y, r.y);
        r.z = fmaf(xv, w.z, r.z); r.w = fmaf(xv, w.w, r.w);
    }
    ((float4*)out)[idx] = r;
}

// ---------------- host launch ----------------
static inline void* sym(const void* s) {
    void* p = nullptr;
    cudaGetSymbolAddress(&p, s);
    return p;
}

extern "C" void kernel_launch(void* const* d_in, const int* in_sizes, int n_in,
                              void* d_out, int out_size) {
    const float* v_x     = (const float*)d_in[0];
    const float* p_x     = (const float*)d_in[1];
    const int*   v_src   = (const int*)d_in[2];
    const int*   v_dst   = (const int*)d_in[3];
    const int*   p_src   = (const int*)d_in[4];
    const int*   p_dst   = (const int*)d_in[5];
    const int*   curr    = (const int*)d_in[8];
    const float* v_initW = (const float*)d_in[9];
    const float* v_initb = (const float*)d_in[10];
    const float* v_W1    = (const float*)d_in[11];
    const float* v_b1    = (const float*)d_in[12];
    const float* v_W2    = (const float*)d_in[13];
    const float* v_b2    = (const float*)d_in[14];
    const float* p_initW = (const float*)d_in[15];
    const float* p_initb = (const float*)d_in[16];
    const float* p_W1    = (const float*)d_in[17];
    const float* p_b1    = (const float*)d_in[18];
    const float* p_W2    = (const float*)d_in[19];
    const float* p_b2    = (const float*)d_in[20];
    float* out = (float*)d_out;

    __half* p_tmp  = (__half*)sym(g_p_tmp);
    __half* p_node = (__half*)sym(g_p_node);
    __half* p_agg  = (__half*)sym(g_p_agg);
    float* v_init  = (float*)sym(g_v_init);
    __half* v_tmp  = (__half*)sym(g_v_tmp);
    __half* v_node = (__half*)sym(g_v_node);
    __half* v_agg  = (__half*)sym(g_v_agg);
    __half* wtv2h = (__half*)sym(g_wtv2_hi);
    __half* wtv2l = (__half*)sym(g_wtv2_lo);
    __half* wtp2h = (__half*)sym(g_wtp2_hi);
    __half* wtp2l = (__half*)sym(g_wtp2_lo);
    float* Mp = (float*)sym(g_Mp);
    float* Mv = (float*)sym(g_Mv);
    float* p_agg8 = (float*)sym(g_p_agg8);
    float* p_s    = (float*)sym(g_p_s);
    float* v_agg8 = (float*)sym(g_v_agg8);
    float* v_s    = (float*)sym(g_v_s);
    int* p_indeg  = (int*)sym(g_p_indeg);
    int* v_indeg  = (int*)sym(g_v_indeg);
    int* p_csr    = (int*)sym(g_p_csr);
    int* v_csr    = (int*)sym(g_v_csr);
    float* pgp    = (float*)sym(g_pg_part);
    float* vg     = (float*)sym(g_vg);
    float* av     = (float*)sym(g_addvec);

    cudaFuncSetAttribute(gemm_smem_both, cudaFuncAttributeMaxDynamicSharedMemorySize, GEMM_SMEM);

    // 1-3: graph structure
    zero_all<<<(NPG + NVG + 255) / 256, 256>>>(p_indeg, v_indeg);
    build_csr<<<(EV + 255) / 256, 256>>>(v_src, v_dst, EV, v_indeg, v_csr);
    build_csr<<<(EP + 255) / 256, 256>>>(p_src, p_dst, EP, p_indeg, p_csr);
    // 4: layer-1 feature-space aggregation (profiling slot)
    agg8_both<<<(NPG + NVG + 255) / 256, 256>>>(p_x, v_x, p_csr, v_csr, p_indeg, v_indeg,
                                                p_agg8, v_agg8, p_s, v_s);
    // 5-7: weight prep + v init emb (independent of CSR)
    prep_M_both<<<18, 256>>>(p_initW, p_initb, p_W1, v_initW, v_initb, v_W1, Mp, Mv);
    prep_wt_both<<<512, 256>>>(p_W2, v_W2, wtp2h, wtp2l, wtv2h, wtv2l);
    init_emb_kernel<<<NVG, 256>>>(v_x, v_initW, v_initb, v_init, FV);
    // 8: layer-1 combine (h1 -> fp16)
    layer1_both<<<NPG + NVG, 256>>>(p_agg8, p_s, v_agg8, v_s, Mp, Mv, p_b1, v_b1, p_tmp, v_tmp);
    // 9: layer-2 aggregation (fp16 in/out)
    gcn_agg_both<<<PBLK + VBLK, 256>>>(p_tmp, v_tmp, p_csr, v_csr, p_indeg, v_indeg,
                                       p_agg, v_agg);
    // 10: merged fp16 GEMM (fp16 out)
    {
        dim3 gg(2, PGY + VGY);
        gemm_smem_both<<<gg, 256, GEMM_SMEM>>>(p_agg, wtp2h, wtp2l, p_b2, p_node,
                                               v_agg, wtv2h, wtv2l, v_b2, v_node);
    }
    // 11: pooling (p partials + v)
    {
        dim3 g(NB, PPOOL + 1);
        pool_both<<<g, 256>>>(p_node, v_node, pgp, vg);
    }
    // 12: per-graph additive vector
    addvec_kernel<<<NB, 256>>>(pgp, vg, v_node, v_init, curr, av);
    // 13: final fuse
    const int total4 = NPG * (DD / 4);
    final_kernel<<<(total4 + 255) / 256, 256>>>(p_node, p_x, p_initW, p_initb, av, out);
}

// round 15
// speedup vs baseline: 1.6121x; 1.1725x over previous
#include <cuda_runtime.h>
#include <cuda_bf16.h>
#include <cuda_fp16.h>
#include <cstdint>

// ---------------- problem constants ----------------
#define NB   128
#define NPV  20
#define NPP  500
#define NVG  (NB*NPV)     // 2560
#define NPG  (NB*NPP)     // 64000
#define DD   256
#define FV   6
#define FP   8
#define DEG  8
#define EV   (NVG*DEG)
#define EP   (NPG*DEG)
#define CAP  64
#define PPOOL 10

// ---------------- static device scratch ----------------
__device__ __half g_p_tmp [NPG*DD];           // h1 (p layer-1 output, fp16)
__device__ __half g_p_node[NPG*DD];           // p layer-2 output (fp16)
__device__ __half g_p_agg [NPG*DD];           // agg(h1), fp16

__device__ float  g_v_init[NVG*DD];
__device__ __half g_v_tmp [NVG*DD];           // v h1 (fp16)
__device__ __half g_v_node[NVG*DD];           // v layer-2 output (fp16)
__device__ __half g_v_agg [NVG*DD];

__device__ __half g_wtv2_hi[DD*DD]; __device__ __half g_wtv2_lo[DD*DD];
__device__ __half g_wtp2_hi[DD*DD]; __device__ __half g_wtp2_lo[DD*DD];

__device__ float g_Mp[9*DD];   // rows 0-7: Wi@W1 (zero-padded); row 8: bi@W1
__device__ float g_Mv[9*DD];

__device__ int   g_p_indeg[NPG];
__device__ int   g_v_indeg[NVG];
__device__ int   g_p_csr[NPG*CAP];
__device__ int   g_v_csr[NVG*CAP];

__device__ float g_pg_part[NB*PPOOL*DD];
__device__ float g_vg[NB*DD];
__device__ float g_addvec[NB*DD];

// ---------------- helpers ----------------
__device__ __forceinline__ uint32_t smem_u32(const void* p) {
    uint32_t a;
    asm("{ .reg .u64 t; cvta.to.shared.u64 t, %1; cvt.u32.u64 %0, t; }" : "=r"(a) : "l"(p));
    return a;
}
__device__ __forceinline__ void cpa16(uint32_t dst, const void* src) {
    asm volatile("cp.async.cg.shared.global [%0], [%1], 16;" :: "r"(dst), "l"(src) : "memory");
}
#define CPA_COMMIT() asm volatile("cp.async.commit_group;" ::: "memory")
#define CPA_WAIT0()  asm volatile("cp.async.wait_group 0;" ::: "memory")

#define MMA_F16(ACC, AH, B0, B1)                                                  \
    asm volatile(                                                                  \
        "mma.sync.aligned.m16n8k16.row.col.f32.f16.f16.f32 "                      \
        "{%0,%1,%2,%3}, {%4,%5,%6,%7}, {%8,%9}, {%0,%1,%2,%3};"                   \
        : "+f"((ACC)[0]), "+f"((ACC)[1]), "+f"((ACC)[2]), "+f"((ACC)[3])          \
        : "r"((AH)[0]), "r"((AH)[1]), "r"((AH)[2]), "r"((AH)[3]),                 \
          "r"(B0), "r"(B1))

// ---------------- setup: zero indeg + prep_M + prep_wt + v init_emb ----------
// block ranges: [0,260) zero; [260,278) prep_M; [278,790) prep_wt; [790,3350) init_emb
#define ZB   ((NPG + NVG + 255) / 256)        // 260
#define SB_M (ZB)                              // 18 blocks
#define SB_W (SB_M + 18)                       // 512 blocks
#define SB_I (SB_W + 512)                      // NVG blocks
#define SB_TOT (SB_I + NVG)

__global__ __launch_bounds__(256) void setup_kernel(
    int* __restrict__ p_indeg, int* __restrict__ v_indeg,
    const float* __restrict__ pWi, const float* __restrict__ pbi, const float* __restrict__ pW1,
    const float* __restrict__ vWi, const float* __restrict__ vbi, const float* __restrict__ vW1,
    float* __restrict__ Mp, float* __restrict__ Mv,
    const float* __restrict__ pW2, const float* __restrict__ vW2,
    __half* __restrict__ wph, __half* __restrict__ wpl,
    __half* __restrict__ wvh, __half* __restrict__ wvl,
    const float* __restrict__ v_x, float* __restrict__ v_init) {
    int blk = blockIdx.x, d = threadIdx.x;
    if (blk < ZB) {
        int i = blk * 256 + d;
        if (i < NPG) p_indeg[i] = 0;
        else if (i < NPG + NVG) v_indeg[i - NPG] = 0;
    } else if (blk < SB_W) {
        int fb = blk - SB_M;
        const float* Wi; const float* bi; const float* W1; float* M; int F, f;
        if (fb < 9) { Wi = pWi; bi = pbi; W1 = pW1; M = Mp; F = FP; f = fb; }
        else        { Wi = vWi; bi = vbi; W1 = vW1; M = Mv; F = FV; f = fb - 9; }
        float acc = 0.0f;
        if (f < 8) {
            if (f < F)
                for (int j = 0; j < DD; j++)
                    acc = fmaf(__ldg(&Wi[f * DD + j]), __ldg(&W1[j * DD + d]), acc);
        } else {
            for (int j = 0; j < DD; j++)
                acc = fmaf(__ldg(&bi[j]), __ldg(&W1[j * DD + d]), acc);
        }
        M[f * DD + d] = acc;
    } else if (blk < SB_I) {
        int wb = blk - SB_W;   // 0..511
        const float* W; __half *hi, *lo; int n;
        if (wb < DD) { W = pW2; hi = wph; lo = wpl; n = wb; }
        else         { W = vW2; hi = wvh; lo = wvl; n = wb - DD; }
        float w = W[d * DD + n];
        __half h = __float2half_rn(w);
        hi[n * DD + d] = h;
        lo[n * DD + d] = __float2half_rn(w - __half2float(h));
    } else {
        int node = blk - SB_I;   // 0..NVG-1
        const float* xr = v_x + node * FV;
        float acc = __ldg(&vbi[d]);
        #pragma unroll
        for (int k = 0; k < FV; k++)
            acc = fmaf(__ldg(&xr[k]), __ldg(&vWi[k * DD + d]), acc);
        v_init[node * DD + d] = acc;
    }
}

// ---------------- CSR build (both nets, one launch) ----------------
__global__ void build_csr_both(
    const int* __restrict__ p_src, const int* __restrict__ p_dst,
    const int* __restrict__ v_src, const int* __restrict__ v_dst,
    int* __restrict__ p_indeg, int* __restrict__ v_indeg,
    int* __restrict__ p_csr, int* __restrict__ v_csr) {
    int e = blockIdx.x * blockDim.x + threadIdx.x;
    if (e < EP) {
        int dn = p_dst[e];
        int slot = atomicAdd(&p_indeg[dn], 1);
        if (slot < CAP) p_csr[dn * CAP + slot] = p_src[e];
    } else if (e < EP + EV) {
        int i = e - EP;
        int dn = v_dst[i];
        int slot = atomicAdd(&v_indeg[dn], 1);
        if (slot < CAP) v_csr[dn * CAP + slot] = v_src[i];
    }
}

// ---------------- fused layer 1: agg8 + combine -> fp16 h1 (warp per node) ------
#define L1_BLKS ((NPG + NVG + 7) / 8)
__global__ __launch_bounds__(256) void layer1_fused(
    const float* __restrict__ px, const float* __restrict__ vx,
    const int* __restrict__ p_csr, const int* __restrict__ v_csr,
    const int* __restrict__ p_indeg, const int* __restrict__ v_indeg,
    const float* __restrict__ Mp, const float* __restrict__ Mv,
    const float* __restrict__ pb1, const float* __restrict__ vb1,
    __half* __restrict__ p_h1, __half* __restrict__ v_h1) {
    int gw = blockIdx.x * 8 + (threadIdx.x >> 5);
    int lane = threadIdx.x & 31;
    const float* x; const int* csr; const int* indeg; const float* M;
    const float* b1; __half* h1; int node, F;
    if (gw < NPG) { x = px; csr = p_csr; indeg = p_indeg; M = Mp; b1 = pb1;
                    h1 = p_h1; node = gw; F = FP; }
    else if (gw < NPG + NVG) { x = vx; csr = v_csr; indeg = v_indeg; M = Mv; b1 = vb1;
                    h1 = v_h1; node = gw - NPG; F = FV; }
    else return;

    int deg = indeg[node];
    int cnt = deg < CAP ? deg : CAP;
    float self = 1.0f / ((float)deg + 1.0f);
    float ddst = rsqrtf((float)deg + 1.0f);

    float a[8];
    #pragma unroll
    for (int f = 0; f < 8; f++) a[f] = 0.0f;
    float s_part = 0.0f;
    const int* cp = csr + node * CAP;
    for (int e = lane; e < cnt; e += 32) {
        int src = cp[e];
        float c = ddst * rsqrtf((float)indeg[src] + 1.0f);
        s_part += c;
        if (F == 8) {
            float4 m0 = *(const float4*)(x + src * 8);
            float4 m1 = *(const float4*)(x + src * 8 + 4);
            a[0] = fmaf(c, m0.x, a[0]); a[1] = fmaf(c, m0.y, a[1]);
            a[2] = fmaf(c, m0.z, a[2]); a[3] = fmaf(c, m0.w, a[3]);
            a[4] = fmaf(c, m1.x, a[4]); a[5] = fmaf(c, m1.y, a[5]);
            a[6] = fmaf(c, m1.z, a[6]); a[7] = fmaf(c, m1.w, a[7]);
        } else {
            #pragma unroll
            for (int f = 0; f < FV; f++) a[f] = fmaf(c, x[src * FV + f], a[f]);
        }
    }
    // butterfly reduce across warp (all lanes end with full sums)
    #pragma unroll
    for (int off = 16; off; off >>= 1) {
        s_part += __shfl_xor_sync(0xFFFFFFFFu, s_part, off);
        #pragma unroll
        for (int f = 0; f < 8; f++)
            a[f] += __shfl_xor_sync(0xFFFFFFFFu, a[f], off);
    }
    float s = s_part + self;
    // self term (uniform across lanes; broadcast loads)
    if (F == 8) {
        float4 x0 = *(const float4*)(x + node * 8);
        float4 x1 = *(const float4*)(x + node * 8 + 4);
        a[0] = fmaf(self, x0.x, a[0]); a[1] = fmaf(self, x0.y, a[1]);
        a[2] = fmaf(self, x0.z, a[2]); a[3] = fmaf(self, x0.w, a[3]);
        a[4] = fmaf(self, x1.x, a[4]); a[5] = fmaf(self, x1.y, a[5]);
        a[6] = fmaf(self, x1.z, a[6]); a[7] = fmaf(self, x1.w, a[7]);
    } else {
        #pragma unroll
        for (int f = 0; f < FV; f++) a[f] = fmaf(self, x[node * FV + f], a[f]);
    }
    // each lane computes 8 channels
    int d0 = lane * 8;
    float acc[8];
    {
        float4 b0 = *(const float4*)(b1 + d0);
        float4 bb1 = *(const float4*)(b1 + d0 + 4);
        float4 m80 = *(const float4*)(M + 8 * DD + d0);
        float4 m81 = *(const float4*)(M + 8 * DD + d0 + 4);
        acc[0] = fmaf(s, m80.x, b0.x);  acc[1] = fmaf(s, m80.y, b0.y);
        acc[2] = fmaf(s, m80.z, b0.z);  acc[3] = fmaf(s, m80.w, b0.w);
        acc[4] = fmaf(s, m81.x, bb1.x); acc[5] = fmaf(s, m81.y, bb1.y);
        acc[6] = fmaf(s, m81.z, bb1.z); acc[7] = fmaf(s, m81.w, bb1.w);
    }
    #pragma unroll
    for (int k = 0; k < 8; k++) {
        float4 w0 = *(const float4*)(M + k * DD + d0);
        float4 w1 = *(const float4*)(M + k * DD + d0 + 4);
        float ak = a[k];
        acc[0] = fmaf(ak, w0.x, acc[0]); acc[1] = fmaf(ak, w0.y, acc[1]);
        acc[2] = fmaf(ak, w0.z, acc[2]); acc[3] = fmaf(ak, w0.w, acc[3]);
        acc[4] = fmaf(ak, w1.x, acc[4]); acc[5] = fmaf(ak, w1.y, acc[5]);
        acc[6] = fmaf(ak, w1.z, acc[6]); acc[7] = fmaf(ak, w1.w, acc[7]);
    }
    __half2 o0 = __floats2half2_rn(fmaxf(acc[0], 0.f), fmaxf(acc[1], 0.f));
    __half2 o1 = __floats2half2_rn(fmaxf(acc[2], 0.f), fmaxf(acc[3], 0.f));
    __half2 o2 = __floats2half2_rn(fmaxf(acc[4], 0.f), fmaxf(acc[5], 0.f));
    __half2 o3 = __floats2half2_rn(fmaxf(acc[6], 0.f), fmaxf(acc[7], 0.f));
    uint4 ov = make_uint4(*(uint32_t*)&o0, *(uint32_t*)&o1, *(uint32_t*)&o2, *(uint32_t*)&o3);
    *(uint4*)(h1 + node * DD + d0) = ov;
}

// ---------------- 256-dim aggregation (fp16 gather) -> fp16 ----------
#define PBLK ((NPG + 7) / 8)
#define VBLK ((NVG + 7) / 8)
__global__ __launch_bounds__(256) void gcn_agg_both(
    const __half* __restrict__ p_h, const __half* __restrict__ v_h,
    const int* __restrict__ p_csr, const int* __restrict__ v_csr,
    const int* __restrict__ p_indeg, const int* __restrict__ v_indeg,
    __half* __restrict__ p_out, __half* __restrict__ v_out) {
    int blk = blockIdx.x;
    const __half* h; const int* csr; const int* indeg;
    __half* outp; int node0, n_nodes;
    if (blk < PBLK) { h = p_h; csr = p_csr; indeg = p_indeg;
                      outp = p_out; node0 = blk * 8; n_nodes = NPG; }
    else            { h = v_h; csr = v_csr; indeg = v_indeg;
                      outp = v_out; node0 = (blk - PBLK) * 8; n_nodes = NVG; }
    int warp = threadIdx.x >> 5;
    int lane = threadIdx.x & 31;
    int node = node0 + warp;
    if (node >= n_nodes) return;
    int d0 = lane * 8;

    int deg = indeg[node];
    int cnt = deg < CAP ? deg : CAP;
    float self = 1.0f / ((float)deg + 1.0f);
    float ddst = rsqrtf((float)deg + 1.0f);

    uint4 hv = *(const uint4*)(h + node * DD + d0);
    const __half2* hp = (const __half2*)&hv;
    float2 f0 = __half22float2(hp[0]);
    float2 f1 = __half22float2(hp[1]);
    float2 f2 = __half22float2(hp[2]);
    float2 f3 = __half22float2(hp[3]);
    float acc[8] = {f0.x * self, f0.y * self, f1.x * self, f1.y * self,
                    f2.x * self, f2.y * self, f3.x * self, f3.y * self};

    const int* cp = csr + node * CAP;
    for (int e = 0; e < cnt; e++) {
        int src = cp[e];
        float c = ddst * rsqrtf((float)indeg[src] + 1.0f);
        uint4 mv = *(const uint4*)(h + src * DD + d0);
        const __half2* mp = (const __half2*)&mv;
        float2 m0 = __half22float2(mp[0]);
        float2 m1 = __half22float2(mp[1]);
        float2 m2 = __half22float2(mp[2]);
        float2 m3 = __half22float2(mp[3]);
        acc[0] = fmaf(c, m0.x, acc[0]); acc[1] = fmaf(c, m0.y, acc[1]);
        acc[2] = fmaf(c, m1.x, acc[2]); acc[3] = fmaf(c, m1.y, acc[3]);
        acc[4] = fmaf(c, m2.x, acc[4]); acc[5] = fmaf(c, m2.y, acc[5]);
        acc[6] = fmaf(c, m3.x, acc[6]); acc[7] = fmaf(c, m3.y, acc[7]);
    }
    int base = node * DD + d0;
    __half2 o0 = __floats2half2_rn(acc[0], acc[1]);
    __half2 o1 = __floats2half2_rn(acc[2], acc[3]);
    __half2 o2 = __floats2half2_rn(acc[4], acc[5]);
    __half2 o3 = __floats2half2_rn(acc[6], acc[7]);
    uint4 ov = make_uint4(*(uint32_t*)&o0, *(uint32_t*)&o1, *(uint32_t*)&o2, *(uint32_t*)&o3);
    *(uint4*)(outp + base) = ov;
}

// ---------------- smem-staged fp16 GEMM, 2-term B split, fp16 out (merged p+v) --
#define KC 32
#define APITCH 80
#define PIECE (128*APITCH)
#define STAGE_BYTES (3*PIECE)
#define GEMM_SMEM (2*STAGE_BYTES)
#define PGY (NPG / 128)   // 500
#define VGY (NVG / 128)   // 20

__global__ void __launch_bounds__(256, 2) gemm_smem_both(
    const __half* __restrict__ pA, const __half* __restrict__ pB_hi,
    const __half* __restrict__ pB_lo, const float* __restrict__ p_bias,
    __half* __restrict__ pC,
    const __half* __restrict__ vA, const __half* __restrict__ vB_hi,
    const __half* __restrict__ vB_lo, const float* __restrict__ v_bias,
    __half* __restrict__ vC) {
    const __half *A, *Bt_hi, *Bt_lo;
    const float* bias; __half* C; int row0;
    if (blockIdx.y < PGY) {
        A = pA; Bt_hi = pB_hi; Bt_lo = pB_lo;
        bias = p_bias; C = pC; row0 = blockIdx.y * 128;
    } else {
        A = vA; Bt_hi = vB_hi; Bt_lo = vB_lo;
        bias = v_bias; C = vC; row0 = (blockIdx.y - PGY) * 128;
    }
    extern __shared__ char sm[];
    uint32_t sb = smem_u32(sm);
    int tid = threadIdx.x;
    int wid = tid >> 5, lane = tid & 31;
    int g = lane >> 2, t = lane & 3;
    int warp_m = wid & 3, warp_n = wid >> 2;
    int col0 = blockIdx.x * 128;

    float acc[2][8][4];
    #pragma unroll
    for (int s = 0; s < 2; s++)
        #pragma unroll
        for (int n = 0; n < 8; n++)
            #pragma unroll
            for (int q = 0; q < 4; q++) acc[s][n][q] = 0.0f;

    int r0i = (tid + 0) >> 2,  c0i = (tid + 0) & 3;
    int r1i = (tid + 256) >> 2, c1i = (tid + 256) & 3;

    auto stage_load = [&](int st) {
        uint32_t base = sb + (st & 1) * STAGE_BYTES;
        int kc0 = st * KC;
        {
            uint32_t d0 = base + r0i * APITCH + c0i * 16;
            size_t ga = (size_t)(row0 + r0i) * DD + kc0 + c0i * 8;
            size_t gb = (size_t)(col0 + r0i) * DD + kc0 + c0i * 8;
            cpa16(d0,           A + ga);
            cpa16(d0 + PIECE,   Bt_hi + gb);
            cpa16(d0 + 2*PIECE, Bt_lo + gb);
        }
        {
            uint32_t d0 = base + r1i * APITCH + c1i * 16;
            size_t ga = (size_t)(row0 + r1i) * DD + kc0 + c1i * 8;
            size_t gb = (size_t)(col0 + r1i) * DD + kc0 + c1i * 8;
            cpa16(d0,           A + ga);
            cpa16(d0 + PIECE,   Bt_hi + gb);
            cpa16(d0 + 2*PIECE, Bt_lo + gb);
        }
        CPA_COMMIT();
    };

    stage_load(0);
    CPA_WAIT0();
    __syncthreads();

    for (int st = 0; st < DD / KC; st++) {
        if (st + 1 < DD / KC) stage_load(st + 1);
        const char* cur = sm + (st & 1) * STAGE_BYTES;

        #pragma unroll
        for (int kk = 0; kk < 2; kk++) {
            int kb = (kk * 16 + t * 2) * 2;
            uint32_t ah[2][4];
            #pragma unroll
            for (int s = 0; s < 2; s++) {
                const char* pa = cur + (warp_m * 32 + s * 16 + g) * APITCH + kb;
                ah[s][0] = *(const uint32_t*)pa;
                ah[s][1] = *(const uint32_t*)(pa + 8 * APITCH);
                ah[s][2] = *(const uint32_t*)(pa + 16);
                ah[s][3] = *(const uint32_t*)(pa + 8 * APITCH + 16);
            }
            #pragma unroll
            for (int nt = 0; nt < 8; nt++) {
                const char* pb = cur + PIECE + (warp_n * 64 + nt * 8 + g) * APITCH + kb;
                uint32_t bh0 = *(const uint32_t*)pb;
                uint32_t bh1 = *(const uint32_t*)(pb + 16);
                const char* pbl = pb + PIECE;
                uint32_t bl0 = *(const uint32_t*)pbl;
                uint32_t bl1 = *(const uint32_t*)(pbl + 16);
                #pragma unroll
                for (int s = 0; s < 2; s++) {
                    MMA_F16(acc[s][nt], ah[s], bh0, bh1);
                    MMA_F16(acc[s][nt], ah[s], bl0, bl1);
                }
            }
        }
        CPA_WAIT0();
        __syncthreads();
    }

    #pragma unroll
    for (int s = 0; s < 2; s++) {
        int r = row0 + warp_m * 32 + s * 16 + g;
        #pragma unroll
        for (int nt = 0; nt < 8; nt++) {
            int c = col0 + warp_n * 64 + nt * 8 + t * 2;
            float bx = __ldg(&bias[c]), by = __ldg(&bias[c + 1]);
            __half2 o0 = __floats2half2_rn(acc[s][nt][0] + bx, acc[s][nt][1] + by);
            __half2 o1 = __floats2half2_rn(acc[s][nt][2] + bx, acc[s][nt][3] + by);
            *(uint32_t*)(C + r * DD + c)       = *(uint32_t*)&o0;
            *(uint32_t*)(C + (r + 8) * DD + c) = *(uint32_t*)&o1;
        }
    }
}

// ---------------- pooling (merged p partials + v) ----------------
__global__ __launch_bounds__(256) void pool_both(
    const __half* __restrict__ p_node, const __half* __restrict__ v_node,
    float* __restrict__ part, float* __restrict__ vg) {
    int b = blockIdx.x, y = blockIdx.y, d = threadIdx.x;
    if (y < PPOOL) {
        const int chunk = NPP / PPOOL;
        const __half* p = p_node + ((size_t)b * NPP + y * chunk) * DD + d;
        float s0 = 0.f, s1 = 0.f;
        #pragma unroll
        for (int i = 0; i < chunk; i += 2) {
            s0 += __half2float(p[i * DD]);
            s1 += __half2float(p[(i + 1) * DD]);
        }
        part[(b * PPOOL + y) * DD + d] = s0 + s1;
    } else {
        const __half* p = v_node + (size_t)b * NPV * DD + d;
        float s = 0.f;
        #pragma unroll
        for (int i = 0; i < NPV; i++) s += __half2float(p[i * DD]);
        vg[b * DD + d] = s * (1.0f / NPV);
    }
}

__global__ void addvec_kernel(const float* __restrict__ pg_part, const float* __restrict__ vg,
                              const __half* __restrict__ v_node, const float* __restrict__ v_init,
                              const int* __restrict__ curr, float* __restrict__ av) {
    int b = blockIdx.x, d = threadIdx.x;
    float pgs = 0.f;
    #pragma unroll
    for (int j = 0; j < PPOOL; j++) pgs += pg_part[(b * PPOOL + j) * DD + d];
    float pgd = pgs * (1.0f / NPP);
    int cid = curr[b];
    int vi = (b * NPV + cid) * DD + d;
    av[b * DD + d] = pgd + 2.0f * vg[b * DD + d] + __half2float(v_node[vi]) + v_init[vi];
}

// out = p_node(fp16) + (p_x@Wi + bi) + addvec[b]
__global__ void final_kernel(const __half* __restrict__ pn, const float* __restrict__ px,
                             const float* __restrict__ Wi, const float* __restrict__ bi,
                             const float* __restrict__ av, float* __restrict__ out) {
    int idx = blockIdx.x * blockDim.x + threadIdx.x;
    const int total4 = NPG * (DD / 4);
    if (idx >= total4) return;
    int node = idx >> 6;
    int d4 = idx & 63;
    int d = d4 * 4;
    int b = node / NPP;
    uint2 pv = *(const uint2*)(pn + (size_t)idx * 4);
    const __half2* ph = (const __half2*)&pv;
    float2 a01 = __half22float2(ph[0]);
    float2 a23 = __half22float2(ph[1]);
    float4 v = ((const float4*)av)[b * (DD / 4) + d4];
    float4 bb = *(const float4*)(bi + d);
    float4 r = make_float4(a01.x + v.x + bb.x, a01.y + v.y + bb.y,
                           a23.x + v.z + bb.z, a23.y + v.w + bb.w);
    const float* xr = px + node * FP;
    #pragma unroll
    for (int k = 0; k < FP; k++) {
        float xv = __ldg(&xr[k]);
        float4 w = *(const float4*)(Wi + k * DD + d);
        r.x = fmaf(xv, w.x, r.x); r.y = fmaf(xv, w.y, r.y);
        r.z = fmaf(xv, w.z, r.z); r.w = fmaf(xv, w.w, r.w);
    }
    ((float4*)out)[idx] = r;
}

// ---------------- host launch ----------------
static inline void* sym(const void* s) {
    void* p = nullptr;
    cudaGetSymbolAddress(&p, s);
    return p;
}

extern "C" void kernel_launch(void* const* d_in, const int* in_sizes, int n_in,
                              void* d_out, int out_size) {
    const float* v_x     = (const float*)d_in[0];
    const float* p_x     = (const float*)d_in[1];
    const int*   v_src   = (const int*)d_in[2];
    const int*   v_dst   = (const int*)d_in[3];
    const int*   p_src   = (const int*)d_in[4];
    const int*   p_dst   = (const int*)d_in[5];
    const int*   curr    = (const int*)d_in[8];
    const float* v_initW = (const float*)d_in[9];
    const float* v_initb = (const float*)d_in[10];
    const float* v_W1    = (const float*)d_in[11];
    const float* v_b1    = (const float*)d_in[12];
    const float* v_W2    = (const float*)d_in[13];
    const float* v_b2    = (const float*)d_in[14];
    const float* p_initW = (const float*)d_in[15];
    const float* p_initb = (const float*)d_in[16];
    const float* p_W1    = (const float*)d_in[17];
    const float* p_b1    = (const float*)d_in[18];
    const float* p_W2    = (const float*)d_in[19];
    const float* p_b2    = (const float*)d_in[20];
    float* out = (float*)d_out;

    __half* p_tmp  = (__half*)sym(g_p_tmp);
    __half* p_node = (__half*)sym(g_p_node);
    __half* p_agg  = (__half*)sym(g_p_agg);
    float* v_init  = (float*)sym(g_v_init);
    __half* v_tmp  = (__half*)sym(g_v_tmp);
    __half* v_node = (__half*)sym(g_v_node);
    __half* v_agg  = (__half*)sym(g_v_agg);
    __half* wtv2h = (__half*)sym(g_wtv2_hi);
    __half* wtv2l = (__half*)sym(g_wtv2_lo);
    __half* wtp2h = (__half*)sym(g_wtp2_hi);
    __half* wtp2l = (__half*)sym(g_wtp2_lo);
    float* Mp = (float*)sym(g_Mp);
    float* Mv = (float*)sym(g_Mv);
    int* p_indeg  = (int*)sym(g_p_indeg);
    int* v_indeg  = (int*)sym(g_v_indeg);
    int* p_csr    = (int*)sym(g_p_csr);
    int* v_csr    = (int*)sym(g_v_csr);
    float* pgp    = (float*)sym(g_pg_part);
    float* vg     = (float*)sym(g_vg);
    float* av     = (float*)sym(g_addvec);

    cudaFuncSetAttribute(gemm_smem_both, cudaFuncAttributeMaxDynamicSharedMemorySize, GEMM_SMEM);

    // 1: setup (zero + prep_M + prep_wt + v init_emb)
    setup_kernel<<<SB_TOT, 256>>>(p_indeg, v_indeg,
                                  p_initW, p_initb, p_W1, v_initW, v_initb, v_W1, Mp, Mv,
                                  p_W2, v_W2, wtp2h, wtp2l, wtv2h, wtv2l, v_x, v_init);
    // 2: CSR build (both)
    build_csr_both<<<(EP + EV + 255) / 256, 256>>>(p_src, p_dst, v_src, v_dst,
                                                   p_indeg, v_indeg, p_csr, v_csr);
    // 3: fused layer-1 (agg8 + combine, warp per node)
    layer1_fused<<<L1_BLKS, 256>>>(p_x, v_x, p_csr, v_csr, p_indeg, v_indeg,
                                   Mp, Mv, p_b1, v_b1, p_tmp, v_tmp);
    // 4: layer-2 aggregation (fp16 in/out) — profiling slot
    gcn_agg_both<<<PBLK + VBLK, 256>>>(p_tmp, v_tmp, p_csr, v_csr, p_indeg, v_indeg,
                                       p_agg, v_agg);
    // 5: merged fp16 GEMM (fp16 out)
    {
        dim3 gg(2, PGY + VGY);
        gemm_smem_both<<<gg, 256, GEMM_SMEM>>>(p_agg, wtp2h, wtp2l, p_b2, p_node,
                                               v_agg, wtv2h, wtv2l, v_b2, v_node);
    }
    // 6: pooling
    {
        dim3 g(NB, PPOOL + 1);
        pool_both<<<g, 256>>>(p_node, v_node, pgp, vg);
    }
    // 7: per-graph additive vector
    addvec_kernel<<<NB, 256>>>(pgp, vg, v_node, v_init, curr, av);
    // 8: final fuse
    const int total4 = NPG * (DD / 4);
    final_kernel<<<(total4 + 255) / 256, 256>>>(p_node, p_x, p_initW, p_initb, av, out);
}

// round 16
// speedup vs baseline: 1.8150x; 1.1259x over previous
#include <cuda_runtime.h>
#include <cuda_bf16.h>
#include <cuda_fp16.h>
#include <cstdint>

// ---------------- problem constants ----------------
#define NB   128
#define NPV  20
#define NPP  500
#define NVG  (NB*NPV)     // 2560
#define NPG  (NB*NPP)     // 64000
#define DD   256
#define FV   6
#define FP   8
#define DEG  8
#define EV   (NVG*DEG)
#define EP   (NPG*DEG)
#define CAP  64
#define PPOOL 10

// ---------------- static device scratch ----------------
__device__ __half g_p_tmp [NPG*DD];           // h1 (p layer-1 output, fp16)
__device__ __half g_p_agg [NPG*DD];           // agg(h1), fp16
__device__ __half g_px8   [NPG*8];            // p_x in fp16 (K-extension A)

__device__ float  g_v_init[NVG*DD];
__device__ __half g_v_tmp [NVG*DD];           // v h1 (fp16)
__device__ __half g_v_node[NVG*DD];           // v layer-2 output (fp16)
__device__ __half g_v_agg [NVG*DD];

__device__ __half g_wtv2[DD*DD];              // fp16(W2t) v
__device__ __half g_wtp2[DD*DD];              // fp16(W2t) p
__device__ __half g_wit8[DD*8];               // fp16(Wi_p transposed): wit8[c*8+k]

__device__ float g_Mp[9*DD];   // rows 0-7: Wi@W1 (zero-padded); row 8: bi@W1
__device__ float g_Mv[9*DD];

__device__ int   g_p_indeg[NPG];
__device__ int   g_v_indeg[NVG];
__device__ int   g_p_csr[NPG*CAP];
__device__ int   g_v_csr[NVG*CAP];

__device__ float g_pg_part[NB*PPOOL*DD];
__device__ float g_vg[NB*DD];
__device__ float g_av2[NB*DD];

// ---------------- helpers ----------------
__device__ __forceinline__ uint32_t smem_u32(const void* p) {
    uint32_t a;
    asm("{ .reg .u64 t; cvta.to.shared.u64 t, %1; cvt.u32.u64 %0, t; }" : "=r"(a) : "l"(p));
    return a;
}
__device__ __forceinline__ void cpa16(uint32_t dst, const void* src) {
    asm volatile("cp.async.cg.shared.global [%0], [%1], 16;" :: "r"(dst), "l"(src) : "memory");
}
#define CPA_COMMIT() asm volatile("cp.async.commit_group;" ::: "memory")
#define CPA_WAIT0()  asm volatile("cp.async.wait_group 0;" ::: "memory")

#define MMA_F16(ACC, AH, B0, B1)                                                  \
    asm volatile(                                                                  \
        "mma.sync.aligned.m16n8k16.row.col.f32.f16.f16.f32 "                      \
        "{%0,%1,%2,%3}, {%4,%5,%6,%7}, {%8,%9}, {%0,%1,%2,%3};"                   \
        : "+f"((ACC)[0]), "+f"((ACC)[1]), "+f"((ACC)[2]), "+f"((ACC)[3])          \
        : "r"((AH)[0]), "r"((AH)[1]), "r"((AH)[2]), "r"((AH)[3]),                 \
          "r"(B0), "r"(B1))

// ---------------- setup: zero + prep_M + W2t fp16 + Wit8 + v init_emb ----------
#define ZB    ((NPG + NVG + 255) / 256)       // 260
#define SB_M  (ZB)                             // +18
#define SB_WT (SB_M + 18)                      // +512
#define SB_WI (SB_WT + 512)                    // +8
#define SB_IE (SB_WI + 8)                      // +NVG
#define SB_TOT (SB_IE + NVG)

__global__ __launch_bounds__(256) void setup_kernel(
    int* __restrict__ p_indeg, int* __restrict__ v_indeg,
    const float* __restrict__ pWi, const float* __restrict__ pbi, const float* __restrict__ pW1,
    const float* __restrict__ vWi, const float* __restrict__ vbi, const float* __restrict__ vW1,
    float* __restrict__ Mp, float* __restrict__ Mv,
    const float* __restrict__ pW2, const float* __restrict__ vW2,
    __half* __restrict__ wtp, __half* __restrict__ wtv, __half* __restrict__ wit8,
    const float* __restrict__ v_x, float* __restrict__ v_init) {
    int blk = blockIdx.x, d = threadIdx.x;
    if (blk < ZB) {
        int i = blk * 256 + d;
        if (i < NPG) p_indeg[i] = 0;
        else if (i < NPG + NVG) v_indeg[i - NPG] = 0;
    } else if (blk < SB_WT) {
        int fb = blk - SB_M;
        const float* Wi; const float* bi; const float* W1; float* M; int F, f;
        if (fb < 9) { Wi = pWi; bi = pbi; W1 = pW1; M = Mp; F = FP; f = fb; }
        else        { Wi = vWi; bi = vbi; W1 = vW1; M = Mv; F = FV; f = fb - 9; }
        float acc = 0.0f;
        if (f < 8) {
            if (f < F)
                for (int j = 0; j < DD; j++)
                    acc = fmaf(__ldg(&Wi[f * DD + j]), __ldg(&W1[j * DD + d]), acc);
        } else {
            for (int j = 0; j < DD; j++)
                acc = fmaf(__ldg(&bi[j]), __ldg(&W1[j * DD + d]), acc);
        }
        M[f * DD + d] = acc;
    } else if (blk < SB_WI) {
        int wb = blk - SB_WT;   // 0..511
        const float* W; __half* hi; int n;
        if (wb < DD) { W = pW2; hi = wtp; n = wb; }
        else         { W = vW2; hi = wtv; n = wb - DD; }
        hi[n * DD + d] = __float2half_rn(W[d * DD + n]);
    } else if (blk < SB_IE) {
        int elem = (blk - SB_WI) * 256 + d;      // 0..2047
        if (elem < DD * 8) {
            int col = elem >> 3, k = elem & 7;
            wit8[elem] = __float2half_rn(__ldg(&pWi[k * DD + col]));
        }
    } else {
        int node = blk - SB_IE;
        const float* xr = v_x + node * FV;
        float acc = __ldg(&vbi[d]);
        #pragma unroll
        for (int k = 0; k < FV; k++)
            acc = fmaf(__ldg(&xr[k]), __ldg(&vWi[k * DD + d]), acc);
        v_init[node * DD + d] = acc;
    }
}

// ---------------- CSR build (both nets, one launch) ----------------
__global__ void build_csr_both(
    const int* __restrict__ p_src, const int* __restrict__ p_dst,
    const int* __restrict__ v_src, const int* __restrict__ v_dst,
    int* __restrict__ p_indeg, int* __restrict__ v_indeg,
    int* __restrict__ p_csr, int* __restrict__ v_csr) {
    int e = blockIdx.x * blockDim.x + threadIdx.x;
    if (e < EP) {
        int dn = p_dst[e];
        int slot = atomicAdd(&p_indeg[dn], 1);
        if (slot < CAP) p_csr[dn * CAP + slot] = p_src[e];
    } else if (e < EP + EV) {
        int i = e - EP;
        int dn = v_dst[i];
        int slot = atomicAdd(&v_indeg[dn], 1);
        if (slot < CAP) v_csr[dn * CAP + slot] = v_src[i];
    }
}

// ---------------- fused layer 1 (warp per node) + px8 emit ----------------
#define L1_BLKS ((NPG + NVG + 7) / 8)
__global__ __launch_bounds__(256) void layer1_fused(
    const float* __restrict__ px, const float* __restrict__ vx,
    const int* __restrict__ p_csr, const int* __restrict__ v_csr,
    const int* __restrict__ p_indeg, const int* __restrict__ v_indeg,
    const float* __restrict__ Mp, const float* __restrict__ Mv,
    const float* __restrict__ pb1, const float* __restrict__ vb1,
    __half* __restrict__ p_h1, __half* __restrict__ v_h1,
    __half* __restrict__ px8) {
    int gw = blockIdx.x * 8 + (threadIdx.x >> 5);
    int lane = threadIdx.x & 31;
    const float* x; const int* csr; const int* indeg; const float* M;
    const float* b1; __half* h1; int node, F;
    bool is_p = gw < NPG;
    if (is_p) { x = px; csr = p_csr; indeg = p_indeg; M = Mp; b1 = pb1;
                h1 = p_h1; node = gw; F = FP; }
    else if (gw < NPG + NVG) { x = vx; csr = v_csr; indeg = v_indeg; M = Mv; b1 = vb1;
                h1 = v_h1; node = gw - NPG; F = FV; }
    else return;

    if (is_p && lane < 8)
        px8[node * 8 + lane] = __float2half_rn(x[node * 8 + lane]);

    int deg = indeg[node];
    int cnt = deg < CAP ? deg : CAP;
    float self = 1.0f / ((float)deg + 1.0f);
    float ddst = rsqrtf((float)deg + 1.0f);

    float a[8];
    #pragma unroll
    for (int f = 0; f < 8; f++) a[f] = 0.0f;
    float s_part = 0.0f;
    const int* cp = csr + node * CAP;
    for (int e = lane; e < cnt; e += 32) {
        int src = cp[e];
        float c = ddst * rsqrtf((float)indeg[src] + 1.0f);
        s_part += c;
        if (F == 8) {
            float4 m0 = *(const float4*)(x + src * 8);
            float4 m1 = *(const float4*)(x + src * 8 + 4);
            a[0] = fmaf(c, m0.x, a[0]); a[1] = fmaf(c, m0.y, a[1]);
            a[2] = fmaf(c, m0.z, a[2]); a[3] = fmaf(c, m0.w, a[3]);
            a[4] = fmaf(c, m1.x, a[4]); a[5] = fmaf(c, m1.y, a[5]);
            a[6] = fmaf(c, m1.z, a[6]); a[7] = fmaf(c, m1.w, a[7]);
        } else {
            #pragma unroll
            for (int f = 0; f < FV; f++) a[f] = fmaf(c, x[src * FV + f], a[f]);
        }
    }
    #pragma unroll
    for (int off = 16; off; off >>= 1) {
        s_part += __shfl_xor_sync(0xFFFFFFFFu, s_part, off);
        #pragma unroll
        for (int f = 0; f < 8; f++)
            a[f] += __shfl_xor_sync(0xFFFFFFFFu, a[f], off);
    }
    float s = s_part + self;
    if (F == 8) {
        float4 x0 = *(const float4*)(x + node * 8);
        float4 x1 = *(const float4*)(x + node * 8 + 4);
        a[0] = fmaf(self, x0.x, a[0]); a[1] = fmaf(self, x0.y, a[1]);
        a[2] = fmaf(self, x0.z, a[2]); a[3] = fmaf(self, x0.w, a[3]);
        a[4] = fmaf(self, x1.x, a[4]); a[5] = fmaf(self, x1.y, a[5]);
        a[6] = fmaf(self, x1.z, a[6]); a[7] = fmaf(self, x1.w, a[7]);
    } else {
        #pragma unroll
        for (int f = 0; f < FV; f++) a[f] = fmaf(self, x[node * FV + f], a[f]);
    }
    int d0 = lane * 8;
    float acc[8];
    {
        float4 b0 = *(const float4*)(b1 + d0);
        float4 bb1 = *(const float4*)(b1 + d0 + 4);
        float4 m80 = *(const float4*)(M + 8 * DD + d0);
        float4 m81 = *(const float4*)(M + 8 * DD + d0 + 4);
        acc[0] = fmaf(s, m80.x, b0.x);  acc[1] = fmaf(s, m80.y, b0.y);
        acc[2] = fmaf(s, m80.z, b0.z);  acc[3] = fmaf(s, m80.w, b0.w);
        acc[4] = fmaf(s, m81.x, bb1.x); acc[5] = fmaf(s, m81.y, bb1.y);
        acc[6] = fmaf(s, m81.z, bb1.z); acc[7] = fmaf(s, m81.w, bb1.w);
    }
    #pragma unroll
    for (int k = 0; k < 8; k++) {
        float4 w0 = *(const float4*)(M + k * DD + d0);
        float4 w1 = *(const float4*)(M + k * DD + d0 + 4);
        float ak = a[k];
        acc[0] = fmaf(ak, w0.x, acc[0]); acc[1] = fmaf(ak, w0.y, acc[1]);
        acc[2] = fmaf(ak, w0.z, acc[2]); acc[3] = fmaf(ak, w0.w, acc[3]);
        acc[4] = fmaf(ak, w1.x, acc[4]); acc[5] = fmaf(ak, w1.y, acc[5]);
        acc[6] = fmaf(ak, w1.z, acc[6]); acc[7] = fmaf(ak, w1.w, acc[7]);
    }
    __half2 o0 = __floats2half2_rn(fmaxf(acc[0], 0.f), fmaxf(acc[1], 0.f));
    __half2 o1 = __floats2half2_rn(fmaxf(acc[2], 0.f), fmaxf(acc[3], 0.f));
    __half2 o2 = __floats2half2_rn(fmaxf(acc[4], 0.f), fmaxf(acc[5], 0.f));
    __half2 o3 = __floats2half2_rn(fmaxf(acc[6], 0.f), fmaxf(acc[7], 0.f));
    uint4 ov = make_uint4(*(uint32_t*)&o0, *(uint32_t*)&o1, *(uint32_t*)&o2, *(uint32_t*)&o3);
    *(uint4*)(h1 + node * DD + d0) = ov;
}

// ---------------- 256-dim aggregation (fp16 gather) -> fp16 ----------
#define PBLK ((NPG + 7) / 8)
#define VBLK ((NVG + 7) / 8)
__global__ __launch_bounds__(256) void gcn_agg_both(
    const __half* __restrict__ p_h, const __half* __restrict__ v_h,
    const int* __restrict__ p_csr, const int* __restrict__ v_csr,
    const int* __restrict__ p_indeg, const int* __restrict__ v_indeg,
    __half* __restrict__ p_out, __half* __restrict__ v_out) {
    int blk = blockIdx.x;
    const __half* h; const int* csr; const int* indeg;
    __half* outp; int node0, n_nodes;
    if (blk < PBLK) { h = p_h; csr = p_csr; indeg = p_indeg;
                      outp = p_out; node0 = blk * 8; n_nodes = NPG; }
    else            { h = v_h; csr = v_csr; indeg = v_indeg;
                      outp = v_out; node0 = (blk - PBLK) * 8; n_nodes = NVG; }
    int warp = threadIdx.x >> 5;
    int lane = threadIdx.x & 31;
    int node = node0 + warp;
    if (node >= n_nodes) return;
    int d0 = lane * 8;

    int deg = indeg[node];
    int cnt = deg < CAP ? deg : CAP;
    float self = 1.0f / ((float)deg + 1.0f);
    float ddst = rsqrtf((float)deg + 1.0f);

    uint4 hv = *(const uint4*)(h + node * DD + d0);
    const __half2* hp = (const __half2*)&hv;
    float2 f0 = __half22float2(hp[0]);
    float2 f1 = __half22float2(hp[1]);
    float2 f2 = __half22float2(hp[2]);
    float2 f3 = __half22float2(hp[3]);
    float acc[8] = {f0.x * self, f0.y * self, f1.x * self, f1.y * self,
                    f2.x * self, f2.y * self, f3.x * self, f3.y * self};

    const int* cp = csr + node * CAP;
    for (int e = 0; e < cnt; e++) {
        int src = cp[e];
        float c = ddst * rsqrtf((float)indeg[src] + 1.0f);
        uint4 mv = *(const uint4*)(h + src * DD + d0);
        const __half2* mp = (const __half2*)&mv;
        float2 m0 = __half22float2(mp[0]);
        float2 m1 = __half22float2(mp[1]);
        float2 m2 = __half22float2(mp[2]);
        float2 m3 = __half22float2(mp[3]);
        acc[0] = fmaf(c, m0.x, acc[0]); acc[1] = fmaf(c, m0.y, acc[1]);
        acc[2] = fmaf(c, m1.x, acc[2]); acc[3] = fmaf(c, m1.y, acc[3]);
        acc[4] = fmaf(c, m2.x, acc[4]); acc[5] = fmaf(c, m2.y, acc[5]);
        acc[6] = fmaf(c, m3.x, acc[6]); acc[7] = fmaf(c, m3.y, acc[7]);
    }
    int base = node * DD + d0;
    __half2 o0 = __floats2half2_rn(acc[0], acc[1]);
    __half2 o1 = __floats2half2_rn(acc[2], acc[3]);
    __half2 o2 = __floats2half2_rn(acc[4], acc[5]);
    __half2 o3 = __floats2half2_rn(acc[6], acc[7]);
    uint4 ov = make_uint4(*(uint32_t*)&o0, *(uint32_t*)&o1, *(uint32_t*)&o2, *(uint32_t*)&o3);
    *(uint4*)(outp + base) = ov;
}

// ---------------- GEMM common: 1-term fp16, 128x128 tile ----------------
#define KC 32
#define APITCH 80
#define PIECE (128*APITCH)
#define STAGE_BYTES (2*PIECE)      // A + B
#define GEMM_SMEM (2*STAGE_BYTES)  // 40960
#define PGY (NPG / 128)   // 500
#define VGY (NVG / 128)   // 20

#define GEMM_CORE(A, BT, ROW0, COL0)                                               \
    extern __shared__ char sm[];                                                   \
    uint32_t sb = smem_u32(sm);                                                    \
    int tid = threadIdx.x;                                                         \
    int wid = tid >> 5, lane = tid & 31;                                           \
    int g = lane >> 2, t = lane & 3;                                               \
    int warp_m = wid & 3, warp_n = wid >> 2;                                       \
    float acc[2][8][4];                                                            \
    _Pragma("unroll")                                                              \
    for (int s = 0; s < 2; s++)                                                    \
        _Pragma("unroll")                                                          \
        for (int n = 0; n < 8; n++)                                                \
            _Pragma("unroll")                                                      \
            for (int q = 0; q < 4; q++) acc[s][n][q] = 0.0f;                       \
    int r0i = (tid + 0) >> 2,  c0i = (tid + 0) & 3;                                \
    int r1i = (tid + 256) >> 2, c1i = (tid + 256) & 3;                             \
    auto stage_load = [&](int st) {                                                \
        uint32_t base = sb + (st & 1) * STAGE_BYTES;                               \
        int kc0 = st * KC;                                                         \
        {                                                                          \
            uint32_t dd0 = base + r0i * APITCH + c0i * 16;                         \
            cpa16(dd0,         A  + (size_t)(ROW0 + r0i) * DD + kc0 + c0i * 8);    \
            cpa16(dd0 + PIECE, BT + (size_t)(COL0 + r0i) * DD + kc0 + c0i * 8);    \
        }                                                                          \
        {                                                                          \
            uint32_t dd0 = base + r1i * APITCH + c1i * 16;                         \
            cpa16(dd0,         A  + (size_t)(ROW0 + r1i) * DD + kc0 + c1i * 8);    \
            cpa16(dd0 + PIECE, BT + (size_t)(COL0 + r1i) * DD + kc0 + c1i * 8);    \
        }                                                                          \
        CPA_COMMIT();                                                              \
    };                                                                             \
    stage_load(0);                                                                 \
    CPA_WAIT0();                                                                   \
    __syncthreads();                                                               \
    for (int st = 0; st < DD / KC; st++) {                                         \
        if (st + 1 < DD / KC) stage_load(st + 1);                                  \
        const char* cur = sm + (st & 1) * STAGE_BYTES;                             \
        _Pragma("unroll")                                                          \
        for (int kk = 0; kk < 2; kk++) {                                           \
            int kb = (kk * 16 + t * 2) * 2;                                        \
            uint32_t ah[2][4];                                                     \
            _Pragma("unroll")                                                      \
            for (int s = 0; s < 2; s++) {                                          \
                const char* pa = cur + (warp_m * 32 + s * 16 + g) * APITCH + kb;   \
                ah[s][0] = *(const uint32_t*)pa;                                   \
                ah[s][1] = *(const uint32_t*)(pa + 8 * APITCH);                    \
                ah[s][2] = *(const uint32_t*)(pa + 16);                            \
                ah[s][3] = *(const uint32_t*)(pa + 8 * APITCH + 16);               \
            }                                                                      \
            _Pragma("unroll")                                                      \
            for (int nt = 0; nt < 8; nt++) {                                       \
                const char* pb = cur + PIECE + (warp_n * 64 + nt * 8 + g) * APITCH + kb; \
                uint32_t b0 = *(const uint32_t*)pb;                                \
                uint32_t b1 = *(const uint32_t*)(pb + 16);                         \
                _Pragma("unroll")                                                  \
                for (int s = 0; s < 2; s++)                                        \
                    MMA_F16(acc[s][nt], ah[s], b0, b1);                            \
            }                                                                      \
        }                                                                          \
        CPA_WAIT0();                                                               \
        __syncthreads();                                                           \
    }

// v-net GEMM: v_node = v_agg @ W2v + b2 (fp16 out)
__global__ void __launch_bounds__(256, 2) gemm_v(
    const __half* __restrict__ A, const __half* __restrict__ BT,
    const float* __restrict__ bias, __half* __restrict__ C) {
    int row0 = blockIdx.y * 128;
    int col0 = blockIdx.x * 128;
    GEMM_CORE(A, BT, row0, col0)
    #pragma unroll
    for (int s = 0; s < 2; s++) {
        int r = row0 + warp_m * 32 + s * 16 + g;
        #pragma unroll
        for (int nt = 0; nt < 8; nt++) {
            int c = col0 + warp_n * 64 + nt * 8 + t * 2;
            float bx = __ldg(&bias[c]), by = __ldg(&bias[c + 1]);
            __half2 o0 = __floats2half2_rn(acc[s][nt][0] + bx, acc[s][nt][1] + by);
            __half2 o1 = __floats2half2_rn(acc[s][nt][2] + bx, acc[s][nt][3] + by);
            *(uint32_t*)(C + r * DD + c)       = *(uint32_t*)&o0;
            *(uint32_t*)(C + (r + 8) * DD + c) = *(uint32_t*)&o1;
        }
    }
}

// p-net GEMM with K-extension (px@Wi) and fused final output:
// out[r,c] = agg[r]@W2[c] + px[r]@Wi[c] + av2[b(r),c]
__global__ void __launch_bounds__(256, 2) gemm_p_fused(
    const __half* __restrict__ A, const __half* __restrict__ BT,
    const __half* __restrict__ px8, const __half* __restrict__ wit8,
    const float* __restrict__ av2, float* __restrict__ Cout) {
    int row0 = blockIdx.y * 128;
    int col0 = blockIdx.x * 128;
    GEMM_CORE(A, BT, row0, col0)
    // K-extension step: one K=16 MMA with upper 8 k zeroed
    {
        uint32_t zero = 0u;
        uint32_t ae[2][4];
        #pragma unroll
        for (int s = 0; s < 2; s++) {
            int r = row0 + warp_m * 32 + s * 16 + g;
            ae[s][0] = *(const uint32_t*)(px8 + r * 8 + t * 2);
            ae[s][1] = *(const uint32_t*)(px8 + (r + 8) * 8 + t * 2);
            ae[s][2] = zero;
            ae[s][3] = zero;
        }
        #pragma unroll
        for (int nt = 0; nt < 8; nt++) {
            int c = col0 + warp_n * 64 + nt * 8 + g;
            uint32_t b0 = *(const uint32_t*)(wit8 + c * 8 + t * 2);
            #pragma unroll
            for (int s = 0; s < 2; s++)
                MMA_F16(acc[s][nt], ae[s], b0, zero);
        }
    }
    #pragma unroll
    for (int s = 0; s < 2; s++) {
        int r0 = row0 + warp_m * 32 + s * 16 + g;
        int r1 = r0 + 8;
        int b0g = r0 / NPP, b1g = r1 / NPP;
        #pragma unroll
        for (int nt = 0; nt < 8; nt++) {
            int c = col0 + warp_n * 64 + nt * 8 + t * 2;
            float2 v0 = *(const float2*)(av2 + b0g * DD + c);
            float2 v1 = *(const float2*)(av2 + b1g * DD + c);
            *(float2*)(Cout + (size_t)r0 * DD + c) =
                make_float2(acc[s][nt][0] + v0.x, acc[s][nt][1] + v0.y);
            *(float2*)(Cout + (size_t)r1 * DD + c) =
                make_float2(acc[s][nt][2] + v1.x, acc[s][nt][3] + v1.y);
        }
    }
}

// ---------------- pooling: p partials from p_agg + vg from v_node ----------------
__global__ __launch_bounds__(256) void pool_both(
    const __half* __restrict__ p_agg, const __half* __restrict__ v_node,
    float* __restrict__ part, float* __restrict__ vg) {
    int b = blockIdx.x, y = blockIdx.y, d = threadIdx.x;
    if (y < PPOOL) {
        const int chunk = NPP / PPOOL;
        const __half* p = p_agg + ((size_t)b * NPP + y * chunk) * DD + d;
        float s0 = 0.f, s1 = 0.f;
        #pragma unroll
        for (int i = 0; i < chunk; i += 2) {
            s0 += __half2float(p[i * DD]);
            s1 += __half2float(p[(i + 1) * DD]);
        }
        part[(b * PPOOL + y) * DD + d] = s0 + s1;
    } else {
        const __half* p = v_node + (size_t)b * NPV * DD + d;
        float s = 0.f;
        #pragma unroll
        for (int i = 0; i < NPV; i++) s += __half2float(p[i * DD]);
        vg[b * DD + d] = s * (1.0f / NPV);
    }
}

// av2[b,d] = meanAgg[b]@W2[:,d] + 2*b2[d] + bi[d] + 2*vg + v_node[cid] + v_init[cid]
__global__ __launch_bounds__(256) void pg_addvec(
    const float* __restrict__ part, const float* __restrict__ W2,
    const float* __restrict__ p_b2, const float* __restrict__ p_bi,
    const float* __restrict__ vg, const __half* __restrict__ v_node,
    const float* __restrict__ v_init, const int* __restrict__ curr,
    float* __restrict__ av2) {
    int b = blockIdx.x, d = threadIdx.x;
    __shared__ float pa[DD];
    float s = 0.f;
    #pragma unroll
    for (int j = 0; j < PPOOL; j++) s += part[(b * PPOOL + j) * DD + d];
    pa[d] = s * (1.0f / NPP);
    __syncthreads();
    float acc = 0.f;
    #pragma unroll 8
    for (int k = 0; k < DD; k++)
        acc = fmaf(pa[k], __ldg(&W2[k * DD + d]), acc);
    int cid = curr[b];
    int vi = (b * NPV + cid) * DD + d;
    av2[b * DD + d] = acc + 2.0f * __ldg(&p_b2[d]) + __ldg(&p_bi[d])
                    + 2.0f * vg[b * DD + d] + __half2float(v_node[vi]) + v_init[vi];
}

// ---------------- host launch ----------------
static inline void* sym(const void* s) {
    void* p = nullptr;
    cudaGetSymbolAddress(&p, s);
    return p;
}

extern "C" void kernel_launch(void* const* d_in, const int* in_sizes, int n_in,
                              void* d_out, int out_size) {
    const float* v_x     = (const float*)d_in[0];
    const float* p_x     = (const float*)d_in[1];
    const int*   v_src   = (const int*)d_in[2];
    const int*   v_dst   = (const int*)d_in[3];
    const int*   p_src   = (const int*)d_in[4];
    const int*   p_dst   = (const int*)d_in[5];
    const int*   curr    = (const int*)d_in[8];
    const float* v_initW = (const float*)d_in[9];
    const float* v_initb = (const float*)d_in[10];
    const float* v_W1    = (const float*)d_in[11];
    const float* v_b1    = (const float*)d_in[12];
    const float* v_W2    = (const float*)d_in[13];
    const float* v_b2    = (const float*)d_in[14];
    const float* p_initW = (const float*)d_in[15];
    const float* p_initb = (const float*)d_in[16];
    const float* p_W1    = (const float*)d_in[17];
    const float* p_b1    = (const float*)d_in[18];
    const float* p_W2    = (const float*)d_in[19];
    const float* p_b2    = (const float*)d_in[20];
    float* out = (float*)d_out;

    __half* p_tmp  = (__half*)sym(g_p_tmp);
    __half* p_agg  = (__half*)sym(g_p_agg);
    __half* px8    = (__half*)sym(g_px8);
    float* v_init  = (float*)sym(g_v_init);
    __half* v_tmp  = (__half*)sym(g_v_tmp);
    __half* v_node = (__half*)sym(g_v_node);
    __half* v_agg  = (__half*)sym(g_v_agg);
    __half* wtv2   = (__half*)sym(g_wtv2);
    __half* wtp2   = (__half*)sym(g_wtp2);
    __half* wit8   = (__half*)sym(g_wit8);
    float* Mp = (float*)sym(g_Mp);
    float* Mv = (float*)sym(g_Mv);
    int* p_indeg  = (int*)sym(g_p_indeg);
    int* v_indeg  = (int*)sym(g_v_indeg);
    int* p_csr    = (int*)sym(g_p_csr);
    int* v_csr    = (int*)sym(g_v_csr);
    float* pgp    = (float*)sym(g_pg_part);
    float* vg     = (float*)sym(g_vg);
    float* av2    = (float*)sym(g_av2);

    cudaFuncSetAttribute(gemm_v, cudaFuncAttributeMaxDynamicSharedMemorySize, GEMM_SMEM);
    cudaFuncSetAttribute(gemm_p_fused, cudaFuncAttributeMaxDynamicSharedMemorySize, GEMM_SMEM);

    // 1: setup
    setup_kernel<<<SB_TOT, 256>>>(p_indeg, v_indeg,
                                  p_initW, p_initb, p_W1, v_initW, v_initb, v_W1, Mp, Mv,
                                  p_W2, v_W2, wtp2, wtv2, wit8, v_x, v_init);
    // 2: CSR
    build_csr_both<<<(EP + EV + 255) / 256, 256>>>(p_src, p_dst, v_src, v_dst,
                                                   p_indeg, v_indeg, p_csr, v_csr);
    // 3: fused layer-1 (+ px8)
    layer1_fused<<<L1_BLKS, 256>>>(p_x, v_x, p_csr, v_csr, p_indeg, v_indeg,
                                   Mp, Mv, p_b1, v_b1, p_tmp, v_tmp, px8);
    // 4: layer-2 aggregation
    gcn_agg_both<<<PBLK + VBLK, 256>>>(p_tmp, v_tmp, p_csr, v_csr, p_indeg, v_indeg,
                                       p_agg, v_agg);
    // 5: v GEMM (small)
    {
        dim3 gv(2, VGY);
        gemm_v<<<gv, 256, GEMM_SMEM>>>(v_agg, wtv2, v_b2, v_node);
    }
    // 6: pooling (p_agg partials + vg)
    {
        dim3 g(NB, PPOOL + 1);
        pool_both<<<g, 256>>>(p_agg, v_node, pgp, vg);
    }
    // 7: per-graph additive vector (incl. pg via meanAgg@W2)
    pg_addvec<<<NB, 256>>>(pgp, p_W2, p_b2, p_initb, vg, v_node, v_init, curr, av2);
    // 8: p GEMM with K-extension + fused output
    {
        dim3 gp(2, PGY);
        gemm_p_fused<<<gp, 256, GEMM_SMEM>>>(p_agg, wtp2, px8, wit8, av2, out);
    }
}